// round 2
// baseline (speedup 1.0000x reference)
#include <cuda_runtime.h>
#include <cstdint>
#include <cstddef>

#define BATCH 8
#define TLEN  16384
#define CIN   256
#define T1    16383   // causal conv output length
#define L0    16382   // gated0 output length
#define LMAX  16382   // per-batch row stride for 24-ch buffers
#define BC    24
#define TOUT  15360

// Scratch (static device globals: allocation-free per harness rules)
__device__ float g_h1[(size_t)BATCH * T1 * CIN];     // 134 MB
__device__ float g_bufA[(size_t)BATCH * LMAX * BC];  // 12.6 MB
__device__ float g_bufB[(size_t)BATCH * LMAX * BC];  // 12.6 MB

// ---------------------------------------------------------------------------
// K1: causal conv  h1[b,t,o] = cb[o] + sum_{k,i} x[b,t+k,i] * W[k,i,o]
// Block: 64 time steps x 256 outputs. Thread: 4 outputs (float4) x 16 t.
// ---------------------------------------------------------------------------
__global__ __launch_bounds__(256) void k_causal(const float* __restrict__ x,
                                                const float* __restrict__ W,
                                                const float* __restrict__ bias) {
    const int b  = blockIdx.y;
    const int t0 = blockIdx.x * 64;
    const int tid = threadIdx.x;
    const int og = tid & 63;   // output float4 index: o = og*4..og*4+3
    const int tg = tid >> 6;   // 4 groups x 16 t

    __shared__ float xs[65][64];

    float acc[16][4];
    const float4 bv = reinterpret_cast<const float4*>(bias)[og];
#pragma unroll
    for (int t = 0; t < 16; ++t) {
        acc[t][0] = bv.x; acc[t][1] = bv.y; acc[t][2] = bv.z; acc[t][3] = bv.w;
    }

    const float4* W4 = reinterpret_cast<const float4*>(W);

    for (int chunk = 0; chunk < 4; ++chunk) {
        const int i0 = chunk * 64;
        __syncthreads();
        // load x rows t0..t0+64, channels i0..i0+63
        for (int idx = tid; idx < 65 * 16; idx += 256) {
            int r = idx >> 4, c4 = idx & 15;
            int trow = t0 + r; if (trow > TLEN - 1) trow = TLEN - 1;
            float4 v = reinterpret_cast<const float4*>(
                x + ((size_t)b * TLEN + trow) * CIN + i0)[c4];
            reinterpret_cast<float4*>(&xs[r][0])[c4] = v;
        }
        __syncthreads();
#pragma unroll 2
        for (int i = 0; i < 64; ++i) {
            const int ii = i0 + i;
            float4 w0 = W4[ii * 64 + og];            // W[0][ii][o..]
            float4 w1 = W4[(256 + ii) * 64 + og];    // W[1][ii][o..]
            float xv[17];
#pragma unroll
            for (int r = 0; r < 17; ++r) xv[r] = xs[tg * 16 + r][i];
#pragma unroll
            for (int t = 0; t < 16; ++t) {
                acc[t][0] += xv[t] * w0.x + xv[t + 1] * w1.x;
                acc[t][1] += xv[t] * w0.y + xv[t + 1] * w1.y;
                acc[t][2] += xv[t] * w0.z + xv[t + 1] * w1.z;
                acc[t][3] += xv[t] * w0.w + xv[t + 1] * w1.w;
            }
        }
    }
#pragma unroll
    for (int t = 0; t < 16; ++t) {
        int trow = t0 + tg * 16 + t;
        if (trow < T1) {
            float4 v = make_float4(acc[t][0], acc[t][1], acc[t][2], acc[t][3]);
            reinterpret_cast<float4*>(g_h1 + ((size_t)b * T1 + trow) * CIN)[og] = v;
        }
    }
}

// ---------------------------------------------------------------------------
// K2: gated layer 0: 256->24 g/f K=2 convs + gate + 24->24 1x1. Out -> g_bufA.
// Block: 64 t. Thread: one o (of 24, padded to 32 lanes) x 8 t.
// ---------------------------------------------------------------------------
__global__ __launch_bounds__(256) void k_gated0(const float* __restrict__ gW,
                                                const float* __restrict__ gb,
                                                const float* __restrict__ fW,
                                                const float* __restrict__ fb,
                                                const float* __restrict__ sW,
                                                const float* __restrict__ sb) {
    const int b  = blockIdx.y;
    const int t0 = blockIdx.x * 64;
    const int tid = threadIdx.x;
    const int oid = tid & 31;
    const int o = (oid < 24) ? oid : 0;
    const int tg = tid >> 5;   // 8 groups x 8 t

    __shared__ float xs[65][64];
    __shared__ float hs[64][25];

    float accg[8], accf[8];
    const float gbo = gb[o], fbo = fb[o];
#pragma unroll
    for (int t = 0; t < 8; ++t) { accg[t] = gbo; accf[t] = fbo; }

    for (int chunk = 0; chunk < 4; ++chunk) {
        const int i0 = chunk * 64;
        __syncthreads();
        for (int idx = tid; idx < 65 * 16; idx += 256) {
            int r = idx >> 4, c4 = idx & 15;
            int trow = t0 + r; if (trow > T1 - 1) trow = T1 - 1;
            float4 v = reinterpret_cast<const float4*>(
                g_h1 + ((size_t)b * T1 + trow) * CIN + i0)[c4];
            reinterpret_cast<float4*>(&xs[r][0])[c4] = v;
        }
        __syncthreads();
#pragma unroll 2
        for (int i = 0; i < 64; ++i) {
            const int ii = i0 + i;
            float wg0 = gW[ii * 24 + o];
            float wg1 = gW[(256 + ii) * 24 + o];
            float wf0 = fW[ii * 24 + o];
            float wf1 = fW[(256 + ii) * 24 + o];
            float xv[9];
#pragma unroll
            for (int r = 0; r < 9; ++r) xv[r] = xs[tg * 8 + r][i];
#pragma unroll
            for (int t = 0; t < 8; ++t) {
                accg[t] += xv[t] * wg0 + xv[t + 1] * wg1;
                accf[t] += xv[t] * wf0 + xv[t + 1] * wf1;
            }
        }
    }
#pragma unroll
    for (int t = 0; t < 8; ++t) {
        float g = 1.0f / (1.0f + __expf(-accg[t]));
        float f = tanhf(accf[t]);
        if (oid < 24) hs[tg * 8 + t][oid] = f * g;
    }
    __syncthreads();
    float outv[8];
    const float sbo = sb[o];
#pragma unroll
    for (int t = 0; t < 8; ++t) outv[t] = sbo;
#pragma unroll 4
    for (int c = 0; c < 24; ++c) {
        float w = sW[c * 24 + o];
#pragma unroll
        for (int t = 0; t < 8; ++t) outv[t] += hs[tg * 8 + t][c] * w;
    }
    if (oid < 24) {
#pragma unroll
        for (int t = 0; t < 8; ++t) {
            int trow = t0 + tg * 8 + t;
            if (trow < L0)
                g_bufA[((size_t)b * LMAX + trow) * 24 + o] = outv[t];
        }
    }
}

// ---------------------------------------------------------------------------
// K3: dilated gated layer (24->24 g/f K=2 dilation d, gate, 24->24 1x1).
// dir==0: bufA -> bufB ; dir==1: bufB -> bufA.
// Block: 128 t, one t per thread; weights + two input tiles in shared.
// ---------------------------------------------------------------------------
__global__ __launch_bounds__(128) void k_dilated(const float* __restrict__ gW,
                                                 const float* __restrict__ gb,
                                                 const float* __restrict__ fW,
                                                 const float* __restrict__ fb,
                                                 const float* __restrict__ sW,
                                                 const float* __restrict__ sb,
                                                 int d, int Lout, int dir) {
    const float* in  = dir ? g_bufB : g_bufA;
    float*       outp = dir ? g_bufA : g_bufB;
    const int b  = blockIdx.y;
    const int t0 = blockIdx.x * 128;
    const int tid = threadIdx.x;

    __shared__ float sA[128][25];
    __shared__ float sB[128][25];
    __shared__ float swg[1152], swf[1152], sws[576];
    __shared__ float sgb[24], sfb[24], ssb[24];

    for (int idx = tid; idx < 1152; idx += 128) { swg[idx] = gW[idx]; swf[idx] = fW[idx]; }
    for (int idx = tid; idx < 576;  idx += 128) sws[idx] = sW[idx];
    if (tid < 24) { sgb[tid] = gb[tid]; sfb[tid] = fb[tid]; ssb[tid] = sb[tid]; }

    const int Lin = Lout + d;
    for (int idx = tid; idx < 128 * 24; idx += 128) {
        int r = idx / 24, c = idx % 24;
        int ta = t0 + r;
        sA[r][c] = (ta < Lin) ? in[((size_t)b * LMAX + ta) * 24 + c] : 0.0f;
        int tb = t0 + d + r;
        sB[r][c] = (tb < Lin) ? in[((size_t)b * LMAX + tb) * 24 + c] : 0.0f;
    }
    __syncthreads();

    float a[24], bv[24], h[24];
#pragma unroll
    for (int c = 0; c < 24; ++c) { a[c] = sA[tid][c]; bv[c] = sB[tid][c]; }
#pragma unroll 4
    for (int o = 0; o < 24; ++o) {
        float g = sgb[o], f = sfb[o];
#pragma unroll
        for (int c = 0; c < 24; ++c) {
            g += a[c] * swg[c * 24 + o] + bv[c] * swg[576 + c * 24 + o];
            f += a[c] * swf[c * 24 + o] + bv[c] * swf[576 + c * 24 + o];
        }
        h[o] = tanhf(f) * (1.0f / (1.0f + __expf(-g)));
    }
    const int t = t0 + tid;
    if (t < Lout) {
#pragma unroll 4
        for (int o = 0; o < 24; ++o) {
            float s = ssb[o];
#pragma unroll
            for (int c = 0; c < 24; ++c) s += h[c] * sws[c * 24 + o];
            outp[((size_t)b * LMAX + t) * 24 + o] = s;
        }
    }
}

// ---------------------------------------------------------------------------
// K4: final fused stage.
// in24 = prev[t+256] + out[t]; acc128 = resW8 conv; relu; f1 (128->256); relu;
// f2 (256->256); softmax over channels.  prev = g_bufA (len 15872), out = g_bufB.
// Block: 16 time steps, 256 threads, 3 staged GEMM phases + warp softmax.
// ---------------------------------------------------------------------------
__global__ __launch_bounds__(256) void k_final(const float* __restrict__ resW,
                                               const float* __restrict__ resb,
                                               const float* __restrict__ f1W,
                                               const float* __restrict__ f1b,
                                               const float* __restrict__ f2W,
                                               const float* __restrict__ f2b,
                                               float* __restrict__ y) {
    const int b  = blockIdx.y;
    const int t0 = blockIdx.x * 16;
    const int tid = threadIdx.x;

    __shared__ float s_in[16][25];
    __shared__ float s_a[16][128];
    __shared__ float s_v[16][256];
    __shared__ float s_y[16][256];

    for (int idx = tid; idx < 16 * 24; idx += 256) {
        int r = idx / 24, c = idx % 24;
        size_t prow = (size_t)b * LMAX + 256 + t0 + r;
        size_t orow = (size_t)b * LMAX + t0 + r;
        s_in[r][c] = g_bufA[prow * 24 + c] + g_bufB[orow * 24 + c];
    }
    __syncthreads();

    // Phase A: 24 -> 128 (resW), relu
    {
        const int og = tid & 31;   // o = og*4..
        const int tg = tid >> 5;   // 8 groups x 2 t
        float4 bb = reinterpret_cast<const float4*>(resb)[og];
        float acc[2][4];
#pragma unroll
        for (int tt = 0; tt < 2; ++tt) {
            acc[tt][0] = bb.x; acc[tt][1] = bb.y; acc[tt][2] = bb.z; acc[tt][3] = bb.w;
        }
#pragma unroll 4
        for (int c = 0; c < 24; ++c) {
            float4 w = reinterpret_cast<const float4*>(resW)[c * 32 + og];
#pragma unroll
            for (int tt = 0; tt < 2; ++tt) {
                float xin = s_in[tg * 2 + tt][c];
                acc[tt][0] += xin * w.x; acc[tt][1] += xin * w.y;
                acc[tt][2] += xin * w.z; acc[tt][3] += xin * w.w;
            }
        }
#pragma unroll
        for (int tt = 0; tt < 2; ++tt) {
            float4 v = make_float4(fmaxf(acc[tt][0], 0.f), fmaxf(acc[tt][1], 0.f),
                                   fmaxf(acc[tt][2], 0.f), fmaxf(acc[tt][3], 0.f));
            reinterpret_cast<float4*>(&s_a[tg * 2 + tt][0])[og] = v;
        }
    }
    __syncthreads();

    // Phase B: 128 -> 256 (f1), relu
    {
        const int og = tid & 63;
        const int tg = tid >> 6;   // 4 groups x 4 t
        float4 bb = reinterpret_cast<const float4*>(f1b)[og];
        float acc[4][4];
#pragma unroll
        for (int tt = 0; tt < 4; ++tt) {
            acc[tt][0] = bb.x; acc[tt][1] = bb.y; acc[tt][2] = bb.z; acc[tt][3] = bb.w;
        }
#pragma unroll 2
        for (int c = 0; c < 128; ++c) {
            float4 w = reinterpret_cast<const float4*>(f1W)[c * 64 + og];
#pragma unroll
            for (int tt = 0; tt < 4; ++tt) {
                float av = s_a[tg * 4 + tt][c];
                acc[tt][0] += av * w.x; acc[tt][1] += av * w.y;
                acc[tt][2] += av * w.z; acc[tt][3] += av * w.w;
            }
        }
#pragma unroll
        for (int tt = 0; tt < 4; ++tt) {
            float4 v = make_float4(fmaxf(acc[tt][0], 0.f), fmaxf(acc[tt][1], 0.f),
                                   fmaxf(acc[tt][2], 0.f), fmaxf(acc[tt][3], 0.f));
            reinterpret_cast<float4*>(&s_v[tg * 4 + tt][0])[og] = v;
        }
    }
    __syncthreads();

    // Phase C: 256 -> 256 (f2)
    {
        const int og = tid & 63;
        const int tg = tid >> 6;
        float4 bb = reinterpret_cast<const float4*>(f2b)[og];
        float acc[4][4];
#pragma unroll
        for (int tt = 0; tt < 4; ++tt) {
            acc[tt][0] = bb.x; acc[tt][1] = bb.y; acc[tt][2] = bb.z; acc[tt][3] = bb.w;
        }
#pragma unroll 2
        for (int c = 0; c < 256; ++c) {
            float4 w = reinterpret_cast<const float4*>(f2W)[c * 64 + og];
#pragma unroll
            for (int tt = 0; tt < 4; ++tt) {
                float av = s_v[tg * 4 + tt][c];
                acc[tt][0] += av * w.x; acc[tt][1] += av * w.y;
                acc[tt][2] += av * w.z; acc[tt][3] += av * w.w;
            }
        }
#pragma unroll
        for (int tt = 0; tt < 4; ++tt) {
            float4 v = make_float4(acc[tt][0], acc[tt][1], acc[tt][2], acc[tt][3]);
            reinterpret_cast<float4*>(&s_y[tg * 4 + tt][0])[og] = v;
        }
    }
    __syncthreads();

    // Softmax: 8 warps, each handles 2 time steps
    const int warp = tid >> 5, lane = tid & 31;
#pragma unroll
    for (int tt = 0; tt < 2; ++tt) {
        int t = warp * 2 + tt;
        float vals[8];
        float m = -1e30f;
#pragma unroll
        for (int j = 0; j < 8; ++j) {
            vals[j] = s_y[t][lane + 32 * j];
            m = fmaxf(m, vals[j]);
        }
#pragma unroll
        for (int off = 16; off; off >>= 1)
            m = fmaxf(m, __shfl_xor_sync(0xffffffffu, m, off));
        float s = 0.f;
#pragma unroll
        for (int j = 0; j < 8; ++j) { vals[j] = __expf(vals[j] - m); s += vals[j]; }
#pragma unroll
        for (int off = 16; off; off >>= 1)
            s += __shfl_xor_sync(0xffffffffu, s, off);
        float inv = 1.0f / s;
        size_t base = ((size_t)b * TOUT + t0 + t) * 256;
#pragma unroll
        for (int j = 0; j < 8; ++j) y[base + lane + 32 * j] = vals[j] * inv;
    }
}

// ---------------------------------------------------------------------------
extern "C" void kernel_launch(void* const* d_in, const int* in_sizes, int n_in,
                              void* d_out, int out_size) {
    const float* x     = (const float*)d_in[0];
    const float* cW    = (const float*)d_in[1];
    const float* cb    = (const float*)d_in[2];
    const float* gW0   = (const float*)d_in[3];
    const float* gb0   = (const float*)d_in[4];
    const float* fW0   = (const float*)d_in[5];
    const float* fb0   = (const float*)d_in[6];
    const float* sW0   = (const float*)d_in[7];
    const float* sb0   = (const float*)d_in[8];
    const float* gateW = (const float*)d_in[9];
    const float* gateB = (const float*)d_in[10];
    const float* filtW = (const float*)d_in[11];
    const float* filtB = (const float*)d_in[12];
    const float* scW   = (const float*)d_in[13];
    const float* scB   = (const float*)d_in[14];
    const float* resW  = (const float*)d_in[15];
    const float* resB  = (const float*)d_in[16];
    const float* f1W   = (const float*)d_in[17];
    const float* f1b   = (const float*)d_in[18];
    const float* f2W   = (const float*)d_in[19];
    const float* f2b   = (const float*)d_in[20];
    float* out = (float*)d_out;

    k_causal<<<dim3(256, BATCH), 256>>>(x, cW, cb);
    k_gated0<<<dim3(256, BATCH), 256>>>(gW0, gb0, fW0, fb0, sW0, sb0);

    int L = L0;
    for (int i = 0; i < 9; ++i) {
        int d = 2 << i;          // 2,4,...,512
        int Lout = L - d;
        int nb = (Lout + 127) / 128;
        // NOTE: only the LAST residual conv contributes to the output (acc is
        // overwritten each iteration in the reference), so res convs 0..7 are skipped.
        k_dilated<<<dim3(nb, BATCH), 128>>>(gateW + i * 1152, gateB + i * 24,
                                            filtW + i * 1152, filtB + i * 24,
                                            scW + i * 576, scB + i * 24,
                                            d, Lout, i & 1);
        L = Lout;
    }
    // prev (input of layer i=8) lives in g_bufA (len 15872); its output in g_bufB (15360)
    k_final<<<dim3(TOUT / 16, BATCH), 256>>>(resW + 8 * 24 * 128, resB + 8 * 128,
                                             f1W, f1b, f2W, f2b, out);
}

// round 3
// speedup vs baseline: 1.5778x; 1.5778x over previous
#include <cuda_runtime.h>
#include <cstdint>
#include <cstddef>

#define BATCH 8
#define TLEN  16384
#define CIN   256
#define T1    16383   // causal conv output length
#define L0    16382   // gated0 output length
#define LMAX  16382   // per-batch row stride for 24-ch buffers
#define BC    24
#define TOUT  15360

// Scratch (static device globals: allocation-free per harness rules)
__device__ float g_h1[(size_t)BATCH * T1 * CIN];     // 134 MB
__device__ float g_bufA[(size_t)BATCH * LMAX * BC];  // 12.6 MB
__device__ float g_bufB[(size_t)BATCH * LMAX * BC];  // 12.6 MB

__device__ __forceinline__ float to_tf32(float x) {
    asm("cvt.rna.tf32.f32 %0, %0;" : "+f"(x));
    return x;
}

__device__ __forceinline__ void mma_tf32(float c[4], const uint32_t a[4], const uint32_t b[2]) {
    asm volatile(
        "mma.sync.aligned.m16n8k8.row.col.f32.tf32.tf32.f32 "
        "{%0,%1,%2,%3}, {%4,%5,%6,%7}, {%8,%9}, {%0,%1,%2,%3};"
        : "+f"(c[0]), "+f"(c[1]), "+f"(c[2]), "+f"(c[3])
        : "r"(a[0]), "r"(a[1]), "r"(a[2]), "r"(a[3]), "r"(b[0]), "r"(b[1]));
}

// ---------------------------------------------------------------------------
// K1: causal conv as tf32 tensor-core GEMM.
// out[t,o] = cb[o] + sum_{r<512} A[t,r] * Wc[r,o],  A[t,r] = x[t + (r>>8), r&255].
// Block tile: 128(M) x 128(N), BK=32. 8 warps (2x4), warp tile 64x32 (m16n8k8).
// ---------------------------------------------------------------------------
__global__ __launch_bounds__(256) void k_causal_mma(const float* __restrict__ x,
                                                    const float* __restrict__ W,
                                                    const float* __restrict__ cb) {
    const int t0 = blockIdx.x * 128;
    const int o0 = blockIdx.y * 128;
    const int b  = blockIdx.z;
    const int tid  = threadIdx.x;
    const int warp = tid >> 5, lane = tid & 31;
    const int mw = warp >> 2;          // 0..1
    const int nw = warp & 3;           // 0..3
    const int m_off = mw * 64;
    const int n_off = nw * 32;
    const int g  = lane >> 2;          // 0..7
    const int tq = lane & 3;           // 0..3

    __shared__ float As[128][36];      // pad 4: conflict-free A-frag loads
    __shared__ float Bs[32][136];      // pad 8: conflict-free B-frag loads

    float acc[4][4][4];
#pragma unroll
    for (int mt = 0; mt < 4; ++mt)
#pragma unroll
        for (int nt = 0; nt < 4; ++nt)
#pragma unroll
            for (int q = 0; q < 4; ++q) acc[mt][nt][q] = 0.0f;

    for (int k0 = 0; k0 < 512; k0 += 32) {
        const int tap = k0 >> 8;
        const int ch  = k0 & 255;
        __syncthreads();
        // Load A tile: 128 rows x 32 cols (8 float4 per row)
#pragma unroll
        for (int q = 0; q < 4; ++q) {
            int idx = tid + q * 256;
            int r = idx >> 3, c4 = idx & 7;
            int row = t0 + r + tap;
            if (row > TLEN - 1) row = TLEN - 1;
            float4 v = *reinterpret_cast<const float4*>(
                x + ((size_t)b * TLEN + row) * CIN + ch + c4 * 4);
            As[r][c4 * 4 + 0] = to_tf32(v.x);
            As[r][c4 * 4 + 1] = to_tf32(v.y);
            As[r][c4 * 4 + 2] = to_tf32(v.z);
            As[r][c4 * 4 + 3] = to_tf32(v.w);
        }
        // Load B tile: 32 rows x 128 cols (32 float4 per row)
#pragma unroll
        for (int q = 0; q < 4; ++q) {
            int idx = tid + q * 256;
            int r = idx >> 5, c4 = idx & 31;
            float4 v = *reinterpret_cast<const float4*>(
                W + (size_t)(k0 + r) * CIN + o0 + c4 * 4);
            Bs[r][c4 * 4 + 0] = to_tf32(v.x);
            Bs[r][c4 * 4 + 1] = to_tf32(v.y);
            Bs[r][c4 * 4 + 2] = to_tf32(v.z);
            Bs[r][c4 * 4 + 3] = to_tf32(v.w);
        }
        __syncthreads();
#pragma unroll
        for (int kk = 0; kk < 32; kk += 8) {
            uint32_t af[4][4];
#pragma unroll
            for (int mt = 0; mt < 4; ++mt) {
                int r0 = m_off + mt * 16 + g;
                af[mt][0] = __float_as_uint(As[r0][kk + tq]);
                af[mt][1] = __float_as_uint(As[r0 + 8][kk + tq]);
                af[mt][2] = __float_as_uint(As[r0][kk + tq + 4]);
                af[mt][3] = __float_as_uint(As[r0 + 8][kk + tq + 4]);
            }
            uint32_t bf[4][2];
#pragma unroll
            for (int nt = 0; nt < 4; ++nt) {
                int c0 = n_off + nt * 8 + g;
                bf[nt][0] = __float_as_uint(Bs[kk + tq][c0]);
                bf[nt][1] = __float_as_uint(Bs[kk + tq + 4][c0]);
            }
#pragma unroll
            for (int mt = 0; mt < 4; ++mt)
#pragma unroll
                for (int nt = 0; nt < 4; ++nt)
                    mma_tf32(acc[mt][nt], af[mt], bf[nt]);
        }
    }

    // Epilogue: bias add + store (float2 pairs per fragment)
#pragma unroll
    for (int nt = 0; nt < 4; ++nt) {
        const int col = o0 + n_off + nt * 8 + 2 * tq;
        const float2 bias = *reinterpret_cast<const float2*>(cb + col);
#pragma unroll
        for (int mt = 0; mt < 4; ++mt) {
            int row = t0 + m_off + mt * 16 + g;
            if (row < T1) {
                float2 v = make_float2(acc[mt][nt][0] + bias.x, acc[mt][nt][1] + bias.y);
                *reinterpret_cast<float2*>(g_h1 + ((size_t)b * T1 + row) * CIN + col) = v;
            }
            if (row + 8 < T1) {
                float2 v = make_float2(acc[mt][nt][2] + bias.x, acc[mt][nt][3] + bias.y);
                *reinterpret_cast<float2*>(g_h1 + ((size_t)b * T1 + row + 8) * CIN + col) = v;
            }
        }
    }
}

// ---------------------------------------------------------------------------
// K2: gated layer 0: 256->24 g/f K=2 convs + gate + 24->24 1x1. Out -> g_bufA.
// ---------------------------------------------------------------------------
__global__ __launch_bounds__(256) void k_gated0(const float* __restrict__ gW,
                                                const float* __restrict__ gb,
                                                const float* __restrict__ fW,
                                                const float* __restrict__ fb,
                                                const float* __restrict__ sW,
                                                const float* __restrict__ sb) {
    const int b  = blockIdx.y;
    const int t0 = blockIdx.x * 64;
    const int tid = threadIdx.x;
    const int oid = tid & 31;
    const int o = (oid < 24) ? oid : 0;
    const int tg = tid >> 5;   // 8 groups x 8 t

    __shared__ float xs[65][64];
    __shared__ float hs[64][25];

    float accg[8], accf[8];
    const float gbo = gb[o], fbo = fb[o];
#pragma unroll
    for (int t = 0; t < 8; ++t) { accg[t] = gbo; accf[t] = fbo; }

    for (int chunk = 0; chunk < 4; ++chunk) {
        const int i0 = chunk * 64;
        __syncthreads();
        for (int idx = tid; idx < 65 * 16; idx += 256) {
            int r = idx >> 4, c4 = idx & 15;
            int trow = t0 + r; if (trow > T1 - 1) trow = T1 - 1;
            float4 v = reinterpret_cast<const float4*>(
                g_h1 + ((size_t)b * T1 + trow) * CIN + i0)[c4];
            reinterpret_cast<float4*>(&xs[r][0])[c4] = v;
        }
        __syncthreads();
#pragma unroll 2
        for (int i = 0; i < 64; ++i) {
            const int ii = i0 + i;
            float wg0 = gW[ii * 24 + o];
            float wg1 = gW[(256 + ii) * 24 + o];
            float wf0 = fW[ii * 24 + o];
            float wf1 = fW[(256 + ii) * 24 + o];
            float xv[9];
#pragma unroll
            for (int r = 0; r < 9; ++r) xv[r] = xs[tg * 8 + r][i];
#pragma unroll
            for (int t = 0; t < 8; ++t) {
                accg[t] += xv[t] * wg0 + xv[t + 1] * wg1;
                accf[t] += xv[t] * wf0 + xv[t + 1] * wf1;
            }
        }
    }
#pragma unroll
    for (int t = 0; t < 8; ++t) {
        float g = 1.0f / (1.0f + __expf(-accg[t]));
        float f = tanhf(accf[t]);
        if (oid < 24) hs[tg * 8 + t][oid] = f * g;
    }
    __syncthreads();
    float outv[8];
    const float sbo = sb[o];
#pragma unroll
    for (int t = 0; t < 8; ++t) outv[t] = sbo;
#pragma unroll 4
    for (int c = 0; c < 24; ++c) {
        float w = sW[c * 24 + o];
#pragma unroll
        for (int t = 0; t < 8; ++t) outv[t] += hs[tg * 8 + t][c] * w;
    }
    if (oid < 24) {
#pragma unroll
        for (int t = 0; t < 8; ++t) {
            int trow = t0 + tg * 8 + t;
            if (trow < L0)
                g_bufA[((size_t)b * LMAX + trow) * 24 + o] = outv[t];
        }
    }
}

// ---------------------------------------------------------------------------
// K3: dilated gated layer. Weights packed: gate/filter as float2 (LDS.64
// broadcast), scale as float4 (LDS.128), float4 output stores.
// ---------------------------------------------------------------------------
__global__ __launch_bounds__(128) void k_dilated(const float* __restrict__ gW,
                                                 const float* __restrict__ gb,
                                                 const float* __restrict__ fW,
                                                 const float* __restrict__ fb,
                                                 const float* __restrict__ sW,
                                                 const float* __restrict__ sb,
                                                 int d, int Lout, int dir) {
    const float* in   = dir ? g_bufB : g_bufA;
    float*       outp = dir ? g_bufA : g_bufB;
    const int b  = blockIdx.y;
    const int t0 = blockIdx.x * 128;
    const int tid = threadIdx.x;

    __shared__ float sA[128][25];
    __shared__ float sB[128][25];
    __shared__ float2 swgf0[576];   // {gate, filter} tap 0, [c*24+o]
    __shared__ float2 swgf1[576];   // {gate, filter} tap 1
    __shared__ float4 sws4[144];    // scale weights [c*6 + o/4]
    __shared__ float sgb[24], sfb[24], ssb[24];

    for (int idx = tid; idx < 576; idx += 128) {
        swgf0[idx] = make_float2(gW[idx], fW[idx]);
        swgf1[idx] = make_float2(gW[576 + idx], fW[576 + idx]);
    }
    for (int idx = tid; idx < 144; idx += 128)
        sws4[idx] = reinterpret_cast<const float4*>(sW)[idx];
    if (tid < 24) { sgb[tid] = gb[tid]; sfb[tid] = fb[tid]; ssb[tid] = sb[tid]; }

    const int Lin = Lout + d;
    for (int idx = tid; idx < 128 * 24; idx += 128) {
        int r = idx / 24, c = idx % 24;
        int ta = t0 + r;
        sA[r][c] = (ta < Lin) ? in[((size_t)b * LMAX + ta) * 24 + c] : 0.0f;
        int tb = t0 + d + r;
        sB[r][c] = (tb < Lin) ? in[((size_t)b * LMAX + tb) * 24 + c] : 0.0f;
    }
    __syncthreads();

    float a[24], bv[24], h[24];
#pragma unroll
    for (int c = 0; c < 24; ++c) { a[c] = sA[tid][c]; bv[c] = sB[tid][c]; }
#pragma unroll 4
    for (int o = 0; o < 24; ++o) {
        float g = sgb[o], f = sfb[o];
#pragma unroll
        for (int c = 0; c < 24; ++c) {
            float2 w0 = swgf0[c * 24 + o];
            float2 w1 = swgf1[c * 24 + o];
            g += a[c] * w0.x + bv[c] * w1.x;
            f += a[c] * w0.y + bv[c] * w1.y;
        }
        h[o] = tanhf(f) * (1.0f / (1.0f + __expf(-g)));
    }
    const int t = t0 + tid;
    if (t < Lout) {
        float* orow = outp + ((size_t)b * LMAX + t) * 24;
#pragma unroll
        for (int oq = 0; oq < 6; ++oq) {
            float s0 = ssb[oq * 4 + 0], s1 = ssb[oq * 4 + 1];
            float s2 = ssb[oq * 4 + 2], s3 = ssb[oq * 4 + 3];
#pragma unroll
            for (int c = 0; c < 24; ++c) {
                float4 w = sws4[c * 6 + oq];
                s0 += h[c] * w.x; s1 += h[c] * w.y;
                s2 += h[c] * w.z; s3 += h[c] * w.w;
            }
            reinterpret_cast<float4*>(orow)[oq] = make_float4(s0, s1, s2, s3);
        }
    }
}

// ---------------------------------------------------------------------------
// K4: final fused stage (unchanged this round).
// ---------------------------------------------------------------------------
__global__ __launch_bounds__(256) void k_final(const float* __restrict__ resW,
                                               const float* __restrict__ resb,
                                               const float* __restrict__ f1W,
                                               const float* __restrict__ f1b,
                                               const float* __restrict__ f2W,
                                               const float* __restrict__ f2b,
                                               float* __restrict__ y) {
    const int b  = blockIdx.y;
    const int t0 = blockIdx.x * 16;
    const int tid = threadIdx.x;

    __shared__ float s_in[16][25];
    __shared__ float s_a[16][128];
    __shared__ float s_v[16][256];
    __shared__ float s_y[16][256];

    for (int idx = tid; idx < 16 * 24; idx += 256) {
        int r = idx / 24, c = idx % 24;
        size_t prow = (size_t)b * LMAX + 256 + t0 + r;
        size_t orow = (size_t)b * LMAX + t0 + r;
        s_in[r][c] = g_bufA[prow * 24 + c] + g_bufB[orow * 24 + c];
    }
    __syncthreads();

    // Phase A: 24 -> 128 (resW), relu
    {
        const int og = tid & 31;
        const int tg = tid >> 5;
        float4 bb = reinterpret_cast<const float4*>(resb)[og];
        float acc[2][4];
#pragma unroll
        for (int tt = 0; tt < 2; ++tt) {
            acc[tt][0] = bb.x; acc[tt][1] = bb.y; acc[tt][2] = bb.z; acc[tt][3] = bb.w;
        }
#pragma unroll 4
        for (int c = 0; c < 24; ++c) {
            float4 w = reinterpret_cast<const float4*>(resW)[c * 32 + og];
#pragma unroll
            for (int tt = 0; tt < 2; ++tt) {
                float xin = s_in[tg * 2 + tt][c];
                acc[tt][0] += xin * w.x; acc[tt][1] += xin * w.y;
                acc[tt][2] += xin * w.z; acc[tt][3] += xin * w.w;
            }
        }
#pragma unroll
        for (int tt = 0; tt < 2; ++tt) {
            float4 v = make_float4(fmaxf(acc[tt][0], 0.f), fmaxf(acc[tt][1], 0.f),
                                   fmaxf(acc[tt][2], 0.f), fmaxf(acc[tt][3], 0.f));
            reinterpret_cast<float4*>(&s_a[tg * 2 + tt][0])[og] = v;
        }
    }
    __syncthreads();

    // Phase B: 128 -> 256 (f1), relu
    {
        const int og = tid & 63;
        const int tg = tid >> 6;
        float4 bb = reinterpret_cast<const float4*>(f1b)[og];
        float acc[4][4];
#pragma unroll
        for (int tt = 0; tt < 4; ++tt) {
            acc[tt][0] = bb.x; acc[tt][1] = bb.y; acc[tt][2] = bb.z; acc[tt][3] = bb.w;
        }
#pragma unroll 2
        for (int c = 0; c < 128; ++c) {
            float4 w = reinterpret_cast<const float4*>(f1W)[c * 64 + og];
#pragma unroll
            for (int tt = 0; tt < 4; ++tt) {
                float av = s_a[tg * 4 + tt][c];
                acc[tt][0] += av * w.x; acc[tt][1] += av * w.y;
                acc[tt][2] += av * w.z; acc[tt][3] += av * w.w;
            }
        }
#pragma unroll
        for (int tt = 0; tt < 4; ++tt) {
            float4 v = make_float4(fmaxf(acc[tt][0], 0.f), fmaxf(acc[tt][1], 0.f),
                                   fmaxf(acc[tt][2], 0.f), fmaxf(acc[tt][3], 0.f));
            reinterpret_cast<float4*>(&s_v[tg * 4 + tt][0])[og] = v;
        }
    }
    __syncthreads();

    // Phase C: 256 -> 256 (f2)
    {
        const int og = tid & 63;
        const int tg = tid >> 6;
        float4 bb = reinterpret_cast<const float4*>(f2b)[og];
        float acc[4][4];
#pragma unroll
        for (int tt = 0; tt < 4; ++tt) {
            acc[tt][0] = bb.x; acc[tt][1] = bb.y; acc[tt][2] = bb.z; acc[tt][3] = bb.w;
        }
#pragma unroll 2
        for (int c = 0; c < 256; ++c) {
            float4 w = reinterpret_cast<const float4*>(f2W)[c * 64 + og];
#pragma unroll
            for (int tt = 0; tt < 4; ++tt) {
                float av = s_v[tg * 4 + tt][c];
                acc[tt][0] += av * w.x; acc[tt][1] += av * w.y;
                acc[tt][2] += av * w.z; acc[tt][3] += av * w.w;
            }
        }
#pragma unroll
        for (int tt = 0; tt < 4; ++tt) {
            float4 v = make_float4(acc[tt][0], acc[tt][1], acc[tt][2], acc[tt][3]);
            reinterpret_cast<float4*>(&s_y[tg * 4 + tt][0])[og] = v;
        }
    }
    __syncthreads();

    // Softmax: 8 warps, each handles 2 time steps
    const int warp = tid >> 5, lane = tid & 31;
#pragma unroll
    for (int tt = 0; tt < 2; ++tt) {
        int t = warp * 2 + tt;
        float vals[8];
        float m = -1e30f;
#pragma unroll
        for (int j = 0; j < 8; ++j) {
            vals[j] = s_y[t][lane + 32 * j];
            m = fmaxf(m, vals[j]);
        }
#pragma unroll
        for (int off = 16; off; off >>= 1)
            m = fmaxf(m, __shfl_xor_sync(0xffffffffu, m, off));
        float s = 0.f;
#pragma unroll
        for (int j = 0; j < 8; ++j) { vals[j] = __expf(vals[j] - m); s += vals[j]; }
#pragma unroll
        for (int off = 16; off; off >>= 1)
            s += __shfl_xor_sync(0xffffffffu, s, off);
        float inv = 1.0f / s;
        size_t base = ((size_t)b * TOUT + t0 + t) * 256;
#pragma unroll
        for (int j = 0; j < 8; ++j) y[base + lane + 32 * j] = vals[j] * inv;
    }
}

// ---------------------------------------------------------------------------
extern "C" void kernel_launch(void* const* d_in, const int* in_sizes, int n_in,
                              void* d_out, int out_size) {
    const float* x     = (const float*)d_in[0];
    const float* cW    = (const float*)d_in[1];
    const float* cb    = (const float*)d_in[2];
    const float* gW0   = (const float*)d_in[3];
    const float* gb0   = (const float*)d_in[4];
    const float* fW0   = (const float*)d_in[5];
    const float* fb0   = (const float*)d_in[6];
    const float* sW0   = (const float*)d_in[7];
    const float* sb0   = (const float*)d_in[8];
    const float* gateW = (const float*)d_in[9];
    const float* gateB = (const float*)d_in[10];
    const float* filtW = (const float*)d_in[11];
    const float* filtB = (const float*)d_in[12];
    const float* scW   = (const float*)d_in[13];
    const float* scB   = (const float*)d_in[14];
    const float* resW  = (const float*)d_in[15];
    const float* resB  = (const float*)d_in[16];
    const float* f1W   = (const float*)d_in[17];
    const float* f1b   = (const float*)d_in[18];
    const float* f2W   = (const float*)d_in[19];
    const float* f2b   = (const float*)d_in[20];
    float* out = (float*)d_out;

    k_causal_mma<<<dim3(128, 2, BATCH), 256>>>(x, cW, cb);
    k_gated0<<<dim3(256, BATCH), 256>>>(gW0, gb0, fW0, fb0, sW0, sb0);

    int L = L0;
    for (int i = 0; i < 9; ++i) {
        int d = 2 << i;          // 2,4,...,512
        int Lout = L - d;
        int nb = (Lout + 127) / 128;
        // Only the LAST residual conv contributes to the output (acc is
        // overwritten each iteration in the reference), so res convs 0..7 are skipped.
        k_dilated<<<dim3(nb, BATCH), 128>>>(gateW + i * 1152, gateB + i * 24,
                                            filtW + i * 1152, filtB + i * 24,
                                            scW + i * 576, scB + i * 24,
                                            d, Lout, i & 1);
        L = Lout;
    }
    // prev (input of layer i=8) lives in g_bufA (len 15872); its output in g_bufB (15360)
    k_final<<<dim3(TOUT / 16, BATCH), 256>>>(resW + 8 * 24 * 128, resB + 8 * 128,
                                             f1W, f1b, f2W, f2b, out);
}

// round 4
// speedup vs baseline: 1.5915x; 1.0086x over previous
#include <cuda_runtime.h>
#include <cstdint>
#include <cstddef>

#define BATCH 8
#define TLEN  16384
#define CIN   256
#define T1    16383   // causal conv output length
#define L0    16382   // gated0 output length
#define LMAX  16382   // per-batch row stride for 24-ch buffers
#define TOUT  15360

// Scratch (static device globals: allocation-free per harness rules)
__device__ float g_h1[(size_t)BATCH * T1 * CIN];        // 134 MB
__device__ float g_bufA[(size_t)BATCH * LMAX * 24];     // 12.6 MB
__device__ float g_bufB[(size_t)BATCH * LMAX * 24];     // 12.6 MB
__device__ float g_act128[(size_t)BATCH * TOUT * 128];  // 63 MB
__device__ float g_act256[(size_t)BATCH * TOUT * 256];  // 126 MB

__device__ __forceinline__ float to_tf32(float x) {
    asm("cvt.rna.tf32.f32 %0, %0;" : "+f"(x));
    return x;
}

__device__ __forceinline__ void mma_tf32(float c[4], const uint32_t a[4], const uint32_t b[2]) {
    asm volatile(
        "mma.sync.aligned.m16n8k8.row.col.f32.tf32.tf32.f32 "
        "{%0,%1,%2,%3}, {%4,%5,%6,%7}, {%8,%9}, {%0,%1,%2,%3};"
        : "+f"(c[0]), "+f"(c[1]), "+f"(c[2]), "+f"(c[3])
        : "r"(a[0]), "r"(a[1]), "r"(a[2]), "r"(a[3]), "r"(b[0]), "r"(b[1]));
}

// ---------------------------------------------------------------------------
// K1: causal conv as tf32 GEMM. out[t,o] = cb[o] + sum_{r<512} A[t,r]*W[r,o],
// A[t,r] = x[t + (r>>8), r&255]. 128x128 tile, BK=32, 8 warps (2x4), 64x32 warp.
// ---------------------------------------------------------------------------
__global__ __launch_bounds__(256) void k_causal_mma(const float* __restrict__ x,
                                                    const float* __restrict__ W,
                                                    const float* __restrict__ cb) {
    const int t0 = blockIdx.x * 128;
    const int o0 = blockIdx.y * 128;
    const int b  = blockIdx.z;
    const int tid  = threadIdx.x;
    const int warp = tid >> 5, lane = tid & 31;
    const int m_off = (warp >> 2) * 64;
    const int n_off = (warp & 3) * 32;
    const int g  = lane >> 2;
    const int tq = lane & 3;

    __shared__ float As[128][36];
    __shared__ float Bs[32][136];

    float acc[4][4][4];
#pragma unroll
    for (int mt = 0; mt < 4; ++mt)
#pragma unroll
        for (int nt = 0; nt < 4; ++nt)
#pragma unroll
            for (int q = 0; q < 4; ++q) acc[mt][nt][q] = 0.0f;

    for (int k0 = 0; k0 < 512; k0 += 32) {
        const int tap = k0 >> 8;
        const int ch  = k0 & 255;
        __syncthreads();
#pragma unroll
        for (int q = 0; q < 4; ++q) {
            int idx = tid + q * 256;
            int r = idx >> 3, c4 = idx & 7;
            int row = t0 + r + tap;
            if (row > TLEN - 1) row = TLEN - 1;
            float4 v = *reinterpret_cast<const float4*>(
                x + ((size_t)b * TLEN + row) * CIN + ch + c4 * 4);
            As[r][c4 * 4 + 0] = to_tf32(v.x);
            As[r][c4 * 4 + 1] = to_tf32(v.y);
            As[r][c4 * 4 + 2] = to_tf32(v.z);
            As[r][c4 * 4 + 3] = to_tf32(v.w);
        }
#pragma unroll
        for (int q = 0; q < 4; ++q) {
            int idx = tid + q * 256;
            int r = idx >> 5, c4 = idx & 31;
            float4 v = *reinterpret_cast<const float4*>(
                W + (size_t)(k0 + r) * CIN + o0 + c4 * 4);
            Bs[r][c4 * 4 + 0] = to_tf32(v.x);
            Bs[r][c4 * 4 + 1] = to_tf32(v.y);
            Bs[r][c4 * 4 + 2] = to_tf32(v.z);
            Bs[r][c4 * 4 + 3] = to_tf32(v.w);
        }
        __syncthreads();
#pragma unroll
        for (int kk = 0; kk < 32; kk += 8) {
            uint32_t af[4][4];
#pragma unroll
            for (int mt = 0; mt < 4; ++mt) {
                int r0 = m_off + mt * 16 + g;
                af[mt][0] = __float_as_uint(As[r0][kk + tq]);
                af[mt][1] = __float_as_uint(As[r0 + 8][kk + tq]);
                af[mt][2] = __float_as_uint(As[r0][kk + tq + 4]);
                af[mt][3] = __float_as_uint(As[r0 + 8][kk + tq + 4]);
            }
            uint32_t bf[4][2];
#pragma unroll
            for (int nt = 0; nt < 4; ++nt) {
                int c0 = n_off + nt * 8 + g;
                bf[nt][0] = __float_as_uint(Bs[kk + tq][c0]);
                bf[nt][1] = __float_as_uint(Bs[kk + tq + 4][c0]);
            }
#pragma unroll
            for (int mt = 0; mt < 4; ++mt)
#pragma unroll
                for (int nt = 0; nt < 4; ++nt)
                    mma_tf32(acc[mt][nt], af[mt], bf[nt]);
        }
    }
#pragma unroll
    for (int nt = 0; nt < 4; ++nt) {
        const int col = o0 + n_off + nt * 8 + 2 * tq;
        const float2 bias = *reinterpret_cast<const float2*>(cb + col);
#pragma unroll
        for (int mt = 0; mt < 4; ++mt) {
            int row = t0 + m_off + mt * 16 + g;
            if (row < T1) {
                float2 v = make_float2(acc[mt][nt][0] + bias.x, acc[mt][nt][1] + bias.y);
                *reinterpret_cast<float2*>(g_h1 + ((size_t)b * T1 + row) * CIN + col) = v;
            }
            if (row + 8 < T1) {
                float2 v = make_float2(acc[mt][nt][2] + bias.x, acc[mt][nt][3] + bias.y);
                *reinterpret_cast<float2*>(g_h1 + ((size_t)b * T1 + row + 8) * CIN + col) = v;
            }
        }
    }
}

// ---------------------------------------------------------------------------
// K2: gated0 as tf32 GEMM: A[t,k]=h1[t+(k>>8),k&255] (K=512), B = [gW|fW] (N=48).
// M tile 128, 8 warps all in M (16 rows each), warp tile 16x48.
// Epilogue: h = tanh(f)*sigmoid(g) -> smem, then scalar 24x24 1x1 -> g_bufA.
// ---------------------------------------------------------------------------
__global__ __launch_bounds__(256) void k_gated0_mma(const float* __restrict__ gW,
                                                    const float* __restrict__ gb,
                                                    const float* __restrict__ fW,
                                                    const float* __restrict__ fb,
                                                    const float* __restrict__ sW,
                                                    const float* __restrict__ sb) {
    const int t0 = blockIdx.x * 128;
    const int b  = blockIdx.y;
    const int tid  = threadIdx.x;
    const int warp = tid >> 5, lane = tid & 31;
    const int m_off = warp * 16;
    const int g  = lane >> 2;
    const int tq = lane & 3;

    __shared__ float As[128][36];
    __shared__ float Bs[32][56];
    __shared__ float hs[128][25];
    __shared__ float sws[576];
    __shared__ float ssb[24];

    for (int idx = tid; idx < 576; idx += 256) sws[idx] = sW[idx];
    if (tid < 24) ssb[tid] = sb[tid];

    float acc[6][4];
#pragma unroll
    for (int nt = 0; nt < 6; ++nt) {
        int c0 = nt * 8 + 2 * tq;
        float b0 = (nt < 3) ? gb[c0] : fb[c0 - 24];
        float b1 = (nt < 3) ? gb[c0 + 1] : fb[c0 - 23];
        acc[nt][0] = b0; acc[nt][1] = b1; acc[nt][2] = b0; acc[nt][3] = b1;
    }

    for (int k0 = 0; k0 < 512; k0 += 32) {
        const int tap = k0 >> 8;
        const int ch  = k0 & 255;
        __syncthreads();
#pragma unroll
        for (int q = 0; q < 4; ++q) {
            int idx = tid + q * 256;
            int r = idx >> 3, c4 = idx & 7;
            int row = t0 + r + tap;
            if (row > T1 - 1) row = T1 - 1;
            float4 v = *reinterpret_cast<const float4*>(
                g_h1 + ((size_t)b * T1 + row) * CIN + ch + c4 * 4);
            As[r][c4 * 4 + 0] = to_tf32(v.x);
            As[r][c4 * 4 + 1] = to_tf32(v.y);
            As[r][c4 * 4 + 2] = to_tf32(v.z);
            As[r][c4 * 4 + 3] = to_tf32(v.w);
        }
        // B tile: 32 rows x 48 cols (cols 0-23 gate, 24-47 filter)
        for (int idx = tid; idx < 32 * 48; idx += 256) {
            int r = idx / 48, c = idx % 48;
            int kk2 = k0 + r;
            int tp = kk2 >> 8, chh = kk2 & 255;
            float v = (c < 24) ? gW[tp * 6144 + chh * 24 + c]
                               : fW[tp * 6144 + chh * 24 + (c - 24)];
            Bs[r][c] = to_tf32(v);
        }
        __syncthreads();
#pragma unroll
        for (int kk = 0; kk < 32; kk += 8) {
            uint32_t af[4];
            af[0] = __float_as_uint(As[m_off + g][kk + tq]);
            af[1] = __float_as_uint(As[m_off + g + 8][kk + tq]);
            af[2] = __float_as_uint(As[m_off + g][kk + tq + 4]);
            af[3] = __float_as_uint(As[m_off + g + 8][kk + tq + 4]);
            uint32_t bf[6][2];
#pragma unroll
            for (int nt = 0; nt < 6; ++nt) {
                int c0 = nt * 8 + g;
                bf[nt][0] = __float_as_uint(Bs[kk + tq][c0]);
                bf[nt][1] = __float_as_uint(Bs[kk + tq + 4][c0]);
            }
#pragma unroll
            for (int nt = 0; nt < 6; ++nt)
                mma_tf32(acc[nt], af, bf[nt]);
        }
    }

    // gate nonlinearity -> hs
    const int r0 = m_off + g, r1 = m_off + g + 8;
#pragma unroll
    for (int nt = 0; nt < 3; ++nt) {
        int c0 = nt * 8 + 2 * tq;
        hs[r0][c0]     = tanhf(acc[nt + 3][0]) * (1.0f / (1.0f + __expf(-acc[nt][0])));
        hs[r0][c0 + 1] = tanhf(acc[nt + 3][1]) * (1.0f / (1.0f + __expf(-acc[nt][1])));
        hs[r1][c0]     = tanhf(acc[nt + 3][2]) * (1.0f / (1.0f + __expf(-acc[nt][2])));
        hs[r1][c0 + 1] = tanhf(acc[nt + 3][3]) * (1.0f / (1.0f + __expf(-acc[nt][3])));
    }
    __syncthreads();

    // 1x1: 24->24
    const int oid = tid & 31;
    const int o = (oid < 24) ? oid : 0;
    const int tg = tid >> 5;
#pragma unroll
    for (int rr = 0; rr < 16; ++rr) {
        int r = tg * 16 + rr;
        float s = ssb[o];
#pragma unroll
        for (int c = 0; c < 24; ++c) s += hs[r][c] * sws[c * 24 + o];
        int t = t0 + r;
        if (oid < 24 && t < L0)
            g_bufA[((size_t)b * LMAX + t) * 24 + o] = s;
    }
}

// ---------------------------------------------------------------------------
// K3: dilated gated layer. Weights packed float4 {g0,f0,g1,f1}: 1 LDS.128 / 4 FMA.
// ---------------------------------------------------------------------------
__global__ __launch_bounds__(128) void k_dilated(const float* __restrict__ gW,
                                                 const float* __restrict__ gb,
                                                 const float* __restrict__ fW,
                                                 const float* __restrict__ fb,
                                                 const float* __restrict__ sW,
                                                 const float* __restrict__ sb,
                                                 int d, int Lout, int dir) {
    const float* in   = dir ? g_bufB : g_bufA;
    float*       outp = dir ? g_bufA : g_bufB;
    const int b  = blockIdx.y;
    const int t0 = blockIdx.x * 128;
    const int tid = threadIdx.x;

    __shared__ float sA[128][25];
    __shared__ float sB[128][25];
    __shared__ float4 swc[576];     // {gate0, filt0, gate1, filt1} [c*24+o]
    __shared__ float4 sws4[144];    // scale weights [c*6 + o/4]
    __shared__ float sgb[24], sfb[24], ssb[24];

    for (int idx = tid; idx < 576; idx += 128)
        swc[idx] = make_float4(gW[idx], fW[idx], gW[576 + idx], fW[576 + idx]);
    for (int idx = tid; idx < 144; idx += 128)
        sws4[idx] = reinterpret_cast<const float4*>(sW)[idx];
    if (tid < 24) { sgb[tid] = gb[tid]; sfb[tid] = fb[tid]; ssb[tid] = sb[tid]; }

    const int Lin = Lout + d;
    for (int idx = tid; idx < 128 * 24; idx += 128) {
        int r = idx / 24, c = idx % 24;
        int ta = t0 + r;
        sA[r][c] = (ta < Lin) ? in[((size_t)b * LMAX + ta) * 24 + c] : 0.0f;
        int tb = t0 + d + r;
        sB[r][c] = (tb < Lin) ? in[((size_t)b * LMAX + tb) * 24 + c] : 0.0f;
    }
    __syncthreads();

    float a[24], bv[24], h[24];
#pragma unroll
    for (int c = 0; c < 24; ++c) { a[c] = sA[tid][c]; bv[c] = sB[tid][c]; }
#pragma unroll 4
    for (int o = 0; o < 24; ++o) {
        float g = sgb[o], f = sfb[o];
#pragma unroll
        for (int c = 0; c < 24; ++c) {
            float4 w = swc[c * 24 + o];
            g += a[c] * w.x + bv[c] * w.z;
            f += a[c] * w.y + bv[c] * w.w;
        }
        h[o] = tanhf(f) * (1.0f / (1.0f + __expf(-g)));
    }
    const int t = t0 + tid;
    if (t < Lout) {
        float* orow = outp + ((size_t)b * LMAX + t) * 24;
#pragma unroll
        for (int oq = 0; oq < 6; ++oq) {
            float s0 = ssb[oq * 4 + 0], s1 = ssb[oq * 4 + 1];
            float s2 = ssb[oq * 4 + 2], s3 = ssb[oq * 4 + 3];
#pragma unroll
            for (int c = 0; c < 24; ++c) {
                float4 w = sws4[c * 6 + oq];
                s0 += h[c] * w.x; s1 += h[c] * w.y;
                s2 += h[c] * w.z; s3 += h[c] * w.w;
            }
            reinterpret_cast<float4*>(orow)[oq] = make_float4(s0, s1, s2, s3);
        }
    }
}

// ---------------------------------------------------------------------------
// K4a: act128 = relu(resW conv of (prev[t+256] + out[t])). 64 t per block.
// ---------------------------------------------------------------------------
__global__ __launch_bounds__(256) void k_resrelu(const float* __restrict__ resW,
                                                 const float* __restrict__ resb) {
    const int b  = blockIdx.y;
    const int t0 = blockIdx.x * 64;
    const int tid = threadIdx.x;
    const int og = tid & 31;   // o = og*4..
    const int tg = tid >> 5;   // 8 groups x 8 rows

    __shared__ float s_in[64][25];
    for (int idx = tid; idx < 64 * 24; idx += 256) {
        int r = idx / 24, c = idx % 24;
        size_t prow = (size_t)b * LMAX + 256 + t0 + r;
        size_t orow = (size_t)b * LMAX + t0 + r;
        s_in[r][c] = g_bufA[prow * 24 + c] + g_bufB[orow * 24 + c];
    }
    __syncthreads();

    const float4 bb = reinterpret_cast<const float4*>(resb)[og];
    float acc[8][4];
#pragma unroll
    for (int rr = 0; rr < 8; ++rr) {
        acc[rr][0] = bb.x; acc[rr][1] = bb.y; acc[rr][2] = bb.z; acc[rr][3] = bb.w;
    }
#pragma unroll 4
    for (int c = 0; c < 24; ++c) {
        float4 w = reinterpret_cast<const float4*>(resW)[c * 32 + og];
#pragma unroll
        for (int rr = 0; rr < 8; ++rr) {
            float xin = s_in[tg * 8 + rr][c];
            acc[rr][0] += xin * w.x; acc[rr][1] += xin * w.y;
            acc[rr][2] += xin * w.z; acc[rr][3] += xin * w.w;
        }
    }
#pragma unroll
    for (int rr = 0; rr < 8; ++rr) {
        int row = t0 + tg * 8 + rr;
        float4 v = make_float4(fmaxf(acc[rr][0], 0.f), fmaxf(acc[rr][1], 0.f),
                               fmaxf(acc[rr][2], 0.f), fmaxf(acc[rr][3], 0.f));
        reinterpret_cast<float4*>(g_act128 + ((size_t)b * TOUT + row) * 128)[og] = v;
    }
}

// ---------------------------------------------------------------------------
// K4b: act256 = relu(act128 @ f1W + f1b). tf32 GEMM, 128x128 tile, K=128.
// ---------------------------------------------------------------------------
__global__ __launch_bounds__(256) void k_gemm_relu(const float* __restrict__ f1W,
                                                   const float* __restrict__ f1b) {
    const int t0 = blockIdx.x * 128;
    const int o0 = blockIdx.y * 128;
    const int b  = blockIdx.z;
    const int tid  = threadIdx.x;
    const int warp = tid >> 5, lane = tid & 31;
    const int m_off = (warp >> 2) * 64;
    const int n_off = (warp & 3) * 32;
    const int g  = lane >> 2;
    const int tq = lane & 3;

    __shared__ float As[128][36];
    __shared__ float Bs[32][136];

    float acc[4][4][4];
#pragma unroll
    for (int mt = 0; mt < 4; ++mt)
#pragma unroll
        for (int nt = 0; nt < 4; ++nt)
#pragma unroll
            for (int q = 0; q < 4; ++q) acc[mt][nt][q] = 0.0f;

    for (int k0 = 0; k0 < 128; k0 += 32) {
        __syncthreads();
#pragma unroll
        for (int q = 0; q < 4; ++q) {
            int idx = tid + q * 256;
            int r = idx >> 3, c4 = idx & 7;
            float4 v = *reinterpret_cast<const float4*>(
                g_act128 + ((size_t)b * TOUT + t0 + r) * 128 + k0 + c4 * 4);
            As[r][c4 * 4 + 0] = to_tf32(v.x);
            As[r][c4 * 4 + 1] = to_tf32(v.y);
            As[r][c4 * 4 + 2] = to_tf32(v.z);
            As[r][c4 * 4 + 3] = to_tf32(v.w);
        }
#pragma unroll
        for (int q = 0; q < 4; ++q) {
            int idx = tid + q * 256;
            int r = idx >> 5, c4 = idx & 31;
            float4 v = *reinterpret_cast<const float4*>(
                f1W + (size_t)(k0 + r) * 256 + o0 + c4 * 4);
            Bs[r][c4 * 4 + 0] = to_tf32(v.x);
            Bs[r][c4 * 4 + 1] = to_tf32(v.y);
            Bs[r][c4 * 4 + 2] = to_tf32(v.z);
            Bs[r][c4 * 4 + 3] = to_tf32(v.w);
        }
        __syncthreads();
#pragma unroll
        for (int kk = 0; kk < 32; kk += 8) {
            uint32_t af[4][4];
#pragma unroll
            for (int mt = 0; mt < 4; ++mt) {
                int r0 = m_off + mt * 16 + g;
                af[mt][0] = __float_as_uint(As[r0][kk + tq]);
                af[mt][1] = __float_as_uint(As[r0 + 8][kk + tq]);
                af[mt][2] = __float_as_uint(As[r0][kk + tq + 4]);
                af[mt][3] = __float_as_uint(As[r0 + 8][kk + tq + 4]);
            }
            uint32_t bf[4][2];
#pragma unroll
            for (int nt = 0; nt < 4; ++nt) {
                int c0 = n_off + nt * 8 + g;
                bf[nt][0] = __float_as_uint(Bs[kk + tq][c0]);
                bf[nt][1] = __float_as_uint(Bs[kk + tq + 4][c0]);
            }
#pragma unroll
            for (int mt = 0; mt < 4; ++mt)
#pragma unroll
                for (int nt = 0; nt < 4; ++nt)
                    mma_tf32(acc[mt][nt], af[mt], bf[nt]);
        }
    }
#pragma unroll
    for (int nt = 0; nt < 4; ++nt) {
        const int col = o0 + n_off + nt * 8 + 2 * tq;
        const float2 bias = *reinterpret_cast<const float2*>(f1b + col);
#pragma unroll
        for (int mt = 0; mt < 4; ++mt) {
            int row = t0 + m_off + mt * 16 + g;
            float2 v0 = make_float2(fmaxf(acc[mt][nt][0] + bias.x, 0.f),
                                    fmaxf(acc[mt][nt][1] + bias.y, 0.f));
            float2 v1 = make_float2(fmaxf(acc[mt][nt][2] + bias.x, 0.f),
                                    fmaxf(acc[mt][nt][3] + bias.y, 0.f));
            *reinterpret_cast<float2*>(g_act256 + ((size_t)b * TOUT + row) * 256 + col) = v0;
            *reinterpret_cast<float2*>(g_act256 + ((size_t)b * TOUT + row + 8) * 256 + col) = v1;
        }
    }
}

// ---------------------------------------------------------------------------
// K4c: y = softmax(act256 @ f2W + f2b). tf32 GEMM, M tile 64, full N=256,
// BK=16. 8 warps = 2(M)x4(N), warp tile 32x64. Fused row softmax.
// ---------------------------------------------------------------------------
__global__ __launch_bounds__(256) void k_gemm_softmax(const float* __restrict__ f2W,
                                                      const float* __restrict__ f2b,
                                                      float* __restrict__ y) {
    const int t0 = blockIdx.x * 64;
    const int b  = blockIdx.y;
    const int tid  = threadIdx.x;
    const int warp = tid >> 5, lane = tid & 31;
    const int mw = warp >> 2;          // 0..1
    const int nw = warp & 3;           // 0..3
    const int m_off = mw * 32;
    const int n_off = nw * 64;
    const int g  = lane >> 2;
    const int tq = lane & 3;

    __shared__ float As[64][20];
    __shared__ float Bs[16][264];
    __shared__ float red1[64][4];
    __shared__ float red2[64][4];

    float acc[2][8][4];
#pragma unroll
    for (int mt = 0; mt < 2; ++mt)
#pragma unroll
        for (int nt = 0; nt < 8; ++nt)
#pragma unroll
            for (int q = 0; q < 4; ++q) acc[mt][nt][q] = 0.0f;

    for (int k0 = 0; k0 < 256; k0 += 16) {
        __syncthreads();
        // As: 64 rows x 16 cols = 256 float4, 1 per thread... (2 needed: 64*4=256)
#pragma unroll
        for (int q = 0; q < 1; ++q) {
            int idx = tid;
            int r = idx >> 2, c4 = idx & 3;
            float4 v = *reinterpret_cast<const float4*>(
                g_act256 + ((size_t)b * TOUT + t0 + r) * 256 + k0 + c4 * 4);
            As[r][c4 * 4 + 0] = to_tf32(v.x);
            As[r][c4 * 4 + 1] = to_tf32(v.y);
            As[r][c4 * 4 + 2] = to_tf32(v.z);
            As[r][c4 * 4 + 3] = to_tf32(v.w);
        }
        // Bs: 16 rows x 256 cols = 1024 float4, 4 per thread
#pragma unroll
        for (int q = 0; q < 4; ++q) {
            int idx = tid + q * 256;
            int r = idx >> 6, c4 = idx & 63;
            float4 v = *reinterpret_cast<const float4*>(
                f2W + (size_t)(k0 + r) * 256 + c4 * 4);
            Bs[r][c4 * 4 + 0] = to_tf32(v.x);
            Bs[r][c4 * 4 + 1] = to_tf32(v.y);
            Bs[r][c4 * 4 + 2] = to_tf32(v.z);
            Bs[r][c4 * 4 + 3] = to_tf32(v.w);
        }
        __syncthreads();
#pragma unroll
        for (int kk = 0; kk < 16; kk += 8) {
            uint32_t af[2][4];
#pragma unroll
            for (int mt = 0; mt < 2; ++mt) {
                int r0 = m_off + mt * 16 + g;
                af[mt][0] = __float_as_uint(As[r0][kk + tq]);
                af[mt][1] = __float_as_uint(As[r0 + 8][kk + tq]);
                af[mt][2] = __float_as_uint(As[r0][kk + tq + 4]);
                af[mt][3] = __float_as_uint(As[r0 + 8][kk + tq + 4]);
            }
            uint32_t bf[8][2];
#pragma unroll
            for (int nt = 0; nt < 8; ++nt) {
                int c0 = n_off + nt * 8 + g;
                bf[nt][0] = __float_as_uint(Bs[kk + tq][c0]);
                bf[nt][1] = __float_as_uint(Bs[kk + tq + 4][c0]);
            }
#pragma unroll
            for (int mt = 0; mt < 2; ++mt)
#pragma unroll
                for (int nt = 0; nt < 8; ++nt)
                    mma_tf32(acc[mt][nt], af[mt], bf[nt]);
        }
    }

    // Bias add
#pragma unroll
    for (int nt = 0; nt < 8; ++nt) {
        const int col = n_off + nt * 8 + 2 * tq;
        const float2 bias = *reinterpret_cast<const float2*>(f2b + col);
#pragma unroll
        for (int mt = 0; mt < 2; ++mt) {
            acc[mt][nt][0] += bias.x; acc[mt][nt][1] += bias.y;
            acc[mt][nt][2] += bias.x; acc[mt][nt][3] += bias.y;
        }
    }

    // Row max: local over this warp's 64 cols, then cross-warp via smem
    float rmax[2][2];
#pragma unroll
    for (int mt = 0; mt < 2; ++mt)
#pragma unroll
        for (int rr = 0; rr < 2; ++rr) {
            float m = -1e30f;
#pragma unroll
            for (int nt = 0; nt < 8; ++nt) {
                m = fmaxf(m, acc[mt][nt][rr * 2 + 0]);
                m = fmaxf(m, acc[mt][nt][rr * 2 + 1]);
            }
            m = fmaxf(m, __shfl_xor_sync(0xffffffffu, m, 1));
            m = fmaxf(m, __shfl_xor_sync(0xffffffffu, m, 2));
            rmax[mt][rr] = m;
            if (tq == 0) red1[m_off + mt * 16 + rr * 8 + g][nw] = m;
        }
    __syncthreads();
#pragma unroll
    for (int mt = 0; mt < 2; ++mt)
#pragma unroll
        for (int rr = 0; rr < 2; ++rr) {
            int r = m_off + mt * 16 + rr * 8 + g;
            rmax[mt][rr] = fmaxf(fmaxf(red1[r][0], red1[r][1]),
                                 fmaxf(red1[r][2], red1[r][3]));
        }

    // exp + row sum
    float rsum[2][2];
#pragma unroll
    for (int mt = 0; mt < 2; ++mt)
#pragma unroll
        for (int rr = 0; rr < 2; ++rr) {
            float s = 0.f;
#pragma unroll
            for (int nt = 0; nt < 8; ++nt) {
                float e0 = __expf(acc[mt][nt][rr * 2 + 0] - rmax[mt][rr]);
                float e1 = __expf(acc[mt][nt][rr * 2 + 1] - rmax[mt][rr]);
                acc[mt][nt][rr * 2 + 0] = e0;
                acc[mt][nt][rr * 2 + 1] = e1;
                s += e0 + e1;
            }
            s += __shfl_xor_sync(0xffffffffu, s, 1);
            s += __shfl_xor_sync(0xffffffffu, s, 2);
            rsum[mt][rr] = s;
            if (tq == 0) red2[m_off + mt * 16 + rr * 8 + g][nw] = s;
        }
    __syncthreads();
#pragma unroll
    for (int mt = 0; mt < 2; ++mt)
#pragma unroll
        for (int rr = 0; rr < 2; ++rr) {
            int r = m_off + mt * 16 + rr * 8 + g;
            rsum[mt][rr] = 1.0f / (red2[r][0] + red2[r][1] + red2[r][2] + red2[r][3]);
        }

    // Store
#pragma unroll
    for (int nt = 0; nt < 8; ++nt) {
        const int col = n_off + nt * 8 + 2 * tq;
#pragma unroll
        for (int mt = 0; mt < 2; ++mt) {
            int row = t0 + m_off + mt * 16 + g;
            float2 v0 = make_float2(acc[mt][nt][0] * rsum[mt][0],
                                    acc[mt][nt][1] * rsum[mt][0]);
            float2 v1 = make_float2(acc[mt][nt][2] * rsum[mt][1],
                                    acc[mt][nt][3] * rsum[mt][1]);
            *reinterpret_cast<float2*>(y + ((size_t)b * TOUT + row) * 256 + col) = v0;
            *reinterpret_cast<float2*>(y + ((size_t)b * TOUT + row + 8) * 256 + col) = v1;
        }
    }
}

// ---------------------------------------------------------------------------
extern "C" void kernel_launch(void* const* d_in, const int* in_sizes, int n_in,
                              void* d_out, int out_size) {
    const float* x     = (const float*)d_in[0];
    const float* cW    = (const float*)d_in[1];
    const float* cb    = (const float*)d_in[2];
    const float* gW0   = (const float*)d_in[3];
    const float* gb0   = (const float*)d_in[4];
    const float* fW0   = (const float*)d_in[5];
    const float* fb0   = (const float*)d_in[6];
    const float* sW0   = (const float*)d_in[7];
    const float* sb0   = (const float*)d_in[8];
    const float* gateW = (const float*)d_in[9];
    const float* gateB = (const float*)d_in[10];
    const float* filtW = (const float*)d_in[11];
    const float* filtB = (const float*)d_in[12];
    const float* scW   = (const float*)d_in[13];
    const float* scB   = (const float*)d_in[14];
    const float* resW  = (const float*)d_in[15];
    const float* resB  = (const float*)d_in[16];
    const float* f1W   = (const float*)d_in[17];
    const float* f1b   = (const float*)d_in[18];
    const float* f2W   = (const float*)d_in[19];
    const float* f2b   = (const float*)d_in[20];
    float* out = (float*)d_out;

    k_causal_mma<<<dim3(128, 2, BATCH), 256>>>(x, cW, cb);
    k_gated0_mma<<<dim3(128, BATCH), 256>>>(gW0, gb0, fW0, fb0, sW0, sb0);

    int L = L0;
    for (int i = 0; i < 9; ++i) {
        int d = 2 << i;          // 2,4,...,512
        int Lout = L - d;
        int nb = (Lout + 127) / 128;
        // Only the LAST residual conv contributes to the output (acc is
        // overwritten each iteration in the reference), so res convs 0..7 are skipped.
        k_dilated<<<dim3(nb, BATCH), 128>>>(gateW + i * 1152, gateB + i * 24,
                                            filtW + i * 1152, filtB + i * 24,
                                            scW + i * 576, scB + i * 24,
                                            d, Lout, i & 1);
        L = Lout;
    }
    // prev (input of layer i=8) lives in g_bufA (len 15872); its output in g_bufB (15360)
    k_resrelu<<<dim3(TOUT / 64, BATCH), 256>>>(resW + 8 * 24 * 128, resB + 8 * 128);
    k_gemm_relu<<<dim3(TOUT / 128, 2, BATCH), 256>>>(f1W, f1b);
    k_gemm_softmax<<<dim3(TOUT / 64, BATCH), 256>>>(f2W, f2b, out);
}

// round 5
// speedup vs baseline: 2.8608x; 1.7976x over previous
#include <cuda_runtime.h>
#include <cstdint>
#include <cstddef>

#define BATCH 8
#define TLEN  16384
#define CIN   256
#define T1    16383   // causal conv output length
#define L0    16382   // gated0 output length
#define LMAX  16382   // per-batch row stride for 24-ch buffers
#define TOUT  15360

// Scratch (static device globals: allocation-free per harness rules)
__device__ float g_h1[(size_t)BATCH * T1 * CIN];        // 134 MB
__device__ float g_bufA[(size_t)BATCH * LMAX * 24];     // 12.6 MB
__device__ float g_bufB[(size_t)BATCH * LMAX * 24];     // 12.6 MB
__device__ float g_act128[(size_t)BATCH * TOUT * 128];  // 63 MB
__device__ float g_act256[(size_t)BATCH * TOUT * 256];  // 126 MB

__device__ __forceinline__ float to_tf32(float x) {
    asm("cvt.rna.tf32.f32 %0, %0;" : "+f"(x));
    return x;
}
__device__ __forceinline__ uint32_t frag_tf32(float x) {
    asm("cvt.rna.tf32.f32 %0, %0;" : "+f"(x));
    return __float_as_uint(x);
}

__device__ __forceinline__ void mma_tf32(float c[4], const uint32_t a[4], const uint32_t b[2]) {
    asm volatile(
        "mma.sync.aligned.m16n8k8.row.col.f32.tf32.tf32.f32 "
        "{%0,%1,%2,%3}, {%4,%5,%6,%7}, {%8,%9}, {%0,%1,%2,%3};"
        : "+f"(c[0]), "+f"(c[1]), "+f"(c[2]), "+f"(c[3])
        : "r"(a[0]), "r"(a[1]), "r"(a[2]), "r"(a[3]), "r"(b[0]), "r"(b[1]));
}

__device__ __forceinline__ void cp16(uint32_t smem_dst, const void* gsrc) {
    asm volatile("cp.async.ca.shared.global [%0], [%1], 16;" :: "r"(smem_dst), "l"(gsrc));
}
__device__ __forceinline__ void cp_commit() {
    asm volatile("cp.async.commit_group;" ::: "memory");
}
__device__ __forceinline__ void cp_wait_all() {
    asm volatile("cp.async.wait_group 0;" ::: "memory");
}

__device__ __forceinline__ float sigmoidf_fast(float x) {
    return 1.0f / (1.0f + __expf(-x));
}

// ---------------------------------------------------------------------------
// K1: causal conv as tf32 GEMM, 2-stage cp.async pipeline.
// out[t,o] = cb[o] + sum_{r<512} A[t,r]*W[r,o], A[t,r] = x[t+(r>>8), r&255].
// 128x128 tile, BK=32, 8 warps (2x4), 64x32 warp tile.
// ---------------------------------------------------------------------------
__global__ __launch_bounds__(256) void k_causal_mma(const float* __restrict__ x,
                                                    const float* __restrict__ W,
                                                    const float* __restrict__ cb) {
    const int t0 = blockIdx.x * 128;
    const int o0 = blockIdx.y * 128;
    const int b  = blockIdx.z;
    const int tid  = threadIdx.x;
    const int warp = tid >> 5, lane = tid & 31;
    const int m_off = (warp >> 2) * 64;
    const int n_off = (warp & 3) * 32;
    const int g  = lane >> 2;
    const int tq = lane & 3;

    __shared__ float As[2][128][36];
    __shared__ float Bs[2][32][136];
    const uint32_t as_base = (uint32_t)__cvta_generic_to_shared(&As[0][0][0]);
    const uint32_t bs_base = (uint32_t)__cvta_generic_to_shared(&Bs[0][0][0]);

    float acc[4][4][4];
#pragma unroll
    for (int mt = 0; mt < 4; ++mt)
#pragma unroll
        for (int nt = 0; nt < 4; ++nt)
#pragma unroll
            for (int q = 0; q < 4; ++q) acc[mt][nt][q] = 0.0f;

#define CAUSAL_LOAD(chunk, s) do {                                              \
    int k0 = (chunk) * 32; int tap = k0 >> 8; int ch = k0 & 255;                \
    _Pragma("unroll")                                                            \
    for (int q = 0; q < 4; ++q) {                                                \
        int idx = tid + q * 256;                                                 \
        int r = idx >> 3, c4 = idx & 7;                                          \
        int row = t0 + r + tap; if (row > TLEN - 1) row = TLEN - 1;              \
        cp16(as_base + (uint32_t)(((s) * 128 * 36 + r * 36 + c4 * 4) * 4),       \
             x + ((size_t)b * TLEN + row) * CIN + ch + c4 * 4);                  \
    }                                                                            \
    _Pragma("unroll")                                                            \
    for (int q = 0; q < 4; ++q) {                                                \
        int idx = tid + q * 256;                                                 \
        int r = idx >> 5, c4 = idx & 31;                                         \
        cp16(bs_base + (uint32_t)(((s) * 32 * 136 + r * 136 + c4 * 4) * 4),      \
             W + (size_t)(k0 + r) * CIN + o0 + c4 * 4);                          \
    }                                                                            \
} while (0)

    CAUSAL_LOAD(0, 0);
    cp_commit();

    for (int c = 0; c < 16; ++c) {
        const int s = c & 1;
        cp_wait_all();
        __syncthreads();
        if (c < 15) { CAUSAL_LOAD(c + 1, s ^ 1); cp_commit(); }
#pragma unroll
        for (int kk = 0; kk < 32; kk += 8) {
            uint32_t af[4][4];
#pragma unroll
            for (int mt = 0; mt < 4; ++mt) {
                int r0 = m_off + mt * 16 + g;
                af[mt][0] = frag_tf32(As[s][r0][kk + tq]);
                af[mt][1] = frag_tf32(As[s][r0 + 8][kk + tq]);
                af[mt][2] = frag_tf32(As[s][r0][kk + tq + 4]);
                af[mt][3] = frag_tf32(As[s][r0 + 8][kk + tq + 4]);
            }
            uint32_t bf[4][2];
#pragma unroll
            for (int nt = 0; nt < 4; ++nt) {
                int c0 = n_off + nt * 8 + g;
                bf[nt][0] = frag_tf32(Bs[s][kk + tq][c0]);
                bf[nt][1] = frag_tf32(Bs[s][kk + tq + 4][c0]);
            }
#pragma unroll
            for (int mt = 0; mt < 4; ++mt)
#pragma unroll
                for (int nt = 0; nt < 4; ++nt)
                    mma_tf32(acc[mt][nt], af[mt], bf[nt]);
        }
        __syncthreads();
    }
#undef CAUSAL_LOAD

#pragma unroll
    for (int nt = 0; nt < 4; ++nt) {
        const int col = o0 + n_off + nt * 8 + 2 * tq;
        const float2 bias = *reinterpret_cast<const float2*>(cb + col);
#pragma unroll
        for (int mt = 0; mt < 4; ++mt) {
            int row = t0 + m_off + mt * 16 + g;
            if (row < T1) {
                float2 v = make_float2(acc[mt][nt][0] + bias.x, acc[mt][nt][1] + bias.y);
                *reinterpret_cast<float2*>(g_h1 + ((size_t)b * T1 + row) * CIN + col) = v;
            }
            if (row + 8 < T1) {
                float2 v = make_float2(acc[mt][nt][2] + bias.x, acc[mt][nt][3] + bias.y);
                *reinterpret_cast<float2*>(g_h1 + ((size_t)b * T1 + row + 8) * CIN + col) = v;
            }
        }
    }
}

// ---------------------------------------------------------------------------
// K2: gated0 as tf32 GEMM: A[t,k]=h1[t+(k>>8),k&255] (K=512), B=[gW|fW] (N=48).
// M tile 128, 8 warps all in M, warp tile 16x48. Epilogue: gate + 24x24 1x1.
// ---------------------------------------------------------------------------
__global__ __launch_bounds__(256) void k_gated0_mma(const float* __restrict__ gW,
                                                    const float* __restrict__ gb,
                                                    const float* __restrict__ fW,
                                                    const float* __restrict__ fb,
                                                    const float* __restrict__ sW,
                                                    const float* __restrict__ sb) {
    const int t0 = blockIdx.x * 128;
    const int b  = blockIdx.y;
    const int tid  = threadIdx.x;
    const int warp = tid >> 5, lane = tid & 31;
    const int m_off = warp * 16;
    const int g  = lane >> 2;
    const int tq = lane & 3;

    __shared__ float As[128][36];
    __shared__ float Bs[32][56];
    __shared__ float hs[128][25];
    __shared__ float sws[576];
    __shared__ float ssb[24];

    for (int idx = tid; idx < 576; idx += 256) sws[idx] = sW[idx];
    if (tid < 24) ssb[tid] = sb[tid];

    float acc[6][4];
#pragma unroll
    for (int nt = 0; nt < 6; ++nt) {
        int c0 = nt * 8 + 2 * tq;
        float b0 = (nt < 3) ? gb[c0] : fb[c0 - 24];
        float b1 = (nt < 3) ? gb[c0 + 1] : fb[c0 - 23];
        acc[nt][0] = b0; acc[nt][1] = b1; acc[nt][2] = b0; acc[nt][3] = b1;
    }

    for (int k0 = 0; k0 < 512; k0 += 32) {
        const int tap = k0 >> 8;
        const int ch  = k0 & 255;
        __syncthreads();
#pragma unroll
        for (int q = 0; q < 4; ++q) {
            int idx = tid + q * 256;
            int r = idx >> 3, c4 = idx & 7;
            int row = t0 + r + tap;
            if (row > T1 - 1) row = T1 - 1;
            float4 v = *reinterpret_cast<const float4*>(
                g_h1 + ((size_t)b * T1 + row) * CIN + ch + c4 * 4);
            As[r][c4 * 4 + 0] = to_tf32(v.x);
            As[r][c4 * 4 + 1] = to_tf32(v.y);
            As[r][c4 * 4 + 2] = to_tf32(v.z);
            As[r][c4 * 4 + 3] = to_tf32(v.w);
        }
        for (int idx = tid; idx < 32 * 48; idx += 256) {
            int r = idx / 48, c = idx % 48;
            int kk2 = k0 + r;
            int tp = kk2 >> 8, chh = kk2 & 255;
            float v = (c < 24) ? gW[tp * 6144 + chh * 24 + c]
                               : fW[tp * 6144 + chh * 24 + (c - 24)];
            Bs[r][c] = to_tf32(v);
        }
        __syncthreads();
#pragma unroll
        for (int kk = 0; kk < 32; kk += 8) {
            uint32_t af[4];
            af[0] = __float_as_uint(As[m_off + g][kk + tq]);
            af[1] = __float_as_uint(As[m_off + g + 8][kk + tq]);
            af[2] = __float_as_uint(As[m_off + g][kk + tq + 4]);
            af[3] = __float_as_uint(As[m_off + g + 8][kk + tq + 4]);
            uint32_t bf[6][2];
#pragma unroll
            for (int nt = 0; nt < 6; ++nt) {
                int c0 = nt * 8 + g;
                bf[nt][0] = __float_as_uint(Bs[kk + tq][c0]);
                bf[nt][1] = __float_as_uint(Bs[kk + tq + 4][c0]);
            }
#pragma unroll
            for (int nt = 0; nt < 6; ++nt)
                mma_tf32(acc[nt], af, bf[nt]);
        }
    }

    const int r0 = m_off + g, r1 = m_off + g + 8;
#pragma unroll
    for (int nt = 0; nt < 3; ++nt) {
        int c0 = nt * 8 + 2 * tq;
        hs[r0][c0]     = tanhf(acc[nt + 3][0]) * sigmoidf_fast(acc[nt][0]);
        hs[r0][c0 + 1] = tanhf(acc[nt + 3][1]) * sigmoidf_fast(acc[nt][1]);
        hs[r1][c0]     = tanhf(acc[nt + 3][2]) * sigmoidf_fast(acc[nt][2]);
        hs[r1][c0 + 1] = tanhf(acc[nt + 3][3]) * sigmoidf_fast(acc[nt][3]);
    }
    __syncthreads();

    const int oid = tid & 31;
    const int o = (oid < 24) ? oid : 0;
    const int tg = tid >> 5;
#pragma unroll
    for (int rr = 0; rr < 16; ++rr) {
        int r = tg * 16 + rr;
        float s = ssb[o];
#pragma unroll
        for (int c = 0; c < 24; ++c) s += hs[r][c] * sws[c * 24 + o];
        int t = t0 + r;
        if (oid < 24 && t < L0)
            g_bufA[((size_t)b * LMAX + t) * 24 + o] = s;
    }
}

// ---------------------------------------------------------------------------
// K3: dilated gated layer via tensor cores.
// Block = 128 timesteps. MMA1: A[128x48] (taps t, t+d) x B1[48x48] (gate|filter).
// Nonlinearity -> Hs[128x24]. MMA2: Hs x sW[24x24]. dir: A->B or B->A.
// ---------------------------------------------------------------------------
__global__ __launch_bounds__(256) void k_dilated_mma(const float* __restrict__ gW,
                                                     const float* __restrict__ gb,
                                                     const float* __restrict__ fW,
                                                     const float* __restrict__ fb,
                                                     const float* __restrict__ sW,
                                                     const float* __restrict__ sb,
                                                     int d, int Lout, int dir) {
    const float* in   = dir ? g_bufB : g_bufA;
    float*       outp = dir ? g_bufA : g_bufB;
    const int b  = blockIdx.y;
    const int t0 = blockIdx.x * 128;
    const int tid = threadIdx.x;
    const int warp = tid >> 5, lane = tid & 31;
    const int m_off = warp * 16;
    const int g  = lane >> 2;
    const int tq = lane & 3;

    __shared__ float As[128][52];
    __shared__ float Bs1[48][56];
    __shared__ float Hs[128][28];
    __shared__ float Bs2[24][40];

    const int Lin = Lout + d;
    // A tile: 128 rows x 48 cols (tap0: 0-23, tap1: 24-47), 6 float4 per thread
#pragma unroll
    for (int q = 0; q < 6; ++q) {
        int idx = tid + q * 256;
        int r = idx / 12, v = idx % 12;
        int tap = v / 6, c4 = v % 6;
        int row = t0 + r + tap * d;
        float4 val = make_float4(0.f, 0.f, 0.f, 0.f);
        if (row < Lin)
            val = *reinterpret_cast<const float4*>(in + ((size_t)b * LMAX + row) * 24 + c4 * 4);
        int cc = tap * 24 + c4 * 4;
        As[r][cc + 0] = to_tf32(val.x);
        As[r][cc + 1] = to_tf32(val.y);
        As[r][cc + 2] = to_tf32(val.z);
        As[r][cc + 3] = to_tf32(val.w);
    }
    // B1: 48x48 (k: tap*24+ci ; n<24 gate, n>=24 filter)
    for (int idx = tid; idx < 48 * 48; idx += 256) {
        int k = idx / 48, n = idx % 48;
        int tap = k / 24, ci = k % 24;
        float w = (n < 24) ? gW[tap * 576 + ci * 24 + n]
                           : fW[tap * 576 + ci * 24 + (n - 24)];
        Bs1[k][n] = to_tf32(w);
    }
    // B2: scale weights 24x24
    for (int idx = tid; idx < 576; idx += 256)
        Bs2[idx / 24][idx % 24] = to_tf32(sW[idx]);
    __syncthreads();

    // MMA1
    float acc[6][4];
#pragma unroll
    for (int nt = 0; nt < 6; ++nt) {
        int c0 = (nt < 3) ? (nt * 8 + 2 * tq) : ((nt - 3) * 8 + 2 * tq);
        float b0 = (nt < 3) ? gb[c0] : fb[c0];
        float b1 = (nt < 3) ? gb[c0 + 1] : fb[c0 + 1];
        acc[nt][0] = b0; acc[nt][1] = b1; acc[nt][2] = b0; acc[nt][3] = b1;
    }
#pragma unroll
    for (int kk = 0; kk < 48; kk += 8) {
        uint32_t af[4];
        af[0] = __float_as_uint(As[m_off + g][kk + tq]);
        af[1] = __float_as_uint(As[m_off + g + 8][kk + tq]);
        af[2] = __float_as_uint(As[m_off + g][kk + tq + 4]);
        af[3] = __float_as_uint(As[m_off + g + 8][kk + tq + 4]);
        uint32_t bf[6][2];
#pragma unroll
        for (int nt = 0; nt < 6; ++nt) {
            int c0 = nt * 8 + g;
            bf[nt][0] = __float_as_uint(Bs1[kk + tq][c0]);
            bf[nt][1] = __float_as_uint(Bs1[kk + tq + 4][c0]);
        }
#pragma unroll
        for (int nt = 0; nt < 6; ++nt)
            mma_tf32(acc[nt], af, bf[nt]);
    }

    // Nonlinearity -> Hs
    const int r0 = m_off + g, r1 = r0 + 8;
#pragma unroll
    for (int nt = 0; nt < 3; ++nt) {
        int c0 = nt * 8 + 2 * tq;
        Hs[r0][c0]     = to_tf32(tanhf(acc[nt + 3][0]) * sigmoidf_fast(acc[nt][0]));
        Hs[r0][c0 + 1] = to_tf32(tanhf(acc[nt + 3][1]) * sigmoidf_fast(acc[nt][1]));
        Hs[r1][c0]     = to_tf32(tanhf(acc[nt + 3][2]) * sigmoidf_fast(acc[nt][2]));
        Hs[r1][c0 + 1] = to_tf32(tanhf(acc[nt + 3][3]) * sigmoidf_fast(acc[nt][3]));
    }
    __syncthreads();

    // MMA2: Hs[128x24] x Bs2[24x24]
    float acc2[3][4];
#pragma unroll
    for (int nt = 0; nt < 3; ++nt) {
        int c0 = nt * 8 + 2 * tq;
        float b0 = sb[c0], b1 = sb[c0 + 1];
        acc2[nt][0] = b0; acc2[nt][1] = b1; acc2[nt][2] = b0; acc2[nt][3] = b1;
    }
#pragma unroll
    for (int kk = 0; kk < 24; kk += 8) {
        uint32_t af[4];
        af[0] = __float_as_uint(Hs[r0][kk + tq]);
        af[1] = __float_as_uint(Hs[r1][kk + tq]);
        af[2] = __float_as_uint(Hs[r0][kk + tq + 4]);
        af[3] = __float_as_uint(Hs[r1][kk + tq + 4]);
        uint32_t bf[3][2];
#pragma unroll
        for (int nt = 0; nt < 3; ++nt) {
            int c0 = nt * 8 + g;
            bf[nt][0] = __float_as_uint(Bs2[kk + tq][c0]);
            bf[nt][1] = __float_as_uint(Bs2[kk + tq + 4][c0]);
        }
#pragma unroll
        for (int nt = 0; nt < 3; ++nt)
            mma_tf32(acc2[nt], af, bf[nt]);
    }

    // Store
#pragma unroll
    for (int nt = 0; nt < 3; ++nt) {
        int col = nt * 8 + 2 * tq;
        int ta = t0 + r0;
        if (ta < Lout) {
            *reinterpret_cast<float2*>(outp + ((size_t)b * LMAX + ta) * 24 + col) =
                make_float2(acc2[nt][0], acc2[nt][1]);
        }
        int tb = t0 + r1;
        if (tb < Lout) {
            *reinterpret_cast<float2*>(outp + ((size_t)b * LMAX + tb) * 24 + col) =
                make_float2(acc2[nt][2], acc2[nt][3]);
        }
    }
}

// ---------------------------------------------------------------------------
// K4a: act128 = relu(resW conv of (prev[t+256] + out[t])). 64 t per block.
// ---------------------------------------------------------------------------
__global__ __launch_bounds__(256) void k_resrelu(const float* __restrict__ resW,
                                                 const float* __restrict__ resb) {
    const int b  = blockIdx.y;
    const int t0 = blockIdx.x * 64;
    const int tid = threadIdx.x;
    const int og = tid & 31;
    const int tg = tid >> 5;

    __shared__ float s_in[64][25];
    for (int idx = tid; idx < 64 * 24; idx += 256) {
        int r = idx / 24, c = idx % 24;
        size_t prow = (size_t)b * LMAX + 256 + t0 + r;
        size_t orow = (size_t)b * LMAX + t0 + r;
        s_in[r][c] = g_bufA[prow * 24 + c] + g_bufB[orow * 24 + c];
    }
    __syncthreads();

    const float4 bb = reinterpret_cast<const float4*>(resb)[og];
    float acc[8][4];
#pragma unroll
    for (int rr = 0; rr < 8; ++rr) {
        acc[rr][0] = bb.x; acc[rr][1] = bb.y; acc[rr][2] = bb.z; acc[rr][3] = bb.w;
    }
#pragma unroll 4
    for (int c = 0; c < 24; ++c) {
        float4 w = reinterpret_cast<const float4*>(resW)[c * 32 + og];
#pragma unroll
        for (int rr = 0; rr < 8; ++rr) {
            float xin = s_in[tg * 8 + rr][c];
            acc[rr][0] += xin * w.x; acc[rr][1] += xin * w.y;
            acc[rr][2] += xin * w.z; acc[rr][3] += xin * w.w;
        }
    }
#pragma unroll
    for (int rr = 0; rr < 8; ++rr) {
        int row = t0 + tg * 8 + rr;
        float4 v = make_float4(fmaxf(acc[rr][0], 0.f), fmaxf(acc[rr][1], 0.f),
                               fmaxf(acc[rr][2], 0.f), fmaxf(acc[rr][3], 0.f));
        reinterpret_cast<float4*>(g_act128 + ((size_t)b * TOUT + row) * 128)[og] = v;
    }
}

// ---------------------------------------------------------------------------
// K4b: act256 = relu(act128 @ f1W + f1b). tf32 GEMM, 128x128 tile, K=128.
// ---------------------------------------------------------------------------
__global__ __launch_bounds__(256) void k_gemm_relu(const float* __restrict__ f1W,
                                                   const float* __restrict__ f1b) {
    const int t0 = blockIdx.x * 128;
    const int o0 = blockIdx.y * 128;
    const int b  = blockIdx.z;
    const int tid  = threadIdx.x;
    const int warp = tid >> 5, lane = tid & 31;
    const int m_off = (warp >> 2) * 64;
    const int n_off = (warp & 3) * 32;
    const int g  = lane >> 2;
    const int tq = lane & 3;

    __shared__ float As[128][36];
    __shared__ float Bs[32][136];

    float acc[4][4][4];
#pragma unroll
    for (int mt = 0; mt < 4; ++mt)
#pragma unroll
        for (int nt = 0; nt < 4; ++nt)
#pragma unroll
            for (int q = 0; q < 4; ++q) acc[mt][nt][q] = 0.0f;

    for (int k0 = 0; k0 < 128; k0 += 32) {
        __syncthreads();
#pragma unroll
        for (int q = 0; q < 4; ++q) {
            int idx = tid + q * 256;
            int r = idx >> 3, c4 = idx & 7;
            float4 v = *reinterpret_cast<const float4*>(
                g_act128 + ((size_t)b * TOUT + t0 + r) * 128 + k0 + c4 * 4);
            As[r][c4 * 4 + 0] = to_tf32(v.x);
            As[r][c4 * 4 + 1] = to_tf32(v.y);
            As[r][c4 * 4 + 2] = to_tf32(v.z);
            As[r][c4 * 4 + 3] = to_tf32(v.w);
        }
#pragma unroll
        for (int q = 0; q < 4; ++q) {
            int idx = tid + q * 256;
            int r = idx >> 5, c4 = idx & 31;
            float4 v = *reinterpret_cast<const float4*>(
                f1W + (size_t)(k0 + r) * 256 + o0 + c4 * 4);
            Bs[r][c4 * 4 + 0] = to_tf32(v.x);
            Bs[r][c4 * 4 + 1] = to_tf32(v.y);
            Bs[r][c4 * 4 + 2] = to_tf32(v.z);
            Bs[r][c4 * 4 + 3] = to_tf32(v.w);
        }
        __syncthreads();
#pragma unroll
        for (int kk = 0; kk < 32; kk += 8) {
            uint32_t af[4][4];
#pragma unroll
            for (int mt = 0; mt < 4; ++mt) {
                int r0 = m_off + mt * 16 + g;
                af[mt][0] = __float_as_uint(As[r0][kk + tq]);
                af[mt][1] = __float_as_uint(As[r0 + 8][kk + tq]);
                af[mt][2] = __float_as_uint(As[r0][kk + tq + 4]);
                af[mt][3] = __float_as_uint(As[r0 + 8][kk + tq + 4]);
            }
            uint32_t bf[4][2];
#pragma unroll
            for (int nt = 0; nt < 4; ++nt) {
                int c0 = n_off + nt * 8 + g;
                bf[nt][0] = __float_as_uint(Bs[kk + tq][c0]);
                bf[nt][1] = __float_as_uint(Bs[kk + tq + 4][c0]);
            }
#pragma unroll
            for (int mt = 0; mt < 4; ++mt)
#pragma unroll
                for (int nt = 0; nt < 4; ++nt)
                    mma_tf32(acc[mt][nt], af[mt], bf[nt]);
        }
    }
#pragma unroll
    for (int nt = 0; nt < 4; ++nt) {
        const int col = o0 + n_off + nt * 8 + 2 * tq;
        const float2 bias = *reinterpret_cast<const float2*>(f1b + col);
#pragma unroll
        for (int mt = 0; mt < 4; ++mt) {
            int row = t0 + m_off + mt * 16 + g;
            float2 v0 = make_float2(fmaxf(acc[mt][nt][0] + bias.x, 0.f),
                                    fmaxf(acc[mt][nt][1] + bias.y, 0.f));
            float2 v1 = make_float2(fmaxf(acc[mt][nt][2] + bias.x, 0.f),
                                    fmaxf(acc[mt][nt][3] + bias.y, 0.f));
            *reinterpret_cast<float2*>(g_act256 + ((size_t)b * TOUT + row) * 256 + col) = v0;
            *reinterpret_cast<float2*>(g_act256 + ((size_t)b * TOUT + row + 8) * 256 + col) = v1;
        }
    }
}

// ---------------------------------------------------------------------------
// K4c: y = softmax(act256 @ f2W + f2b). tf32 GEMM, M tile 64, full N=256,
// BK=16, 8 warps = 2(M)x4(N), warp tile 32x64. Fused row softmax.
// ---------------------------------------------------------------------------
__global__ __launch_bounds__(256) void k_gemm_softmax(const float* __restrict__ f2W,
                                                      const float* __restrict__ f2b,
                                                      float* __restrict__ y) {
    const int t0 = blockIdx.x * 64;
    const int b  = blockIdx.y;
    const int tid  = threadIdx.x;
    const int warp = tid >> 5, lane = tid & 31;
    const int mw = warp >> 2;
    const int nw = warp & 3;
    const int m_off = mw * 32;
    const int n_off = nw * 64;
    const int g  = lane >> 2;
    const int tq = lane & 3;

    __shared__ float As[64][20];
    __shared__ float Bs[16][264];
    __shared__ float red1[64][4];
    __shared__ float red2[64][4];

    float acc[2][8][4];
#pragma unroll
    for (int mt = 0; mt < 2; ++mt)
#pragma unroll
        for (int nt = 0; nt < 8; ++nt)
#pragma unroll
            for (int q = 0; q < 4; ++q) acc[mt][nt][q] = 0.0f;

    for (int k0 = 0; k0 < 256; k0 += 16) {
        __syncthreads();
        {
            int idx = tid;
            int r = idx >> 2, c4 = idx & 3;
            float4 v = *reinterpret_cast<const float4*>(
                g_act256 + ((size_t)b * TOUT + t0 + r) * 256 + k0 + c4 * 4);
            As[r][c4 * 4 + 0] = to_tf32(v.x);
            As[r][c4 * 4 + 1] = to_tf32(v.y);
            As[r][c4 * 4 + 2] = to_tf32(v.z);
            As[r][c4 * 4 + 3] = to_tf32(v.w);
        }
#pragma unroll
        for (int q = 0; q < 4; ++q) {
            int idx = tid + q * 256;
            int r = idx >> 6, c4 = idx & 63;
            float4 v = *reinterpret_cast<const float4*>(
                f2W + (size_t)(k0 + r) * 256 + c4 * 4);
            Bs[r][c4 * 4 + 0] = to_tf32(v.x);
            Bs[r][c4 * 4 + 1] = to_tf32(v.y);
            Bs[r][c4 * 4 + 2] = to_tf32(v.z);
            Bs[r][c4 * 4 + 3] = to_tf32(v.w);
        }
        __syncthreads();
#pragma unroll
        for (int kk = 0; kk < 16; kk += 8) {
            uint32_t af[2][4];
#pragma unroll
            for (int mt = 0; mt < 2; ++mt) {
                int r0 = m_off + mt * 16 + g;
                af[mt][0] = __float_as_uint(As[r0][kk + tq]);
                af[mt][1] = __float_as_uint(As[r0 + 8][kk + tq]);
                af[mt][2] = __float_as_uint(As[r0][kk + tq + 4]);
                af[mt][3] = __float_as_uint(As[r0 + 8][kk + tq + 4]);
            }
            uint32_t bf[8][2];
#pragma unroll
            for (int nt = 0; nt < 8; ++nt) {
                int c0 = n_off + nt * 8 + g;
                bf[nt][0] = __float_as_uint(Bs[kk + tq][c0]);
                bf[nt][1] = __float_as_uint(Bs[kk + tq + 4][c0]);
            }
#pragma unroll
            for (int mt = 0; mt < 2; ++mt)
#pragma unroll
                for (int nt = 0; nt < 8; ++nt)
                    mma_tf32(acc[mt][nt], af[mt], bf[nt]);
        }
    }

#pragma unroll
    for (int nt = 0; nt < 8; ++nt) {
        const int col = n_off + nt * 8 + 2 * tq;
        const float2 bias = *reinterpret_cast<const float2*>(f2b + col);
#pragma unroll
        for (int mt = 0; mt < 2; ++mt) {
            acc[mt][nt][0] += bias.x; acc[mt][nt][1] += bias.y;
            acc[mt][nt][2] += bias.x; acc[mt][nt][3] += bias.y;
        }
    }

    float rmax[2][2];
#pragma unroll
    for (int mt = 0; mt < 2; ++mt)
#pragma unroll
        for (int rr = 0; rr < 2; ++rr) {
            float m = -1e30f;
#pragma unroll
            for (int nt = 0; nt < 8; ++nt) {
                m = fmaxf(m, acc[mt][nt][rr * 2 + 0]);
                m = fmaxf(m, acc[mt][nt][rr * 2 + 1]);
            }
            m = fmaxf(m, __shfl_xor_sync(0xffffffffu, m, 1));
            m = fmaxf(m, __shfl_xor_sync(0xffffffffu, m, 2));
            rmax[mt][rr] = m;
            if (tq == 0) red1[m_off + mt * 16 + rr * 8 + g][nw] = m;
        }
    __syncthreads();
#pragma unroll
    for (int mt = 0; mt < 2; ++mt)
#pragma unroll
        for (int rr = 0; rr < 2; ++rr) {
            int r = m_off + mt * 16 + rr * 8 + g;
            rmax[mt][rr] = fmaxf(fmaxf(red1[r][0], red1[r][1]),
                                 fmaxf(red1[r][2], red1[r][3]));
        }

    float rsum[2][2];
#pragma unroll
    for (int mt = 0; mt < 2; ++mt)
#pragma unroll
        for (int rr = 0; rr < 2; ++rr) {
            float s = 0.f;
#pragma unroll
            for (int nt = 0; nt < 8; ++nt) {
                float e0 = __expf(acc[mt][nt][rr * 2 + 0] - rmax[mt][rr]);
                float e1 = __expf(acc[mt][nt][rr * 2 + 1] - rmax[mt][rr]);
                acc[mt][nt][rr * 2 + 0] = e0;
                acc[mt][nt][rr * 2 + 1] = e1;
                s += e0 + e1;
            }
            s += __shfl_xor_sync(0xffffffffu, s, 1);
            s += __shfl_xor_sync(0xffffffffu, s, 2);
            rsum[mt][rr] = s;
            if (tq == 0) red2[m_off + mt * 16 + rr * 8 + g][nw] = s;
        }
    __syncthreads();
#pragma unroll
    for (int mt = 0; mt < 2; ++mt)
#pragma unroll
        for (int rr = 0; rr < 2; ++rr) {
            int r = m_off + mt * 16 + rr * 8 + g;
            rsum[mt][rr] = 1.0f / (red2[r][0] + red2[r][1] + red2[r][2] + red2[r][3]);
        }

#pragma unroll
    for (int nt = 0; nt < 8; ++nt) {
        const int col = n_off + nt * 8 + 2 * tq;
#pragma unroll
        for (int mt = 0; mt < 2; ++mt) {
            int row = t0 + m_off + mt * 16 + g;
            float2 v0 = make_float2(acc[mt][nt][0] * rsum[mt][0],
                                    acc[mt][nt][1] * rsum[mt][0]);
            float2 v1 = make_float2(acc[mt][nt][2] * rsum[mt][1],
                                    acc[mt][nt][3] * rsum[mt][1]);
            *reinterpret_cast<float2*>(y + ((size_t)b * TOUT + row) * 256 + col) = v0;
            *reinterpret_cast<float2*>(y + ((size_t)b * TOUT + row + 8) * 256 + col) = v1;
        }
    }
}

// ---------------------------------------------------------------------------
extern "C" void kernel_launch(void* const* d_in, const int* in_sizes, int n_in,
                              void* d_out, int out_size) {
    const float* x     = (const float*)d_in[0];
    const float* cW    = (const float*)d_in[1];
    const float* cb    = (const float*)d_in[2];
    const float* gW0   = (const float*)d_in[3];
    const float* gb0   = (const float*)d_in[4];
    const float* fW0   = (const float*)d_in[5];
    const float* fb0   = (const float*)d_in[6];
    const float* sW0   = (const float*)d_in[7];
    const float* sb0   = (const float*)d_in[8];
    const float* gateW = (const float*)d_in[9];
    const float* gateB = (const float*)d_in[10];
    const float* filtW = (const float*)d_in[11];
    const float* filtB = (const float*)d_in[12];
    const float* scW   = (const float*)d_in[13];
    const float* scB   = (const float*)d_in[14];
    const float* resW  = (const float*)d_in[15];
    const float* resB  = (const float*)d_in[16];
    const float* f1W   = (const float*)d_in[17];
    const float* f1b   = (const float*)d_in[18];
    const float* f2W   = (const float*)d_in[19];
    const float* f2b   = (const float*)d_in[20];
    float* out = (float*)d_out;

    k_causal_mma<<<dim3(128, 2, BATCH), 256>>>(x, cW, cb);
    k_gated0_mma<<<dim3(128, BATCH), 256>>>(gW0, gb0, fW0, fb0, sW0, sb0);

    int L = L0;
    for (int i = 0; i < 9; ++i) {
        int d = 2 << i;          // 2,4,...,512
        int Lout = L - d;
        int nb = (Lout + 127) / 128;
        // Only the LAST residual conv contributes to the output (acc is
        // overwritten each iteration in the reference), so res convs 0..7 are skipped.
        k_dilated_mma<<<dim3(nb, BATCH), 256>>>(gateW + i * 1152, gateB + i * 24,
                                                filtW + i * 1152, filtB + i * 24,
                                                scW + i * 576, scB + i * 24,
                                                d, Lout, i & 1);
        L = Lout;
    }
    // prev (input of layer i=8) lives in g_bufA (len 15872); its output in g_bufB (15360)
    k_resrelu<<<dim3(TOUT / 64, BATCH), 256>>>(resW + 8 * 24 * 128, resB + 8 * 128);
    k_gemm_relu<<<dim3(TOUT / 128, 2, BATCH), 256>>>(f1W, f1b);
    k_gemm_softmax<<<dim3(TOUT / 64, BATCH), 256>>>(f2W, f2b, out);
}

// round 7
// speedup vs baseline: 3.2115x; 1.1226x over previous
#include <cuda_runtime.h>
#include <cuda_bf16.h>
#include <cstdint>
#include <cstddef>

#define BATCH 8
#define TLEN  16384
#define CIN   256
#define T1    16383   // causal conv output length
#define L0    16382   // gated0 output length
#define LMAX  16382   // per-batch row stride for 24-ch buffers
#define TOUT  15360

// Scratch (static device globals: allocation-free per harness rules)
__device__ __nv_bfloat16 g_h1[(size_t)BATCH * T1 * CIN];        // 67 MB
__device__ float         g_bufA[(size_t)BATCH * LMAX * 24];     // 12.6 MB
__device__ float         g_bufB[(size_t)BATCH * LMAX * 24];     // 12.6 MB
__device__ __nv_bfloat16 g_act128[(size_t)BATCH * TOUT * 128];  // 31 MB
__device__ __nv_bfloat16 g_act256[(size_t)BATCH * TOUT * 256];  // 63 MB

__device__ __forceinline__ float to_tf32(float x) {
    asm("cvt.rna.tf32.f32 %0, %0;" : "+f"(x));
    return x;
}
__device__ __forceinline__ uint32_t frag_tf32(float x) {
    asm("cvt.rna.tf32.f32 %0, %0;" : "+f"(x));
    return __float_as_uint(x);
}
__device__ __forceinline__ float tanh_fast(float x) {
    float y;
    asm("tanh.approx.f32 %0, %1;" : "=f"(y) : "f"(x));
    return y;
}
__device__ __forceinline__ float sigmoid_fast(float x) {
    return __fdividef(1.0f, 1.0f + __expf(-x));
}

__device__ __forceinline__ void mma_tf32(float c[4], const uint32_t a[4], const uint32_t b[2]) {
    asm volatile(
        "mma.sync.aligned.m16n8k8.row.col.f32.tf32.tf32.f32 "
        "{%0,%1,%2,%3}, {%4,%5,%6,%7}, {%8,%9}, {%0,%1,%2,%3};"
        : "+f"(c[0]), "+f"(c[1]), "+f"(c[2]), "+f"(c[3])
        : "r"(a[0]), "r"(a[1]), "r"(a[2]), "r"(a[3]), "r"(b[0]), "r"(b[1]));
}

__device__ __forceinline__ void cp16(uint32_t smem_dst, const void* gsrc) {
    asm volatile("cp.async.ca.shared.global [%0], [%1], 16;" :: "r"(smem_dst), "l"(gsrc));
}
__device__ __forceinline__ void cp_commit() {
    asm volatile("cp.async.commit_group;" ::: "memory");
}
__device__ __forceinline__ void cp_wait_all() {
    asm volatile("cp.async.wait_group 0;" ::: "memory");
}

// Unpack a uint4 (8 bf16) into 8 floats (bf16->f32 is tf32-exact; no cvt needed)
__device__ __forceinline__ void bf16x8_to_f32(const uint4& u, float* dst) {
    const __nv_bfloat162* p = reinterpret_cast<const __nv_bfloat162*>(&u);
#pragma unroll
    for (int i = 0; i < 4; ++i) {
        float2 f = __bfloat1622float2(p[i]);
        dst[i * 2 + 0] = f.x;
        dst[i * 2 + 1] = f.y;
    }
}

// ---------------------------------------------------------------------------
// K1: causal conv as tf32 GEMM, 2-stage cp.async pipeline. Output -> bf16 h1.
// ---------------------------------------------------------------------------
__global__ __launch_bounds__(256) void k_causal_mma(const float* __restrict__ x,
                                                    const float* __restrict__ W,
                                                    const float* __restrict__ cb) {
    const int t0 = blockIdx.x * 128;
    const int o0 = blockIdx.y * 128;
    const int b  = blockIdx.z;
    const int tid  = threadIdx.x;
    const int warp = tid >> 5, lane = tid & 31;
    const int m_off = (warp >> 2) * 64;
    const int n_off = (warp & 3) * 32;
    const int g  = lane >> 2;
    const int tq = lane & 3;

    __shared__ float As[2][128][36];
    __shared__ float Bs[2][32][136];
    const uint32_t as_base = (uint32_t)__cvta_generic_to_shared(&As[0][0][0]);
    const uint32_t bs_base = (uint32_t)__cvta_generic_to_shared(&Bs[0][0][0]);

    float acc[4][4][4];
#pragma unroll
    for (int mt = 0; mt < 4; ++mt)
#pragma unroll
        for (int nt = 0; nt < 4; ++nt)
#pragma unroll
            for (int q = 0; q < 4; ++q) acc[mt][nt][q] = 0.0f;

#define CAUSAL_LOAD(chunk, s) do {                                              \
    int k0 = (chunk) * 32; int tap = k0 >> 8; int ch = k0 & 255;                \
    _Pragma("unroll")                                                            \
    for (int q = 0; q < 4; ++q) {                                                \
        int idx = tid + q * 256;                                                 \
        int r = idx >> 3, c4 = idx & 7;                                          \
        int row = t0 + r + tap; if (row > TLEN - 1) row = TLEN - 1;              \
        cp16(as_base + (uint32_t)(((s) * 128 * 36 + r * 36 + c4 * 4) * 4),       \
             x + ((size_t)b * TLEN + row) * CIN + ch + c4 * 4);                  \
    }                                                                            \
    _Pragma("unroll")                                                            \
    for (int q = 0; q < 4; ++q) {                                                \
        int idx = tid + q * 256;                                                 \
        int r = idx >> 5, c4 = idx & 31;                                         \
        cp16(bs_base + (uint32_t)(((s) * 32 * 136 + r * 136 + c4 * 4) * 4),      \
             W + (size_t)(k0 + r) * CIN + o0 + c4 * 4);                          \
    }                                                                            \
} while (0)

    CAUSAL_LOAD(0, 0);
    cp_commit();

    for (int c = 0; c < 16; ++c) {
        const int s = c & 1;
        cp_wait_all();
        __syncthreads();
        if (c < 15) { CAUSAL_LOAD(c + 1, s ^ 1); cp_commit(); }
#pragma unroll
        for (int kk = 0; kk < 32; kk += 8) {
            uint32_t af[4][4];
#pragma unroll
            for (int mt = 0; mt < 4; ++mt) {
                int r0 = m_off + mt * 16 + g;
                af[mt][0] = frag_tf32(As[s][r0][kk + tq]);
                af[mt][1] = frag_tf32(As[s][r0 + 8][kk + tq]);
                af[mt][2] = frag_tf32(As[s][r0][kk + tq + 4]);
                af[mt][3] = frag_tf32(As[s][r0 + 8][kk + tq + 4]);
            }
            uint32_t bf[4][2];
#pragma unroll
            for (int nt = 0; nt < 4; ++nt) {
                int c0 = n_off + nt * 8 + g;
                bf[nt][0] = frag_tf32(Bs[s][kk + tq][c0]);
                bf[nt][1] = frag_tf32(Bs[s][kk + tq + 4][c0]);
            }
#pragma unroll
            for (int mt = 0; mt < 4; ++mt)
#pragma unroll
                for (int nt = 0; nt < 4; ++nt)
                    mma_tf32(acc[mt][nt], af[mt], bf[nt]);
        }
        __syncthreads();
    }
#undef CAUSAL_LOAD

#pragma unroll
    for (int nt = 0; nt < 4; ++nt) {
        const int col = o0 + n_off + nt * 8 + 2 * tq;
        const float2 bias = *reinterpret_cast<const float2*>(cb + col);
#pragma unroll
        for (int mt = 0; mt < 4; ++mt) {
            int row = t0 + m_off + mt * 16 + g;
            if (row < T1) {
                *reinterpret_cast<__nv_bfloat162*>(g_h1 + ((size_t)b * T1 + row) * CIN + col) =
                    __float22bfloat162_rn(make_float2(acc[mt][nt][0] + bias.x,
                                                      acc[mt][nt][1] + bias.y));
            }
            if (row + 8 < T1) {
                *reinterpret_cast<__nv_bfloat162*>(g_h1 + ((size_t)b * T1 + row + 8) * CIN + col) =
                    __float22bfloat162_rn(make_float2(acc[mt][nt][2] + bias.x,
                                                      acc[mt][nt][3] + bias.y));
            }
        }
    }
}

// ---------------------------------------------------------------------------
// K2: gated0 as tf32 GEMM on bf16 h1: A[t,k]=h1[t+(k>>8),k&255] (K=512),
// B=[gW|fW] (N=48). M tile 128, 8 warps in M. Epilogue: gate + 24x24 1x1.
// ---------------------------------------------------------------------------
__global__ __launch_bounds__(256) void k_gated0_mma(const float* __restrict__ gW,
                                                    const float* __restrict__ gb,
                                                    const float* __restrict__ fW,
                                                    const float* __restrict__ fb,
                                                    const float* __restrict__ sW,
                                                    const float* __restrict__ sb) {
    const int t0 = blockIdx.x * 128;
    const int b  = blockIdx.y;
    const int tid  = threadIdx.x;
    const int warp = tid >> 5, lane = tid & 31;
    const int m_off = warp * 16;
    const int g  = lane >> 2;
    const int tq = lane & 3;

    __shared__ float As[128][36];
    __shared__ float Bs[32][56];
    __shared__ float hs[128][25];
    __shared__ float sws[576];
    __shared__ float ssb[24];

    for (int idx = tid; idx < 576; idx += 256) sws[idx] = sW[idx];
    if (tid < 24) ssb[tid] = sb[tid];

    float acc[6][4];
#pragma unroll
    for (int nt = 0; nt < 6; ++nt) {
        int c0 = nt * 8 + 2 * tq;
        float b0 = (nt < 3) ? gb[c0] : fb[c0 - 24];
        float b1 = (nt < 3) ? gb[c0 + 1] : fb[c0 - 23];
        acc[nt][0] = b0; acc[nt][1] = b1; acc[nt][2] = b0; acc[nt][3] = b1;
    }

    for (int k0 = 0; k0 < 512; k0 += 32) {
        const int tap = k0 >> 8;
        const int ch  = k0 & 255;
        __syncthreads();
        // A tile: 128 rows x 32 bf16 cols -> 512 uint4, 2 per thread
#pragma unroll
        for (int q = 0; q < 2; ++q) {
            int idx = tid + q * 256;
            int r = idx >> 2, u4 = idx & 3;
            int row = t0 + r + tap;
            if (row > T1 - 1) row = T1 - 1;
            uint4 u = *reinterpret_cast<const uint4*>(
                g_h1 + ((size_t)b * T1 + row) * CIN + ch + u4 * 8);
            bf16x8_to_f32(u, &As[r][u4 * 8]);
        }
        for (int idx = tid; idx < 32 * 48; idx += 256) {
            int r = idx / 48, c = idx % 48;
            int kk2 = k0 + r;
            int tp = kk2 >> 8, chh = kk2 & 255;
            float v = (c < 24) ? gW[tp * 6144 + chh * 24 + c]
                               : fW[tp * 6144 + chh * 24 + (c - 24)];
            Bs[r][c] = to_tf32(v);
        }
        __syncthreads();
#pragma unroll
        for (int kk = 0; kk < 32; kk += 8) {
            uint32_t af[4];
            af[0] = __float_as_uint(As[m_off + g][kk + tq]);
            af[1] = __float_as_uint(As[m_off + g + 8][kk + tq]);
            af[2] = __float_as_uint(As[m_off + g][kk + tq + 4]);
            af[3] = __float_as_uint(As[m_off + g + 8][kk + tq + 4]);
            uint32_t bf[6][2];
#pragma unroll
            for (int nt = 0; nt < 6; ++nt) {
                int c0 = nt * 8 + g;
                bf[nt][0] = __float_as_uint(Bs[kk + tq][c0]);
                bf[nt][1] = __float_as_uint(Bs[kk + tq + 4][c0]);
            }
#pragma unroll
            for (int nt = 0; nt < 6; ++nt)
                mma_tf32(acc[nt], af, bf[nt]);
        }
    }

    const int r0 = m_off + g, r1 = m_off + g + 8;
#pragma unroll
    for (int nt = 0; nt < 3; ++nt) {
        int c0 = nt * 8 + 2 * tq;
        hs[r0][c0]     = tanh_fast(acc[nt + 3][0]) * sigmoid_fast(acc[nt][0]);
        hs[r0][c0 + 1] = tanh_fast(acc[nt + 3][1]) * sigmoid_fast(acc[nt][1]);
        hs[r1][c0]     = tanh_fast(acc[nt + 3][2]) * sigmoid_fast(acc[nt][2]);
        hs[r1][c0 + 1] = tanh_fast(acc[nt + 3][3]) * sigmoid_fast(acc[nt][3]);
    }
    __syncthreads();

    const int oid = tid & 31;
    const int o = (oid < 24) ? oid : 0;
    const int tg = tid >> 5;
#pragma unroll
    for (int rr = 0; rr < 16; ++rr) {
        int r = tg * 16 + rr;
        float s = ssb[o];
#pragma unroll
        for (int c = 0; c < 24; ++c) s += hs[r][c] * sws[c * 24 + o];
        int t = t0 + r;
        if (oid < 24 && t < L0)
            g_bufA[((size_t)b * LMAX + t) * 24 + o] = s;
    }
}

// ---------------------------------------------------------------------------
// K3: dilated gated layer via tensor cores. Shift-only A-tile indexing,
// tanh.approx + fast sigmoid.
// ---------------------------------------------------------------------------
__global__ __launch_bounds__(256) void k_dilated_mma(const float* __restrict__ gW,
                                                     const float* __restrict__ gb,
                                                     const float* __restrict__ fW,
                                                     const float* __restrict__ fb,
                                                     const float* __restrict__ sW,
                                                     const float* __restrict__ sb,
                                                     int d, int Lout, int dir) {
    const float* in   = dir ? g_bufB : g_bufA;
    float*       outp = dir ? g_bufA : g_bufB;
    const int b  = blockIdx.y;
    const int t0 = blockIdx.x * 128;
    const int tid = threadIdx.x;
    const int warp = tid >> 5, lane = tid & 31;
    const int m_off = warp * 16;
    const int g  = lane >> 2;
    const int tq = lane & 3;

    __shared__ float As[128][52];
    __shared__ float Bs1[48][56];
    __shared__ float Hs[128][28];
    __shared__ float Bs2[24][40];

    const int Lin = Lout + d;
    // A tile: one (row, tap) task per thread: r = tid>>1, tap = tid&1.
    {
        const int r    = tid >> 1;
        const int tap  = tid & 1;
        const int row  = t0 + r + (tap ? d : 0);
        const bool ok  = row < Lin;
        const float* src = in + ((size_t)b * LMAX + row) * 24;
        const int cbase = tap * 24;
#pragma unroll
        for (int c4 = 0; c4 < 6; ++c4) {
            float4 v = ok ? *reinterpret_cast<const float4*>(src + c4 * 4)
                          : make_float4(0.f, 0.f, 0.f, 0.f);
            As[r][cbase + c4 * 4 + 0] = to_tf32(v.x);
            As[r][cbase + c4 * 4 + 1] = to_tf32(v.y);
            As[r][cbase + c4 * 4 + 2] = to_tf32(v.z);
            As[r][cbase + c4 * 4 + 3] = to_tf32(v.w);
        }
    }
    // B1: 48x48 (k = tap*24+ci ; n<24 gate, n>=24 filter)
    for (int idx = tid; idx < 48 * 48; idx += 256) {
        int k = idx / 48, n = idx % 48;
        int tap = k / 24, ci = k % 24;
        float w = (n < 24) ? gW[tap * 576 + ci * 24 + n]
                           : fW[tap * 576 + ci * 24 + (n - 24)];
        Bs1[k][n] = to_tf32(w);
    }
    // B2: scale weights 24x24
    for (int idx = tid; idx < 576; idx += 256)
        Bs2[idx / 24][idx % 24] = to_tf32(sW[idx]);
    __syncthreads();

    // MMA1
    float acc[6][4];
#pragma unroll
    for (int nt = 0; nt < 6; ++nt) {
        int c0 = (nt < 3) ? (nt * 8 + 2 * tq) : ((nt - 3) * 8 + 2 * tq);
        float b0 = (nt < 3) ? gb[c0] : fb[c0];
        float b1 = (nt < 3) ? gb[c0 + 1] : fb[c0 + 1];
        acc[nt][0] = b0; acc[nt][1] = b1; acc[nt][2] = b0; acc[nt][3] = b1;
    }
#pragma unroll
    for (int kk = 0; kk < 48; kk += 8) {
        uint32_t af[4];
        af[0] = __float_as_uint(As[m_off + g][kk + tq]);
        af[1] = __float_as_uint(As[m_off + g + 8][kk + tq]);
        af[2] = __float_as_uint(As[m_off + g][kk + tq + 4]);
        af[3] = __float_as_uint(As[m_off + g + 8][kk + tq + 4]);
        uint32_t bf[6][2];
#pragma unroll
        for (int nt = 0; nt < 6; ++nt) {
            int c0 = nt * 8 + g;
            bf[nt][0] = __float_as_uint(Bs1[kk + tq][c0]);
            bf[nt][1] = __float_as_uint(Bs1[kk + tq + 4][c0]);
        }
#pragma unroll
        for (int nt = 0; nt < 6; ++nt)
            mma_tf32(acc[nt], af, bf[nt]);
    }

    // Nonlinearity -> Hs
    const int r0 = m_off + g, r1 = r0 + 8;
#pragma unroll
    for (int nt = 0; nt < 3; ++nt) {
        int c0 = nt * 8 + 2 * tq;
        Hs[r0][c0]     = to_tf32(tanh_fast(acc[nt + 3][0]) * sigmoid_fast(acc[nt][0]));
        Hs[r0][c0 + 1] = to_tf32(tanh_fast(acc[nt + 3][1]) * sigmoid_fast(acc[nt][1]));
        Hs[r1][c0]     = to_tf32(tanh_fast(acc[nt + 3][2]) * sigmoid_fast(acc[nt][2]));
        Hs[r1][c0 + 1] = to_tf32(tanh_fast(acc[nt + 3][3]) * sigmoid_fast(acc[nt][3]));
    }
    __syncthreads();

    // MMA2: Hs[128x24] x Bs2[24x24]
    float acc2[3][4];
#pragma unroll
    for (int nt = 0; nt < 3; ++nt) {
        int c0 = nt * 8 + 2 * tq;
        float b0 = sb[c0], b1 = sb[c0 + 1];
        acc2[nt][0] = b0; acc2[nt][1] = b1; acc2[nt][2] = b0; acc2[nt][3] = b1;
    }
#pragma unroll
    for (int kk = 0; kk < 24; kk += 8) {
        uint32_t af[4];
        af[0] = __float_as_uint(Hs[r0][kk + tq]);
        af[1] = __float_as_uint(Hs[r1][kk + tq]);
        af[2] = __float_as_uint(Hs[r0][kk + tq + 4]);
        af[3] = __float_as_uint(Hs[r1][kk + tq + 4]);
        uint32_t bf[3][2];
#pragma unroll
        for (int nt = 0; nt < 3; ++nt) {
            int c0 = nt * 8 + g;
            bf[nt][0] = __float_as_uint(Bs2[kk + tq][c0]);
            bf[nt][1] = __float_as_uint(Bs2[kk + tq + 4][c0]);
        }
#pragma unroll
        for (int nt = 0; nt < 3; ++nt)
            mma_tf32(acc2[nt], af, bf[nt]);
    }

    // Store
#pragma unroll
    for (int nt = 0; nt < 3; ++nt) {
        int col = nt * 8 + 2 * tq;
        int ta = t0 + r0;
        if (ta < Lout) {
            *reinterpret_cast<float2*>(outp + ((size_t)b * LMAX + ta) * 24 + col) =
                make_float2(acc2[nt][0], acc2[nt][1]);
        }
        int tb = t0 + r1;
        if (tb < Lout) {
            *reinterpret_cast<float2*>(outp + ((size_t)b * LMAX + tb) * 24 + col) =
                make_float2(acc2[nt][2], acc2[nt][3]);
        }
    }
}

// ---------------------------------------------------------------------------
// K4a: act128 = relu(resW conv of (prev[t+256] + out[t])). bf16 output.
// ---------------------------------------------------------------------------
__global__ __launch_bounds__(256) void k_resrelu(const float* __restrict__ resW,
                                                 const float* __restrict__ resb) {
    const int b  = blockIdx.y;
    const int t0 = blockIdx.x * 64;
    const int tid = threadIdx.x;
    const int og = tid & 31;
    const int tg = tid >> 5;

    __shared__ float s_in[64][25];
    for (int idx = tid; idx < 64 * 24; idx += 256) {
        int r = idx / 24, c = idx % 24;
        size_t prow = (size_t)b * LMAX + 256 + t0 + r;
        size_t orow = (size_t)b * LMAX + t0 + r;
        s_in[r][c] = g_bufA[prow * 24 + c] + g_bufB[orow * 24 + c];
    }
    __syncthreads();

    const float4 bb = reinterpret_cast<const float4*>(resb)[og];
    float acc[8][4];
#pragma unroll
    for (int rr = 0; rr < 8; ++rr) {
        acc[rr][0] = bb.x; acc[rr][1] = bb.y; acc[rr][2] = bb.z; acc[rr][3] = bb.w;
    }
#pragma unroll 4
    for (int c = 0; c < 24; ++c) {
        float4 w = reinterpret_cast<const float4*>(resW)[c * 32 + og];
#pragma unroll
        for (int rr = 0; rr < 8; ++rr) {
            float xin = s_in[tg * 8 + rr][c];
            acc[rr][0] += xin * w.x; acc[rr][1] += xin * w.y;
            acc[rr][2] += xin * w.z; acc[rr][3] += xin * w.w;
        }
    }
#pragma unroll
    for (int rr = 0; rr < 8; ++rr) {
        int row = t0 + tg * 8 + rr;
        __nv_bfloat16* dst = g_act128 + ((size_t)b * TOUT + row) * 128 + og * 4;
        *reinterpret_cast<__nv_bfloat162*>(dst) =
            __float22bfloat162_rn(make_float2(fmaxf(acc[rr][0], 0.f), fmaxf(acc[rr][1], 0.f)));
        *reinterpret_cast<__nv_bfloat162*>(dst + 2) =
            __float22bfloat162_rn(make_float2(fmaxf(acc[rr][2], 0.f), fmaxf(acc[rr][3], 0.f)));
    }
}

// ---------------------------------------------------------------------------
// K4b: act256 = relu(act128 @ f1W + f1b). tf32 GEMM on bf16 A, K=128.
// ---------------------------------------------------------------------------
__global__ __launch_bounds__(256) void k_gemm_relu(const float* __restrict__ f1W,
                                                   const float* __restrict__ f1b) {
    const int t0 = blockIdx.x * 128;
    const int o0 = blockIdx.y * 128;
    const int b  = blockIdx.z;
    const int tid  = threadIdx.x;
    const int warp = tid >> 5, lane = tid & 31;
    const int m_off = (warp >> 2) * 64;
    const int n_off = (warp & 3) * 32;
    const int g  = lane >> 2;
    const int tq = lane & 3;

    __shared__ float As[128][36];
    __shared__ float Bs[32][136];

    float acc[4][4][4];
#pragma unroll
    for (int mt = 0; mt < 4; ++mt)
#pragma unroll
        for (int nt = 0; nt < 4; ++nt)
#pragma unroll
            for (int q = 0; q < 4; ++q) acc[mt][nt][q] = 0.0f;

    for (int k0 = 0; k0 < 128; k0 += 32) {
        __syncthreads();
#pragma unroll
        for (int q = 0; q < 2; ++q) {
            int idx = tid + q * 256;
            int r = idx >> 2, u4 = idx & 3;
            uint4 u = *reinterpret_cast<const uint4*>(
                g_act128 + ((size_t)b * TOUT + t0 + r) * 128 + k0 + u4 * 8);
            bf16x8_to_f32(u, &As[r][u4 * 8]);
        }
#pragma unroll
        for (int q = 0; q < 4; ++q) {
            int idx = tid + q * 256;
            int r = idx >> 5, c4 = idx & 31;
            float4 v = *reinterpret_cast<const float4*>(
                f1W + (size_t)(k0 + r) * 256 + o0 + c4 * 4);
            Bs[r][c4 * 4 + 0] = to_tf32(v.x);
            Bs[r][c4 * 4 + 1] = to_tf32(v.y);
            Bs[r][c4 * 4 + 2] = to_tf32(v.z);
            Bs[r][c4 * 4 + 3] = to_tf32(v.w);
        }
        __syncthreads();
#pragma unroll
        for (int kk = 0; kk < 32; kk += 8) {
            uint32_t af[4][4];
#pragma unroll
            for (int mt = 0; mt < 4; ++mt) {
                int r0 = m_off + mt * 16 + g;
                af[mt][0] = __float_as_uint(As[r0][kk + tq]);
                af[mt][1] = __float_as_uint(As[r0 + 8][kk + tq]);
                af[mt][2] = __float_as_uint(As[r0][kk + tq + 4]);
                af[mt][3] = __float_as_uint(As[r0 + 8][kk + tq + 4]);
            }
            uint32_t bf[4][2];
#pragma unroll
            for (int nt = 0; nt < 4; ++nt) {
                int c0 = n_off + nt * 8 + g;
                bf[nt][0] = __float_as_uint(Bs[kk + tq][c0]);
                bf[nt][1] = __float_as_uint(Bs[kk + tq + 4][c0]);
            }
#pragma unroll
            for (int mt = 0; mt < 4; ++mt)
#pragma unroll
                for (int nt = 0; nt < 4; ++nt)
                    mma_tf32(acc[mt][nt], af[mt], bf[nt]);
        }
    }
#pragma unroll
    for (int nt = 0; nt < 4; ++nt) {
        const int col = o0 + n_off + nt * 8 + 2 * tq;
        const float2 bias = *reinterpret_cast<const float2*>(f1b + col);
#pragma unroll
        for (int mt = 0; mt < 4; ++mt) {
            int row = t0 + m_off + mt * 16 + g;
            *reinterpret_cast<__nv_bfloat162*>(g_act256 + ((size_t)b * TOUT + row) * 256 + col) =
                __float22bfloat162_rn(make_float2(fmaxf(acc[mt][nt][0] + bias.x, 0.f),
                                                  fmaxf(acc[mt][nt][1] + bias.y, 0.f)));
            *reinterpret_cast<__nv_bfloat162*>(g_act256 + ((size_t)b * TOUT + row + 8) * 256 + col) =
                __float22bfloat162_rn(make_float2(fmaxf(acc[mt][nt][2] + bias.x, 0.f),
                                                  fmaxf(acc[mt][nt][3] + bias.y, 0.f)));
        }
    }
}

// ---------------------------------------------------------------------------
// K4c: y = softmax(act256 @ f2W + f2b). tf32 GEMM on bf16 A, M tile 64,
// full N=256, BK=16. Fused row softmax.
// ---------------------------------------------------------------------------
__global__ __launch_bounds__(256) void k_gemm_softmax(const float* __restrict__ f2W,
                                                      const float* __restrict__ f2b,
                                                      float* __restrict__ y) {
    const int t0 = blockIdx.x * 64;
    const int b  = blockIdx.y;
    const int tid  = threadIdx.x;
    const int warp = tid >> 5, lane = tid & 31;
    const int mw = warp >> 2;
    const int nw = warp & 3;
    const int m_off = mw * 32;
    const int n_off = nw * 64;
    const int g  = lane >> 2;
    const int tq = lane & 3;

    __shared__ float As[64][20];
    __shared__ float Bs[16][264];
    __shared__ float red1[64][4];
    __shared__ float red2[64][4];

    float acc[2][8][4];
#pragma unroll
    for (int mt = 0; mt < 2; ++mt)
#pragma unroll
        for (int nt = 0; nt < 8; ++nt)
#pragma unroll
            for (int q = 0; q < 4; ++q) acc[mt][nt][q] = 0.0f;

    for (int k0 = 0; k0 < 256; k0 += 16) {
        __syncthreads();
        if (tid < 128) {
            int r = tid >> 1, u4 = tid & 1;
            uint4 u = *reinterpret_cast<const uint4*>(
                g_act256 + ((size_t)b * TOUT + t0 + r) * 256 + k0 + u4 * 8);
            bf16x8_to_f32(u, &As[r][u4 * 8]);
        }
#pragma unroll
        for (int q = 0; q < 4; ++q) {
            int idx = tid + q * 256;
            int r = idx >> 6, c4 = idx & 63;
            float4 v = *reinterpret_cast<const float4*>(
                f2W + (size_t)(k0 + r) * 256 + c4 * 4);
            Bs[r][c4 * 4 + 0] = to_tf32(v.x);
            Bs[r][c4 * 4 + 1] = to_tf32(v.y);
            Bs[r][c4 * 4 + 2] = to_tf32(v.z);
            Bs[r][c4 * 4 + 3] = to_tf32(v.w);
        }
        __syncthreads();
#pragma unroll
        for (int kk = 0; kk < 16; kk += 8) {
            uint32_t af[2][4];
#pragma unroll
            for (int mt = 0; mt < 2; ++mt) {
                int r0 = m_off + mt * 16 + g;
                af[mt][0] = __float_as_uint(As[r0][kk + tq]);
                af[mt][1] = __float_as_uint(As[r0 + 8][kk + tq]);
                af[mt][2] = __float_as_uint(As[r0][kk + tq + 4]);
                af[mt][3] = __float_as_uint(As[r0 + 8][kk + tq + 4]);
            }
            uint32_t bf[8][2];
#pragma unroll
            for (int nt = 0; nt < 8; ++nt) {
                int c0 = n_off + nt * 8 + g;
                bf[nt][0] = __float_as_uint(Bs[kk + tq][c0]);
                bf[nt][1] = __float_as_uint(Bs[kk + tq + 4][c0]);
            }
#pragma unroll
            for (int mt = 0; mt < 2; ++mt)
#pragma unroll
                for (int nt = 0; nt < 8; ++nt)
                    mma_tf32(acc[mt][nt], af[mt], bf[nt]);
        }
    }

#pragma unroll
    for (int nt = 0; nt < 8; ++nt) {
        const int col = n_off + nt * 8 + 2 * tq;
        const float2 bias = *reinterpret_cast<const float2*>(f2b + col);
#pragma unroll
        for (int mt = 0; mt < 2; ++mt) {
            acc[mt][nt][0] += bias.x; acc[mt][nt][1] += bias.y;
            acc[mt][nt][2] += bias.x; acc[mt][nt][3] += bias.y;
        }
    }

    float rmax[2][2];
#pragma unroll
    for (int mt = 0; mt < 2; ++mt)
#pragma unroll
        for (int rr = 0; rr < 2; ++rr) {
            float m = -1e30f;
#pragma unroll
            for (int nt = 0; nt < 8; ++nt) {
                m = fmaxf(m, acc[mt][nt][rr * 2 + 0]);
                m = fmaxf(m, acc[mt][nt][rr * 2 + 1]);
            }
            m = fmaxf(m, __shfl_xor_sync(0xffffffffu, m, 1));
            m = fmaxf(m, __shfl_xor_sync(0xffffffffu, m, 2));
            rmax[mt][rr] = m;
            if (tq == 0) red1[m_off + mt * 16 + rr * 8 + g][nw] = m;
        }
    __syncthreads();
#pragma unroll
    for (int mt = 0; mt < 2; ++mt)
#pragma unroll
        for (int rr = 0; rr < 2; ++rr) {
            int r = m_off + mt * 16 + rr * 8 + g;
            rmax[mt][rr] = fmaxf(fmaxf(red1[r][0], red1[r][1]),
                                 fmaxf(red1[r][2], red1[r][3]));
        }

    float rsum[2][2];
#pragma unroll
    for (int mt = 0; mt < 2; ++mt)
#pragma unroll
        for (int rr = 0; rr < 2; ++rr) {
            float s = 0.f;
#pragma unroll
            for (int nt = 0; nt < 8; ++nt) {
                float e0 = __expf(acc[mt][nt][rr * 2 + 0] - rmax[mt][rr]);
                float e1 = __expf(acc[mt][nt][rr * 2 + 1] - rmax[mt][rr]);
                acc[mt][nt][rr * 2 + 0] = e0;
                acc[mt][nt][rr * 2 + 1] = e1;
                s += e0 + e1;
            }
            s += __shfl_xor_sync(0xffffffffu, s, 1);
            s += __shfl_xor_sync(0xffffffffu, s, 2);
            rsum[mt][rr] = s;
            if (tq == 0) red2[m_off + mt * 16 + rr * 8 + g][nw] = s;
        }
    __syncthreads();
#pragma unroll
    for (int mt = 0; mt < 2; ++mt)
#pragma unroll
        for (int rr = 0; rr < 2; ++rr) {
            int r = m_off + mt * 16 + rr * 8 + g;
            rsum[mt][rr] = __fdividef(1.0f, red2[r][0] + red2[r][1] + red2[r][2] + red2[r][3]);
        }

#pragma unroll
    for (int nt = 0; nt < 8; ++nt) {
        const int col = n_off + nt * 8 + 2 * tq;
#pragma unroll
        for (int mt = 0; mt < 2; ++mt) {
            int row = t0 + m_off + mt * 16 + g;
            float2 v0 = make_float2(acc[mt][nt][0] * rsum[mt][0],
                                    acc[mt][nt][1] * rsum[mt][0]);
            float2 v1 = make_float2(acc[mt][nt][2] * rsum[mt][1],
                                    acc[mt][nt][3] * rsum[mt][1]);
            *reinterpret_cast<float2*>(y + ((size_t)b * TOUT + row) * 256 + col) = v0;
            *reinterpret_cast<float2*>(y + ((size_t)b * TOUT + row + 8) * 256 + col) = v1;
        }
    }
}

// ---------------------------------------------------------------------------
extern "C" void kernel_launch(void* const* d_in, const int* in_sizes, int n_in,
                              void* d_out, int out_size) {
    const float* x     = (const float*)d_in[0];
    const float* cW    = (const float*)d_in[1];
    const float* cb    = (const float*)d_in[2];
    const float* gW0   = (const float*)d_in[3];
    const float* gb0   = (const float*)d_in[4];
    const float* fW0   = (const float*)d_in[5];
    const float* fb0   = (const float*)d_in[6];
    const float* sW0   = (const float*)d_in[7];
    const float* sb0   = (const float*)d_in[8];
    const float* gateW = (const float*)d_in[9];
    const float* gateB = (const float*)d_in[10];
    const float* filtW = (const float*)d_in[11];
    const float* filtB = (const float*)d_in[12];
    const float* scW   = (const float*)d_in[13];
    const float* scB   = (const float*)d_in[14];
    const float* resW  = (const float*)d_in[15];
    const float* resB  = (const float*)d_in[16];
    const float* f1W   = (const float*)d_in[17];
    const float* f1b   = (const float*)d_in[18];
    const float* f2W   = (const float*)d_in[19];
    const float* f2b   = (const float*)d_in[20];
    float* out = (float*)d_out;

    k_causal_mma<<<dim3(128, 2, BATCH), 256>>>(x, cW, cb);
    k_gated0_mma<<<dim3(128, BATCH), 256>>>(gW0, gb0, fW0, fb0, sW0, sb0);

    int L = L0;
    for (int i = 0; i < 9; ++i) {
        int d = 2 << i;          // 2,4,...,512
        int Lout = L - d;
        int nb = (Lout + 127) / 128;
        // Only the LAST residual conv contributes to the output (acc is
        // overwritten each iteration in the reference), so res convs 0..7 are skipped.
        k_dilated_mma<<<dim3(nb, BATCH), 256>>>(gateW + i * 1152, gateB + i * 24,
                                                filtW + i * 1152, filtB + i * 24,
                                                scW + i * 576, scB + i * 24,
                                                d, Lout, i & 1);
        L = Lout;
    }
    // prev (input of layer i=8) lives in g_bufA (len 15872); its output in g_bufB (15360)
    k_resrelu<<<dim3(TOUT / 64, BATCH), 256>>>(resW + 8 * 24 * 128, resB + 8 * 128);
    k_gemm_relu<<<dim3(TOUT / 128, 2, BATCH), 256>>>(f1W, f1b);
    k_gemm_softmax<<<dim3(TOUT / 64, BATCH), 256>>>(f2W, f2b, out);
}

// round 9
// speedup vs baseline: 4.3535x; 1.3556x over previous
#include <cuda_runtime.h>
#include <cuda_bf16.h>
#include <cstdint>
#include <cstddef>

#define BATCH 8
#define TLEN  16384
#define CIN   256
#define T1    16383   // causal conv output length
#define L0    16382   // gated0 output length
#define LMAX  16382   // per-batch row stride for 24-ch buffers
#define TOUT  15360

// Scratch (static device globals: allocation-free per harness rules)
__device__ __nv_bfloat16 g_xb[(size_t)BATCH * TLEN * CIN];      // 67 MB (x in bf16)
__device__ __nv_bfloat16 g_h1[(size_t)BATCH * T1 * CIN];        // 67 MB
__device__ float         g_bufA[(size_t)BATCH * LMAX * 24];     // 12.6 MB
__device__ float         g_bufB[(size_t)BATCH * LMAX * 24];     // 12.6 MB
__device__ __nv_bfloat16 g_act128[(size_t)BATCH * TOUT * 128];  // 31 MB
__device__ __nv_bfloat16 g_act256[(size_t)BATCH * TOUT * 256];  // 63 MB
// Pre-converted, transposed bf16 weights: [n][k] layout for mma B-frags
__device__ __nv_bfloat16 g_cWt[256 * 512];
__device__ __nv_bfloat16 g_gf0t[48 * 512];
__device__ __nv_bfloat16 g_f1t[256 * 128];
__device__ __nv_bfloat16 g_f2t[256 * 256];

__device__ __forceinline__ float to_tf32(float x) {
    asm("cvt.rna.tf32.f32 %0, %0;" : "+f"(x));
    return x;
}
__device__ __forceinline__ float tanh_fast(float x) {
    float y;
    asm("tanh.approx.f32 %0, %1;" : "=f"(y) : "f"(x));
    return y;
}
__device__ __forceinline__ float sigmoid_fast(float x) {
    return __fdividef(1.0f, 1.0f + __expf(-x));
}

__device__ __forceinline__ void mma_tf32(float c[4], const uint32_t a[4], const uint32_t b[2]) {
    asm volatile(
        "mma.sync.aligned.m16n8k8.row.col.f32.tf32.tf32.f32 "
        "{%0,%1,%2,%3}, {%4,%5,%6,%7}, {%8,%9}, {%0,%1,%2,%3};"
        : "+f"(c[0]), "+f"(c[1]), "+f"(c[2]), "+f"(c[3])
        : "r"(a[0]), "r"(a[1]), "r"(a[2]), "r"(a[3]), "r"(b[0]), "r"(b[1]));
}
__device__ __forceinline__ void mma_bf16(float c[4], const uint32_t a[4], const uint32_t b[2]) {
    asm volatile(
        "mma.sync.aligned.m16n8k16.row.col.f32.bf16.bf16.f32 "
        "{%0,%1,%2,%3}, {%4,%5,%6,%7}, {%8,%9}, {%0,%1,%2,%3};"
        : "+f"(c[0]), "+f"(c[1]), "+f"(c[2]), "+f"(c[3])
        : "r"(a[0]), "r"(a[1]), "r"(a[2]), "r"(a[3]), "r"(b[0]), "r"(b[1]));
}

__device__ __forceinline__ uint32_t ld_bf2(const __nv_bfloat16* p) {
    return *reinterpret_cast<const uint32_t*>(p);
}

__device__ __forceinline__ void cp16(uint32_t smem_dst, const void* gsrc) {
    asm volatile("cp.async.ca.shared.global [%0], [%1], 16;" :: "r"(smem_dst), "l"(gsrc));
}
__device__ __forceinline__ void cp_commit() {
    asm volatile("cp.async.commit_group;" ::: "memory");
}
__device__ __forceinline__ void cp_wait_all() {
    asm volatile("cp.async.wait_group 0;" ::: "memory");
}

// ---------------------------------------------------------------------------
// Prep: x -> bf16
// ---------------------------------------------------------------------------
__global__ void k_prep_x(const float* __restrict__ x) {
    const size_t n4 = (size_t)BATCH * TLEN * CIN / 4;
    for (size_t i = blockIdx.x * blockDim.x + threadIdx.x; i < n4;
         i += (size_t)gridDim.x * blockDim.x) {
        float4 v = reinterpret_cast<const float4*>(x)[i];
        __nv_bfloat162 lo = __float22bfloat162_rn(make_float2(v.x, v.y));
        __nv_bfloat162 hi = __float22bfloat162_rn(make_float2(v.z, v.w));
        uint2 u;
        u.x = *reinterpret_cast<uint32_t*>(&lo);
        u.y = *reinterpret_cast<uint32_t*>(&hi);
        reinterpret_cast<uint2*>(g_xb)[i] = u;
    }
}

// ---------------------------------------------------------------------------
// Prep: weights -> bf16, transposed [n][k]
// ---------------------------------------------------------------------------
__global__ void k_prep_w(const float* __restrict__ cW,
                         const float* __restrict__ gW0,
                         const float* __restrict__ fW0,
                         const float* __restrict__ f1W,
                         const float* __restrict__ f2W) {
    const int stride = gridDim.x * blockDim.x;
    const int tid = blockIdx.x * blockDim.x + threadIdx.x;
    for (int idx = tid; idx < 256 * 512; idx += stride) {
        int o = idx >> 9, r = idx & 511;
        int tap = r >> 8, i = r & 255;
        g_cWt[idx] = __float2bfloat16(cW[tap * 65536 + i * 256 + o]);
    }
    for (int idx = tid; idx < 48 * 512; idx += stride) {
        int n = idx >> 9, r = idx & 511;
        int tap = r >> 8, i = r & 255;
        float v = (n < 24) ? gW0[tap * 6144 + i * 24 + n]
                           : fW0[tap * 6144 + i * 24 + (n - 24)];
        g_gf0t[idx] = __float2bfloat16(v);
    }
    for (int idx = tid; idx < 256 * 128; idx += stride) {
        int o = idx >> 7, k = idx & 127;
        g_f1t[idx] = __float2bfloat16(f1W[k * 256 + o]);
    }
    for (int idx = tid; idx < 256 * 256; idx += stride) {
        int o = idx >> 8, k = idx & 255;
        g_f2t[idx] = __float2bfloat16(f2W[k * 256 + o]);
    }
}

// ---------------------------------------------------------------------------
// K1: causal conv as bf16 GEMM (m16n8k16), 2-stage cp.async pipeline.
// out[t,o] = cb[o] + sum_{r<512} A[t,r]*W[r,o], A[t,r] = xb[t+(r>>8), r&255].
// 128x128 tile, BK=32, 8 warps (2x4), 64x32 warp tile.
// ---------------------------------------------------------------------------
__global__ __launch_bounds__(256) void k_causal_mma(const float* __restrict__ cb) {
    const int t0 = blockIdx.x * 128;
    const int o0 = blockIdx.y * 128;
    const int b  = blockIdx.z;
    const int tid  = threadIdx.x;
    const int warp = tid >> 5, lane = tid & 31;
    const int m_off = (warp >> 2) * 64;
    const int n_off = (warp & 3) * 32;
    const int g  = lane >> 2;
    const int tq = lane & 3;

    __shared__ __align__(16) __nv_bfloat16 As[2][128][40];  // pad 8 -> 80B rows
    __shared__ __align__(16) __nv_bfloat16 Bs[2][128][40];  // [n][k]
    const uint32_t as_base = (uint32_t)__cvta_generic_to_shared(&As[0][0][0]);
    const uint32_t bs_base = (uint32_t)__cvta_generic_to_shared(&Bs[0][0][0]);

    float acc[4][4][4];
#pragma unroll
    for (int mt = 0; mt < 4; ++mt)
#pragma unroll
        for (int nt = 0; nt < 4; ++nt)
#pragma unroll
            for (int q = 0; q < 4; ++q) acc[mt][nt][q] = 0.0f;

#define CAUSAL_LOAD(chunk, s) do {                                              \
    int k0 = (chunk) * 32; int tap = k0 >> 8; int ch = k0 & 255;                \
    _Pragma("unroll")                                                            \
    for (int q = 0; q < 2; ++q) {                                                \
        int idx = tid + q * 256;                                                 \
        int r = idx >> 2, c8 = idx & 3;                                          \
        int row = t0 + r + tap; if (row > TLEN - 1) row = TLEN - 1;              \
        cp16(as_base + (uint32_t)((((s) * 128 + r) * 40 + c8 * 8) * 2),          \
             g_xb + ((size_t)b * TLEN + row) * CIN + ch + c8 * 8);               \
    }                                                                            \
    _Pragma("unroll")                                                            \
    for (int q = 0; q < 2; ++q) {                                                \
        int idx = tid + q * 256;                                                 \
        int r = idx >> 2, c8 = idx & 3;                                          \
        cp16(bs_base + (uint32_t)((((s) * 128 + r) * 40 + c8 * 8) * 2),          \
             g_cWt + (size_t)(o0 + r) * 512 + k0 + c8 * 8);                      \
    }                                                                            \
} while (0)

    CAUSAL_LOAD(0, 0);
    cp_commit();

    for (int c = 0; c < 16; ++c) {
        const int s = c & 1;
        cp_wait_all();
        __syncthreads();
        if (c < 15) { CAUSAL_LOAD(c + 1, s ^ 1); cp_commit(); }
#pragma unroll
        for (int kk = 0; kk < 32; kk += 16) {
            uint32_t af[4][4];
#pragma unroll
            for (int mt = 0; mt < 4; ++mt) {
                int r0 = m_off + mt * 16 + g;
                af[mt][0] = ld_bf2(&As[s][r0][kk + 2 * tq]);
                af[mt][1] = ld_bf2(&As[s][r0 + 8][kk + 2 * tq]);
                af[mt][2] = ld_bf2(&As[s][r0][kk + 8 + 2 * tq]);
                af[mt][3] = ld_bf2(&As[s][r0 + 8][kk + 8 + 2 * tq]);
            }
            uint32_t bf[4][2];
#pragma unroll
            for (int nt = 0; nt < 4; ++nt) {
                int c0 = n_off + nt * 8 + g;
                bf[nt][0] = ld_bf2(&Bs[s][c0][kk + 2 * tq]);
                bf[nt][1] = ld_bf2(&Bs[s][c0][kk + 8 + 2 * tq]);
            }
#pragma unroll
            for (int mt = 0; mt < 4; ++mt)
#pragma unroll
                for (int nt = 0; nt < 4; ++nt)
                    mma_bf16(acc[mt][nt], af[mt], bf[nt]);
        }
        __syncthreads();
    }
#undef CAUSAL_LOAD

#pragma unroll
    for (int nt = 0; nt < 4; ++nt) {
        const int col = o0 + n_off + nt * 8 + 2 * tq;
        const float2 bias = *reinterpret_cast<const float2*>(cb + col);
#pragma unroll
        for (int mt = 0; mt < 4; ++mt) {
            int row = t0 + m_off + mt * 16 + g;
            if (row < T1) {
                *reinterpret_cast<__nv_bfloat162*>(g_h1 + ((size_t)b * T1 + row) * CIN + col) =
                    __float22bfloat162_rn(make_float2(acc[mt][nt][0] + bias.x,
                                                      acc[mt][nt][1] + bias.y));
            }
            if (row + 8 < T1) {
                *reinterpret_cast<__nv_bfloat162*>(g_h1 + ((size_t)b * T1 + row + 8) * CIN + col) =
                    __float22bfloat162_rn(make_float2(acc[mt][nt][2] + bias.x,
                                                      acc[mt][nt][3] + bias.y));
            }
        }
    }
}

// ---------------------------------------------------------------------------
// K2: gated0 as bf16 GEMM on bf16 h1: K=512, N=48 ([gW|fW], whole B in smem).
// M tile 128, 8 warps in M. Epilogue: gate + 24x24 1x1.
// ---------------------------------------------------------------------------
__global__ __launch_bounds__(256) void k_gated0_mma(const float* __restrict__ gb,
                                                    const float* __restrict__ fb,
                                                    const float* __restrict__ sW,
                                                    const float* __restrict__ sb) {
    const int t0 = blockIdx.x * 128;
    const int b  = blockIdx.y;
    const int tid  = threadIdx.x;
    const int warp = tid >> 5, lane = tid & 31;
    const int m_off = warp * 16;
    const int g  = lane >> 2;
    const int tq = lane & 3;

    __shared__ __align__(16) __nv_bfloat16 sGF[48][520];   // [n][k], pad 8
    __shared__ __align__(16) __nv_bfloat16 As[128][40];
    __shared__ float hs[128][25];
    __shared__ float sws[576];
    __shared__ float ssb[24];

    // full B into smem (48 x 512 bf16)
#pragma unroll
    for (int q = 0; q < 12; ++q) {
        int idx = tid + q * 256;
        int n = idx >> 6, u = idx & 63;
        *reinterpret_cast<uint4*>(&sGF[n][u * 8]) =
            *reinterpret_cast<const uint4*>(g_gf0t + (size_t)n * 512 + u * 8);
    }
    for (int idx = tid; idx < 576; idx += 256) sws[idx] = sW[idx];
    if (tid < 24) ssb[tid] = sb[tid];

    float acc[6][4];
#pragma unroll
    for (int nt = 0; nt < 6; ++nt) {
        int c0 = nt * 8 + 2 * tq;
        float b0 = (nt < 3) ? gb[c0] : fb[c0 - 24];
        float b1 = (nt < 3) ? gb[c0 + 1] : fb[c0 - 23];
        acc[nt][0] = b0; acc[nt][1] = b1; acc[nt][2] = b0; acc[nt][3] = b1;
    }

    for (int k0 = 0; k0 < 512; k0 += 32) {
        const int tap = k0 >> 8;
        const int ch  = k0 & 255;
        __syncthreads();
#pragma unroll
        for (int q = 0; q < 2; ++q) {
            int idx = tid + q * 256;
            int r = idx >> 2, c8 = idx & 3;
            int row = t0 + r + tap;
            if (row > T1 - 1) row = T1 - 1;
            *reinterpret_cast<uint4*>(&As[r][c8 * 8]) =
                *reinterpret_cast<const uint4*>(g_h1 + ((size_t)b * T1 + row) * CIN + ch + c8 * 8);
        }
        __syncthreads();
#pragma unroll
        for (int kk = 0; kk < 32; kk += 16) {
            uint32_t af[4];
            af[0] = ld_bf2(&As[m_off + g][kk + 2 * tq]);
            af[1] = ld_bf2(&As[m_off + g + 8][kk + 2 * tq]);
            af[2] = ld_bf2(&As[m_off + g][kk + 8 + 2 * tq]);
            af[3] = ld_bf2(&As[m_off + g + 8][kk + 8 + 2 * tq]);
            uint32_t bf[6][2];
#pragma unroll
            for (int nt = 0; nt < 6; ++nt) {
                int c0 = nt * 8 + g;
                bf[nt][0] = ld_bf2(&sGF[c0][k0 + kk + 2 * tq]);
                bf[nt][1] = ld_bf2(&sGF[c0][k0 + kk + 8 + 2 * tq]);
            }
#pragma unroll
            for (int nt = 0; nt < 6; ++nt)
                mma_bf16(acc[nt], af, bf[nt]);
        }
    }

    const int r0 = m_off + g, r1 = m_off + g + 8;
#pragma unroll
    for (int nt = 0; nt < 3; ++nt) {
        int c0 = nt * 8 + 2 * tq;
        hs[r0][c0]     = tanh_fast(acc[nt + 3][0]) * sigmoid_fast(acc[nt][0]);
        hs[r0][c0 + 1] = tanh_fast(acc[nt + 3][1]) * sigmoid_fast(acc[nt][1]);
        hs[r1][c0]     = tanh_fast(acc[nt + 3][2]) * sigmoid_fast(acc[nt][2]);
        hs[r1][c0 + 1] = tanh_fast(acc[nt + 3][3]) * sigmoid_fast(acc[nt][3]);
    }
    __syncthreads();

    const int oid = tid & 31;
    const int o = (oid < 24) ? oid : 0;
    const int tg = tid >> 5;
#pragma unroll
    for (int rr = 0; rr < 16; ++rr) {
        int r = tg * 16 + rr;
        float s = ssb[o];
#pragma unroll
        for (int c = 0; c < 24; ++c) s += hs[r][c] * sws[c * 24 + o];
        int t = t0 + r;
        if (oid < 24 && t < L0)
            g_bufA[((size_t)b * LMAX + t) * 24 + o] = s;
    }
}

// ---------------------------------------------------------------------------
// K3: dilated gated layer via tensor cores (tf32). 512 threads, 256 rows/block.
// ---------------------------------------------------------------------------
__global__ __launch_bounds__(512) void k_dilated_mma(const float* __restrict__ gW,
                                                     const float* __restrict__ gb,
                                                     const float* __restrict__ fW,
                                                     const float* __restrict__ fb,
                                                     const float* __restrict__ sW,
                                                     const float* __restrict__ sb,
                                                     int d, int Lout, int dir) {
    const float* in   = dir ? g_bufB : g_bufA;
    float*       outp = dir ? g_bufA : g_bufB;
    const int b  = blockIdx.y;
    const int t0 = blockIdx.x * 256;
    const int tid = threadIdx.x;
    const int warp = tid >> 5, lane = tid & 31;
    const int m_off = warp * 16;    // 16 warps x 16 rows = 256 rows
    const int g  = lane >> 2;
    const int tq = lane & 3;

    __shared__ float As[256][52];
    __shared__ float Bs1[48][56];
    __shared__ float Hs[256][28];
    __shared__ float Bs2[24][40];

    const int Lin = Lout + d;
    // A tile: one (row, tap) task per thread: r = tid>>1, tap = tid&1.
    {
        const int r    = tid >> 1;
        const int tap  = tid & 1;
        const int row  = t0 + r + (tap ? d : 0);
        const bool ok  = row < Lin;
        const float* src = in + ((size_t)b * LMAX + row) * 24;
        const int cbase = tap * 24;
#pragma unroll
        for (int c4 = 0; c4 < 6; ++c4) {
            float4 v = ok ? *reinterpret_cast<const float4*>(src + c4 * 4)
                          : make_float4(0.f, 0.f, 0.f, 0.f);
            As[r][cbase + c4 * 4 + 0] = to_tf32(v.x);
            As[r][cbase + c4 * 4 + 1] = to_tf32(v.y);
            As[r][cbase + c4 * 4 + 2] = to_tf32(v.z);
            As[r][cbase + c4 * 4 + 3] = to_tf32(v.w);
        }
    }
    for (int idx = tid; idx < 48 * 48; idx += 512) {
        int k = idx / 48, n = idx % 48;
        int tap = k / 24, ci = k % 24;
        float w = (n < 24) ? gW[tap * 576 + ci * 24 + n]
                           : fW[tap * 576 + ci * 24 + (n - 24)];
        Bs1[k][n] = to_tf32(w);
    }
    for (int idx = tid; idx < 576; idx += 512)
        Bs2[idx / 24][idx % 24] = to_tf32(sW[idx]);
    __syncthreads();

    // MMA1: A[256x48] x B1[48x48]
    float acc[6][4];
#pragma unroll
    for (int nt = 0; nt < 6; ++nt) {
        int c0 = (nt < 3) ? (nt * 8 + 2 * tq) : ((nt - 3) * 8 + 2 * tq);
        float b0 = (nt < 3) ? gb[c0] : fb[c0];
        float b1 = (nt < 3) ? gb[c0 + 1] : fb[c0 + 1];
        acc[nt][0] = b0; acc[nt][1] = b1; acc[nt][2] = b0; acc[nt][3] = b1;
    }
#pragma unroll
    for (int kk = 0; kk < 48; kk += 8) {
        uint32_t af[4];
        af[0] = __float_as_uint(As[m_off + g][kk + tq]);
        af[1] = __float_as_uint(As[m_off + g + 8][kk + tq]);
        af[2] = __float_as_uint(As[m_off + g][kk + tq + 4]);
        af[3] = __float_as_uint(As[m_off + g + 8][kk + tq + 4]);
        uint32_t bf[6][2];
#pragma unroll
        for (int nt = 0; nt < 6; ++nt) {
            int c0 = nt * 8 + g;
            bf[nt][0] = __float_as_uint(Bs1[kk + tq][c0]);
            bf[nt][1] = __float_as_uint(Bs1[kk + tq + 4][c0]);
        }
#pragma unroll
        for (int nt = 0; nt < 6; ++nt)
            mma_tf32(acc[nt], af, bf[nt]);
    }

    // Nonlinearity -> Hs
    const int r0 = m_off + g, r1 = r0 + 8;
#pragma unroll
    for (int nt = 0; nt < 3; ++nt) {
        int c0 = nt * 8 + 2 * tq;
        Hs[r0][c0]     = to_tf32(tanh_fast(acc[nt + 3][0]) * sigmoid_fast(acc[nt][0]));
        Hs[r0][c0 + 1] = to_tf32(tanh_fast(acc[nt + 3][1]) * sigmoid_fast(acc[nt][1]));
        Hs[r1][c0]     = to_tf32(tanh_fast(acc[nt + 3][2]) * sigmoid_fast(acc[nt][2]));
        Hs[r1][c0 + 1] = to_tf32(tanh_fast(acc[nt + 3][3]) * sigmoid_fast(acc[nt][3]));
    }
    __syncthreads();

    // MMA2: Hs[256x24] x Bs2[24x24]
    float acc2[3][4];
#pragma unroll
    for (int nt = 0; nt < 3; ++nt) {
        int c0 = nt * 8 + 2 * tq;
        float b0 = sb[c0], b1 = sb[c0 + 1];
        acc2[nt][0] = b0; acc2[nt][1] = b1; acc2[nt][2] = b0; acc2[nt][3] = b1;
    }
#pragma unroll
    for (int kk = 0; kk < 24; kk += 8) {
        uint32_t af[4];
        af[0] = __float_as_uint(Hs[r0][kk + tq]);
        af[1] = __float_as_uint(Hs[r1][kk + tq]);
        af[2] = __float_as_uint(Hs[r0][kk + tq + 4]);
        af[3] = __float_as_uint(Hs[r1][kk + tq + 4]);
        uint32_t bf[3][2];
#pragma unroll
        for (int nt = 0; nt < 3; ++nt) {
            int c0 = nt * 8 + g;
            bf[nt][0] = __float_as_uint(Bs2[kk + tq][c0]);
            bf[nt][1] = __float_as_uint(Bs2[kk + tq + 4][c0]);
        }
#pragma unroll
        for (int nt = 0; nt < 3; ++nt)
            mma_tf32(acc2[nt], af, bf[nt]);
    }

    // Store
#pragma unroll
    for (int nt = 0; nt < 3; ++nt) {
        int col = nt * 8 + 2 * tq;
        int ta = t0 + r0;
        if (ta < Lout) {
            *reinterpret_cast<float2*>(outp + ((size_t)b * LMAX + ta) * 24 + col) =
                make_float2(acc2[nt][0], acc2[nt][1]);
        }
        int tb = t0 + r1;
        if (tb < Lout) {
            *reinterpret_cast<float2*>(outp + ((size_t)b * LMAX + tb) * 24 + col) =
                make_float2(acc2[nt][2], acc2[nt][3]);
        }
    }
}

// ---------------------------------------------------------------------------
// K4a: act128 = relu(resW conv of (prev[t+256] + out[t])). bf16 output.
// ---------------------------------------------------------------------------
__global__ __launch_bounds__(256) void k_resrelu(const float* __restrict__ resW,
                                                 const float* __restrict__ resb) {
    const int b  = blockIdx.y;
    const int t0 = blockIdx.x * 64;
    const int tid = threadIdx.x;
    const int og = tid & 31;
    const int tg = tid >> 5;

    __shared__ float s_in[64][25];
    for (int idx = tid; idx < 64 * 24; idx += 256) {
        int r = idx / 24, c = idx % 24;
        size_t prow = (size_t)b * LMAX + 256 + t0 + r;
        size_t orow = (size_t)b * LMAX + t0 + r;
        s_in[r][c] = g_bufA[prow * 24 + c] + g_bufB[orow * 24 + c];
    }
    __syncthreads();

    const float4 bb = reinterpret_cast<const float4*>(resb)[og];
    float acc[8][4];
#pragma unroll
    for (int rr = 0; rr < 8; ++rr) {
        acc[rr][0] = bb.x; acc[rr][1] = bb.y; acc[rr][2] = bb.z; acc[rr][3] = bb.w;
    }
#pragma unroll 4
    for (int c = 0; c < 24; ++c) {
        float4 w = reinterpret_cast<const float4*>(resW)[c * 32 + og];
#pragma unroll
        for (int rr = 0; rr < 8; ++rr) {
            float xin = s_in[tg * 8 + rr][c];
            acc[rr][0] += xin * w.x; acc[rr][1] += xin * w.y;
            acc[rr][2] += xin * w.z; acc[rr][3] += xin * w.w;
        }
    }
#pragma unroll
    for (int rr = 0; rr < 8; ++rr) {
        int row = t0 + tg * 8 + rr;
        __nv_bfloat16* dst = g_act128 + ((size_t)b * TOUT + row) * 128 + og * 4;
        *reinterpret_cast<__nv_bfloat162*>(dst) =
            __float22bfloat162_rn(make_float2(fmaxf(acc[rr][0], 0.f), fmaxf(acc[rr][1], 0.f)));
        *reinterpret_cast<__nv_bfloat162*>(dst + 2) =
            __float22bfloat162_rn(make_float2(fmaxf(acc[rr][2], 0.f), fmaxf(acc[rr][3], 0.f)));
    }
}

// ---------------------------------------------------------------------------
// K4b: act256 = relu(act128 @ f1W + f1b). bf16 GEMM, whole K=128 in smem.
// ---------------------------------------------------------------------------
__global__ __launch_bounds__(256) void k_gemm_relu(const float* __restrict__ f1b) {
    const int t0 = blockIdx.x * 128;
    const int o0 = blockIdx.y * 128;
    const int b  = blockIdx.z;
    const int tid  = threadIdx.x;
    const int warp = tid >> 5, lane = tid & 31;
    const int m_off = (warp >> 2) * 64;
    const int n_off = (warp & 3) * 32;
    const int g  = lane >> 2;
    const int tq = lane & 3;

    __shared__ __align__(16) __nv_bfloat16 As[128][136];  // K=128, pad 8
    __shared__ __align__(16) __nv_bfloat16 Bs[128][136];

#pragma unroll
    for (int q = 0; q < 8; ++q) {
        int idx = tid + q * 256;
        int r = idx >> 4, u = idx & 15;
        *reinterpret_cast<uint4*>(&As[r][u * 8]) =
            *reinterpret_cast<const uint4*>(g_act128 + ((size_t)b * TOUT + t0 + r) * 128 + u * 8);
        *reinterpret_cast<uint4*>(&Bs[r][u * 8]) =
            *reinterpret_cast<const uint4*>(g_f1t + (size_t)(o0 + r) * 128 + u * 8);
    }
    __syncthreads();

    float acc[4][4][4];
#pragma unroll
    for (int mt = 0; mt < 4; ++mt)
#pragma unroll
        for (int nt = 0; nt < 4; ++nt)
#pragma unroll
            for (int q = 0; q < 4; ++q) acc[mt][nt][q] = 0.0f;

#pragma unroll
    for (int kk = 0; kk < 128; kk += 16) {
        uint32_t af[4][4];
#pragma unroll
        for (int mt = 0; mt < 4; ++mt) {
            int r0 = m_off + mt * 16 + g;
            af[mt][0] = ld_bf2(&As[r0][kk + 2 * tq]);
            af[mt][1] = ld_bf2(&As[r0 + 8][kk + 2 * tq]);
            af[mt][2] = ld_bf2(&As[r0][kk + 8 + 2 * tq]);
            af[mt][3] = ld_bf2(&As[r0 + 8][kk + 8 + 2 * tq]);
        }
        uint32_t bf[4][2];
#pragma unroll
        for (int nt = 0; nt < 4; ++nt) {
            int c0 = n_off + nt * 8 + g;
            bf[nt][0] = ld_bf2(&Bs[c0][kk + 2 * tq]);
            bf[nt][1] = ld_bf2(&Bs[c0][kk + 8 + 2 * tq]);
        }
#pragma unroll
        for (int mt = 0; mt < 4; ++mt)
#pragma unroll
            for (int nt = 0; nt < 4; ++nt)
                mma_bf16(acc[mt][nt], af[mt], bf[nt]);
    }

#pragma unroll
    for (int nt = 0; nt < 4; ++nt) {
        const int col = o0 + n_off + nt * 8 + 2 * tq;
        const float2 bias = *reinterpret_cast<const float2*>(f1b + col);
#pragma unroll
        for (int mt = 0; mt < 4; ++mt) {
            int row = t0 + m_off + mt * 16 + g;
            *reinterpret_cast<__nv_bfloat162*>(g_act256 + ((size_t)b * TOUT + row) * 256 + col) =
                __float22bfloat162_rn(make_float2(fmaxf(acc[mt][nt][0] + bias.x, 0.f),
                                                  fmaxf(acc[mt][nt][1] + bias.y, 0.f)));
            *reinterpret_cast<__nv_bfloat162*>(g_act256 + ((size_t)b * TOUT + row + 8) * 256 + col) =
                __float22bfloat162_rn(make_float2(fmaxf(acc[mt][nt][2] + bias.x, 0.f),
                                                  fmaxf(acc[mt][nt][3] + bias.y, 0.f)));
        }
    }
}

// ---------------------------------------------------------------------------
// K4c: y = softmax(act256 @ f2W + f2b). bf16 GEMM, M tile 64, full N=256.
// Whole A (K=256) in smem; B chunked by 32. Fused row softmax.
// ---------------------------------------------------------------------------
__global__ __launch_bounds__(256) void k_gemm_softmax(const float* __restrict__ f2b,
                                                      float* __restrict__ y) {
    const int t0 = blockIdx.x * 64;
    const int b  = blockIdx.y;
    const int tid  = threadIdx.x;
    const int warp = tid >> 5, lane = tid & 31;
    const int mw = warp >> 2;
    const int nw = warp & 3;
    const int m_off = mw * 32;
    const int n_off = nw * 64;
    const int g  = lane >> 2;
    const int tq = lane & 3;

    __shared__ __align__(16) __nv_bfloat16 As[64][264];   // K=256, pad 8
    __shared__ __align__(16) __nv_bfloat16 Bs[256][40];   // [n][k-chunk 32]
    __shared__ float red1[64][4];
    __shared__ float red2[64][4];

    // Whole A tile: 64 rows x 256 bf16 = 2048 uint4, 8 per thread
#pragma unroll
    for (int q = 0; q < 8; ++q) {
        int idx = tid + q * 256;
        int r = idx >> 5, u = idx & 31;
        *reinterpret_cast<uint4*>(&As[r][u * 8]) =
            *reinterpret_cast<const uint4*>(g_act256 + ((size_t)b * TOUT + t0 + r) * 256 + u * 8);
    }

    float acc[2][8][4];
#pragma unroll
    for (int mt = 0; mt < 2; ++mt)
#pragma unroll
        for (int nt = 0; nt < 8; ++nt)
#pragma unroll
            for (int q = 0; q < 4; ++q) acc[mt][nt][q] = 0.0f;

    for (int k0 = 0; k0 < 256; k0 += 32) {
        __syncthreads();
        // B chunk: 256 n-rows x 32 k = 1024 uint4, 4 per thread
#pragma unroll
        for (int q = 0; q < 4; ++q) {
            int idx = tid + q * 256;
            int r = idx >> 2, c8 = idx & 3;
            *reinterpret_cast<uint4*>(&Bs[r][c8 * 8]) =
                *reinterpret_cast<const uint4*>(g_f2t + (size_t)r * 256 + k0 + c8 * 8);
        }
        __syncthreads();
#pragma unroll
        for (int kk = 0; kk < 32; kk += 16) {
            uint32_t af[2][4];
#pragma unroll
            for (int mt = 0; mt < 2; ++mt) {
                int r0 = m_off + mt * 16 + g;
                af[mt][0] = ld_bf2(&As[r0][k0 + kk + 2 * tq]);
                af[mt][1] = ld_bf2(&As[r0 + 8][k0 + kk + 2 * tq]);
                af[mt][2] = ld_bf2(&As[r0][k0 + kk + 8 + 2 * tq]);
                af[mt][3] = ld_bf2(&As[r0 + 8][k0 + kk + 8 + 2 * tq]);
            }
            uint32_t bf[8][2];
#pragma unroll
            for (int nt = 0; nt < 8; ++nt) {
                int c0 = n_off + nt * 8 + g;
                bf[nt][0] = ld_bf2(&Bs[c0][kk + 2 * tq]);
                bf[nt][1] = ld_bf2(&Bs[c0][kk + 8 + 2 * tq]);
            }
#pragma unroll
            for (int mt = 0; mt < 2; ++mt)
#pragma unroll
                for (int nt = 0; nt < 8; ++nt)
                    mma_bf16(acc[mt][nt], af[mt], bf[nt]);
        }
    }

#pragma unroll
    for (int nt = 0; nt < 8; ++nt) {
        const int col = n_off + nt * 8 + 2 * tq;
        const float2 bias = *reinterpret_cast<const float2*>(f2b + col);
#pragma unroll
        for (int mt = 0; mt < 2; ++mt) {
            acc[mt][nt][0] += bias.x; acc[mt][nt][1] += bias.y;
            acc[mt][nt][2] += bias.x; acc[mt][nt][3] += bias.y;
        }
    }

    float rmax[2][2];
#pragma unroll
    for (int mt = 0; mt < 2; ++mt)
#pragma unroll
        for (int rr = 0; rr < 2; ++rr) {
            float m = -1e30f;
#pragma unroll
            for (int nt = 0; nt < 8; ++nt) {
                m = fmaxf(m, acc[mt][nt][rr * 2 + 0]);
                m = fmaxf(m, acc[mt][nt][rr * 2 + 1]);
            }
            m = fmaxf(m, __shfl_xor_sync(0xffffffffu, m, 1));
            m = fmaxf(m, __shfl_xor_sync(0xffffffffu, m, 2));
            rmax[mt][rr] = m;
            if (tq == 0) red1[m_off + mt * 16 + rr * 8 + g][nw] = m;
        }
    __syncthreads();
#pragma unroll
    for (int mt = 0; mt < 2; ++mt)
#pragma unroll
        for (int rr = 0; rr < 2; ++rr) {
            int r = m_off + mt * 16 + rr * 8 + g;
            rmax[mt][rr] = fmaxf(fmaxf(red1[r][0], red1[r][1]),
                                 fmaxf(red1[r][2], red1[r][3]));
        }

    float rsum[2][2];
#pragma unroll
    for (int mt = 0; mt < 2; ++mt)
#pragma unroll
        for (int rr = 0; rr < 2; ++rr) {
            float s = 0.f;
#pragma unroll
            for (int nt = 0; nt < 8; ++nt) {
                float e0 = __expf(acc[mt][nt][rr * 2 + 0] - rmax[mt][rr]);
                float e1 = __expf(acc[mt][nt][rr * 2 + 1] - rmax[mt][rr]);
                acc[mt][nt][rr * 2 + 0] = e0;
                acc[mt][nt][rr * 2 + 1] = e1;
                s += e0 + e1;
            }
            s += __shfl_xor_sync(0xffffffffu, s, 1);
            s += __shfl_xor_sync(0xffffffffu, s, 2);
            rsum[mt][rr] = s;
            if (tq == 0) red2[m_off + mt * 16 + rr * 8 + g][nw] = s;
        }
    __syncthreads();
#pragma unroll
    for (int mt = 0; mt < 2; ++mt)
#pragma unroll
        for (int rr = 0; rr < 2; ++rr) {
            int r = m_off + mt * 16 + rr * 8 + g;
            rsum[mt][rr] = __fdividef(1.0f, red2[r][0] + red2[r][1] + red2[r][2] + red2[r][3]);
        }

#pragma unroll
    for (int nt = 0; nt < 8; ++nt) {
        const int col = n_off + nt * 8 + 2 * tq;
#pragma unroll
        for (int mt = 0; mt < 2; ++mt) {
            int row = t0 + m_off + mt * 16 + g;
            float2 v0 = make_float2(acc[mt][nt][0] * rsum[mt][0],
                                    acc[mt][nt][1] * rsum[mt][0]);
            float2 v1 = make_float2(acc[mt][nt][2] * rsum[mt][1],
                                    acc[mt][nt][3] * rsum[mt][1]);
            *reinterpret_cast<float2*>(y + ((size_t)b * TOUT + row) * 256 + col) = v0;
            *reinterpret_cast<float2*>(y + ((size_t)b * TOUT + row + 8) * 256 + col) = v1;
        }
    }
}

// ---------------------------------------------------------------------------
extern "C" void kernel_launch(void* const* d_in, const int* in_sizes, int n_in,
                              void* d_out, int out_size) {
    const float* x     = (const float*)d_in[0];
    const float* cW    = (const float*)d_in[1];
    const float* cb    = (const float*)d_in[2];
    const float* gW0   = (const float*)d_in[3];
    const float* gb0   = (const float*)d_in[4];
    const float* fW0   = (const float*)d_in[5];
    const float* fb0   = (const float*)d_in[6];
    const float* sW0   = (const float*)d_in[7];
    const float* sb0   = (const float*)d_in[8];
    const float* gateW = (const float*)d_in[9];
    const float* gateB = (const float*)d_in[10];
    const float* filtW = (const float*)d_in[11];
    const float* filtB = (const float*)d_in[12];
    const float* scW   = (const float*)d_in[13];
    const float* scB   = (const float*)d_in[14];
    const float* resW  = (const float*)d_in[15];
    const float* resB  = (const float*)d_in[16];
    const float* f1b   = (const float*)d_in[18];
    const float* f1W   = (const float*)d_in[17];
    const float* f2W   = (const float*)d_in[19];
    const float* f2b   = (const float*)d_in[20];
    float* out = (float*)d_out;

    k_prep_x<<<4096, 256>>>(x);
    k_prep_w<<<256, 256>>>(cW, gW0, fW0, f1W, f2W);

    k_causal_mma<<<dim3(128, 2, BATCH), 256>>>(cb);
    k_gated0_mma<<<dim3(128, BATCH), 256>>>(gb0, fb0, sW0, sb0);

    int L = L0;
    for (int i = 0; i < 9; ++i) {
        int d = 2 << i;          // 2,4,...,512
        int Lout = L - d;
        int nb = (Lout + 255) / 256;
        // Only the LAST residual conv contributes to the output (acc is
        // overwritten each iteration in the reference), so res convs 0..7 are skipped.
        k_dilated_mma<<<dim3(nb, BATCH), 512>>>(gateW + i * 1152, gateB + i * 24,
                                                filtW + i * 1152, filtB + i * 24,
                                                scW + i * 576, scB + i * 24,
                                                d, Lout, i & 1);
        L = Lout;
    }
    // prev (input of layer i=8) lives in g_bufA (len 15872); its output in g_bufB (15360)
    k_resrelu<<<dim3(TOUT / 64, BATCH), 256>>>(resW + 8 * 24 * 128, resB + 8 * 128);
    k_gemm_relu<<<dim3(TOUT / 128, 2, BATCH), 256>>>(f1b);
    k_gemm_softmax<<<dim3(TOUT / 64, BATCH), 256>>>(f2b, out);
}

// round 10
// speedup vs baseline: 4.8311x; 1.1097x over previous
#include <cuda_runtime.h>
#include <cuda_bf16.h>
#include <cstdint>
#include <cstddef>

#define BATCH 8
#define TLEN  16384
#define CIN   256
#define T1    16383   // causal conv output length
#define L0    16382   // gated0 output length
#define LMAX  16382   // per-batch row stride for 24-ch buffers
#define TOUT  15360

// Scratch (static device globals: allocation-free per harness rules)
__device__ __nv_bfloat16 g_xb[(size_t)BATCH * TLEN * CIN];      // 67 MB (x in bf16)
__device__ __nv_bfloat16 g_h1[(size_t)BATCH * T1 * CIN];        // 67 MB
__device__ __nv_bfloat16 g_bufA[(size_t)BATCH * LMAX * 24];     // 6.3 MB
__device__ __nv_bfloat16 g_bufB[(size_t)BATCH * LMAX * 24];     // 6.3 MB
__device__ __nv_bfloat16 g_act128[(size_t)BATCH * TOUT * 128];  // 31 MB
__device__ __nv_bfloat16 g_act256[(size_t)BATCH * TOUT * 256];  // 63 MB
// Pre-converted, transposed bf16 weights: [n][k] layout for mma B-frags
__device__ __nv_bfloat16 g_cWt[256 * 512];
__device__ __nv_bfloat16 g_gf0t[48 * 512];
__device__ __nv_bfloat16 g_f1t[256 * 128];
__device__ __nv_bfloat16 g_f2t[256 * 256];

__device__ __forceinline__ float tanh_fast(float x) {
    float y;
    asm("tanh.approx.f32 %0, %1;" : "=f"(y) : "f"(x));
    return y;
}
__device__ __forceinline__ float sigmoid_fast(float x) {
    return __fdividef(1.0f, 1.0f + __expf(-x));
}
__device__ __forceinline__ uint32_t pack_bf2(float a, float b) {
    __nv_bfloat162 t = __float22bfloat162_rn(make_float2(a, b));
    return *reinterpret_cast<uint32_t*>(&t);
}

__device__ __forceinline__ void mma_bf16(float c[4], const uint32_t a[4], const uint32_t b[2]) {
    asm volatile(
        "mma.sync.aligned.m16n8k16.row.col.f32.bf16.bf16.f32 "
        "{%0,%1,%2,%3}, {%4,%5,%6,%7}, {%8,%9}, {%0,%1,%2,%3};"
        : "+f"(c[0]), "+f"(c[1]), "+f"(c[2]), "+f"(c[3])
        : "r"(a[0]), "r"(a[1]), "r"(a[2]), "r"(a[3]), "r"(b[0]), "r"(b[1]));
}

__device__ __forceinline__ uint32_t ld_bf2(const __nv_bfloat16* p) {
    return *reinterpret_cast<const uint32_t*>(p);
}

__device__ __forceinline__ void cp16(uint32_t smem_dst, const void* gsrc) {
    asm volatile("cp.async.ca.shared.global [%0], [%1], 16;" :: "r"(smem_dst), "l"(gsrc));
}
__device__ __forceinline__ void cp_commit() {
    asm volatile("cp.async.commit_group;" ::: "memory");
}
__device__ __forceinline__ void cp_wait_all() {
    asm volatile("cp.async.wait_group 0;" ::: "memory");
}

// ---------------------------------------------------------------------------
// Prep: x -> bf16
// ---------------------------------------------------------------------------
__global__ void k_prep_x(const float* __restrict__ x) {
    const size_t n4 = (size_t)BATCH * TLEN * CIN / 4;
    for (size_t i = blockIdx.x * blockDim.x + threadIdx.x; i < n4;
         i += (size_t)gridDim.x * blockDim.x) {
        float4 v = reinterpret_cast<const float4*>(x)[i];
        uint2 u;
        u.x = pack_bf2(v.x, v.y);
        u.y = pack_bf2(v.z, v.w);
        reinterpret_cast<uint2*>(g_xb)[i] = u;
    }
}

// ---------------------------------------------------------------------------
// Prep: weights -> bf16, transposed [n][k]
// ---------------------------------------------------------------------------
__global__ void k_prep_w(const float* __restrict__ cW,
                         const float* __restrict__ gW0,
                         const float* __restrict__ fW0,
                         const float* __restrict__ f1W,
                         const float* __restrict__ f2W) {
    const int stride = gridDim.x * blockDim.x;
    const int tid = blockIdx.x * blockDim.x + threadIdx.x;
    for (int idx = tid; idx < 256 * 512; idx += stride) {
        int o = idx >> 9, r = idx & 511;
        int tap = r >> 8, i = r & 255;
        g_cWt[idx] = __float2bfloat16(cW[tap * 65536 + i * 256 + o]);
    }
    for (int idx = tid; idx < 48 * 512; idx += stride) {
        int n = idx >> 9, r = idx & 511;
        int tap = r >> 8, i = r & 255;
        float v = (n < 24) ? gW0[tap * 6144 + i * 24 + n]
                           : fW0[tap * 6144 + i * 24 + (n - 24)];
        g_gf0t[idx] = __float2bfloat16(v);
    }
    for (int idx = tid; idx < 256 * 128; idx += stride) {
        int o = idx >> 7, k = idx & 127;
        g_f1t[idx] = __float2bfloat16(f1W[k * 256 + o]);
    }
    for (int idx = tid; idx < 256 * 256; idx += stride) {
        int o = idx >> 8, k = idx & 255;
        g_f2t[idx] = __float2bfloat16(f2W[k * 256 + o]);
    }
}

// ---------------------------------------------------------------------------
// K1: causal conv as bf16 GEMM (m16n8k16), 2-stage cp.async pipeline.
// ---------------------------------------------------------------------------
__global__ __launch_bounds__(256) void k_causal_mma(const float* __restrict__ cb) {
    const int t0 = blockIdx.x * 128;
    const int o0 = blockIdx.y * 128;
    const int b  = blockIdx.z;
    const int tid  = threadIdx.x;
    const int warp = tid >> 5, lane = tid & 31;
    const int m_off = (warp >> 2) * 64;
    const int n_off = (warp & 3) * 32;
    const int g  = lane >> 2;
    const int tq = lane & 3;

    __shared__ __align__(16) __nv_bfloat16 As[2][128][40];
    __shared__ __align__(16) __nv_bfloat16 Bs[2][128][40];
    const uint32_t as_base = (uint32_t)__cvta_generic_to_shared(&As[0][0][0]);
    const uint32_t bs_base = (uint32_t)__cvta_generic_to_shared(&Bs[0][0][0]);

    float acc[4][4][4];
#pragma unroll
    for (int mt = 0; mt < 4; ++mt)
#pragma unroll
        for (int nt = 0; nt < 4; ++nt)
#pragma unroll
            for (int q = 0; q < 4; ++q) acc[mt][nt][q] = 0.0f;

#define CAUSAL_LOAD(chunk, s) do {                                              \
    int k0 = (chunk) * 32; int tap = k0 >> 8; int ch = k0 & 255;                \
    _Pragma("unroll")                                                            \
    for (int q = 0; q < 2; ++q) {                                                \
        int idx = tid + q * 256;                                                 \
        int r = idx >> 2, c8 = idx & 3;                                          \
        int row = t0 + r + tap; if (row > TLEN - 1) row = TLEN - 1;              \
        cp16(as_base + (uint32_t)((((s) * 128 + r) * 40 + c8 * 8) * 2),          \
             g_xb + ((size_t)b * TLEN + row) * CIN + ch + c8 * 8);               \
    }                                                                            \
    _Pragma("unroll")                                                            \
    for (int q = 0; q < 2; ++q) {                                                \
        int idx = tid + q * 256;                                                 \
        int r = idx >> 2, c8 = idx & 3;                                          \
        cp16(bs_base + (uint32_t)((((s) * 128 + r) * 40 + c8 * 8) * 2),          \
             g_cWt + (size_t)(o0 + r) * 512 + k0 + c8 * 8);                      \
    }                                                                            \
} while (0)

    CAUSAL_LOAD(0, 0);
    cp_commit();

    for (int c = 0; c < 16; ++c) {
        const int s = c & 1;
        cp_wait_all();
        __syncthreads();
        if (c < 15) { CAUSAL_LOAD(c + 1, s ^ 1); cp_commit(); }
#pragma unroll
        for (int kk = 0; kk < 32; kk += 16) {
            uint32_t af[4][4];
#pragma unroll
            for (int mt = 0; mt < 4; ++mt) {
                int r0 = m_off + mt * 16 + g;
                af[mt][0] = ld_bf2(&As[s][r0][kk + 2 * tq]);
                af[mt][1] = ld_bf2(&As[s][r0 + 8][kk + 2 * tq]);
                af[mt][2] = ld_bf2(&As[s][r0][kk + 8 + 2 * tq]);
                af[mt][3] = ld_bf2(&As[s][r0 + 8][kk + 8 + 2 * tq]);
            }
            uint32_t bf[4][2];
#pragma unroll
            for (int nt = 0; nt < 4; ++nt) {
                int c0 = n_off + nt * 8 + g;
                bf[nt][0] = ld_bf2(&Bs[s][c0][kk + 2 * tq]);
                bf[nt][1] = ld_bf2(&Bs[s][c0][kk + 8 + 2 * tq]);
            }
#pragma unroll
            for (int mt = 0; mt < 4; ++mt)
#pragma unroll
                for (int nt = 0; nt < 4; ++nt)
                    mma_bf16(acc[mt][nt], af[mt], bf[nt]);
        }
        __syncthreads();
    }
#undef CAUSAL_LOAD

#pragma unroll
    for (int nt = 0; nt < 4; ++nt) {
        const int col = o0 + n_off + nt * 8 + 2 * tq;
        const float2 bias = *reinterpret_cast<const float2*>(cb + col);
#pragma unroll
        for (int mt = 0; mt < 4; ++mt) {
            int row = t0 + m_off + mt * 16 + g;
            if (row < T1) {
                *reinterpret_cast<uint32_t*>(g_h1 + ((size_t)b * T1 + row) * CIN + col) =
                    pack_bf2(acc[mt][nt][0] + bias.x, acc[mt][nt][1] + bias.y);
            }
            if (row + 8 < T1) {
                *reinterpret_cast<uint32_t*>(g_h1 + ((size_t)b * T1 + row + 8) * CIN + col) =
                    pack_bf2(acc[mt][nt][2] + bias.x, acc[mt][nt][3] + bias.y);
            }
        }
    }
}

// ---------------------------------------------------------------------------
// K2: gated0 as bf16 GEMM on bf16 h1: K=512, N=48 ([gW|fW], whole B in smem).
// cp.async double-buffered A tiles; epilogue = bf16 MMA2 (24x24 1x1).
// Output -> bf16 g_bufA.
// ---------------------------------------------------------------------------
__global__ __launch_bounds__(256) void k_gated0_mma(const float* __restrict__ gb,
                                                    const float* __restrict__ fb,
                                                    const float* __restrict__ sW,
                                                    const float* __restrict__ sb) {
    const int t0 = blockIdx.x * 128;
    const int b  = blockIdx.y;
    const int tid  = threadIdx.x;
    const int warp = tid >> 5, lane = tid & 31;
    const int m_off = warp * 16;
    const int g  = lane >> 2;
    const int tq = lane & 3;

    __shared__ __align__(16) __nv_bfloat16 sGF[48][520];   // [n][k], pad 8
    __shared__ __align__(16) __nv_bfloat16 As[2][128][40];
    __shared__ __align__(16) __nv_bfloat16 Hs[128][32];    // K padded to 32
    __shared__ __align__(16) __nv_bfloat16 Bs2t[24][40];   // [o][c], c padded to 32
    const uint32_t as_base = (uint32_t)__cvta_generic_to_shared(&As[0][0][0]);

    // full B into smem (48 x 512 bf16)
#pragma unroll
    for (int q = 0; q < 12; ++q) {
        int idx = tid + q * 256;
        int n = idx >> 6, u = idx & 63;
        *reinterpret_cast<uint4*>(&sGF[n][u * 8]) =
            *reinterpret_cast<const uint4*>(g_gf0t + (size_t)n * 512 + u * 8);
    }
    // Bs2t[o][c] = sW[c*24+o]; pad c 24..31 with zeros
    for (int idx = tid; idx < 24 * 32; idx += 256) {
        int o = idx >> 5, c = idx & 31;
        Bs2t[o][c] = (c < 24) ? __float2bfloat16(sW[c * 24 + o]) : __float2bfloat16(0.f);
    }

#define G0_LOAD(chunk, s) do {                                                  \
    int k0 = (chunk) * 32; int tap = k0 >> 8; int ch = k0 & 255;                \
    _Pragma("unroll")                                                            \
    for (int q = 0; q < 2; ++q) {                                                \
        int idx = tid + q * 256;                                                 \
        int r = idx >> 2, c8 = idx & 3;                                          \
        int row = t0 + r + tap; if (row > T1 - 1) row = T1 - 1;                  \
        cp16(as_base + (uint32_t)((((s) * 128 + r) * 40 + c8 * 8) * 2),          \
             g_h1 + ((size_t)b * T1 + row) * CIN + ch + c8 * 8);                 \
    }                                                                            \
} while (0)

    float acc[6][4];
#pragma unroll
    for (int nt = 0; nt < 6; ++nt) {
        int c0 = nt * 8 + 2 * tq;
        float b0 = (nt < 3) ? gb[c0] : fb[c0 - 24];
        float b1 = (nt < 3) ? gb[c0 + 1] : fb[c0 - 23];
        acc[nt][0] = b0; acc[nt][1] = b1; acc[nt][2] = b0; acc[nt][3] = b1;
    }

    G0_LOAD(0, 0);
    cp_commit();

    for (int c = 0; c < 16; ++c) {
        const int s = c & 1;
        const int k0 = c * 32;
        cp_wait_all();
        __syncthreads();
        if (c < 15) { G0_LOAD(c + 1, s ^ 1); cp_commit(); }
#pragma unroll
        for (int kk = 0; kk < 32; kk += 16) {
            uint32_t af[4];
            af[0] = ld_bf2(&As[s][m_off + g][kk + 2 * tq]);
            af[1] = ld_bf2(&As[s][m_off + g + 8][kk + 2 * tq]);
            af[2] = ld_bf2(&As[s][m_off + g][kk + 8 + 2 * tq]);
            af[3] = ld_bf2(&As[s][m_off + g + 8][kk + 8 + 2 * tq]);
            uint32_t bf[6][2];
#pragma unroll
            for (int nt = 0; nt < 6; ++nt) {
                int c0 = nt * 8 + g;
                bf[nt][0] = ld_bf2(&sGF[c0][k0 + kk + 2 * tq]);
                bf[nt][1] = ld_bf2(&sGF[c0][k0 + kk + 8 + 2 * tq]);
            }
#pragma unroll
            for (int nt = 0; nt < 6; ++nt)
                mma_bf16(acc[nt], af, bf[nt]);
        }
        __syncthreads();
    }
#undef G0_LOAD

    // Nonlinearity -> Hs (bf16, warp-private rows); zero-pad cols 24..31
    const int r0 = m_off + g, r1 = r0 + 8;
#pragma unroll
    for (int nt = 0; nt < 3; ++nt) {
        int c0 = nt * 8 + 2 * tq;
        *reinterpret_cast<uint32_t*>(&Hs[r0][c0]) =
            pack_bf2(tanh_fast(acc[nt + 3][0]) * sigmoid_fast(acc[nt][0]),
                     tanh_fast(acc[nt + 3][1]) * sigmoid_fast(acc[nt][1]));
        *reinterpret_cast<uint32_t*>(&Hs[r1][c0]) =
            pack_bf2(tanh_fast(acc[nt + 3][2]) * sigmoid_fast(acc[nt][2]),
                     tanh_fast(acc[nt + 3][3]) * sigmoid_fast(acc[nt][3]));
    }
    *reinterpret_cast<uint32_t*>(&Hs[r0][24 + 2 * tq]) = 0u;
    *reinterpret_cast<uint32_t*>(&Hs[r1][24 + 2 * tq]) = 0u;
    __syncwarp();

    // MMA2: Hs[128x32] x Bs2t (24 outputs), K=32
    float acc2[3][4];
#pragma unroll
    for (int nt = 0; nt < 3; ++nt) {
        int c0 = nt * 8 + 2 * tq;
        float b0 = sb[c0], b1 = sb[c0 + 1];
        acc2[nt][0] = b0; acc2[nt][1] = b1; acc2[nt][2] = b0; acc2[nt][3] = b1;
    }
#pragma unroll
    for (int kk = 0; kk < 32; kk += 16) {
        uint32_t af[4];
        af[0] = ld_bf2(&Hs[r0][kk + 2 * tq]);
        af[1] = ld_bf2(&Hs[r1][kk + 2 * tq]);
        af[2] = ld_bf2(&Hs[r0][kk + 8 + 2 * tq]);
        af[3] = ld_bf2(&Hs[r1][kk + 8 + 2 * tq]);
        uint32_t bf[3][2];
#pragma unroll
        for (int nt = 0; nt < 3; ++nt) {
            int c0 = nt * 8 + g;
            bf[nt][0] = ld_bf2(&Bs2t[c0][kk + 2 * tq]);
            bf[nt][1] = ld_bf2(&Bs2t[c0][kk + 8 + 2 * tq]);
        }
#pragma unroll
        for (int nt = 0; nt < 3; ++nt)
            mma_bf16(acc2[nt], af, bf[nt]);
    }

#pragma unroll
    for (int nt = 0; nt < 3; ++nt) {
        int col = nt * 8 + 2 * tq;
        int ta = t0 + r0;
        if (ta < L0)
            *reinterpret_cast<uint32_t*>(g_bufA + ((size_t)b * LMAX + ta) * 24 + col) =
                pack_bf2(acc2[nt][0], acc2[nt][1]);
        int tb = t0 + r1;
        if (tb < L0)
            *reinterpret_cast<uint32_t*>(g_bufA + ((size_t)b * LMAX + tb) * 24 + col) =
                pack_bf2(acc2[nt][2], acc2[nt][3]);
    }
}

// ---------------------------------------------------------------------------
// K3: dilated gated layer, bf16 MMA end-to-end. 512 threads, 256 rows/block.
// ---------------------------------------------------------------------------
__global__ __launch_bounds__(512) void k_dilated_mma(const float* __restrict__ gW,
                                                     const float* __restrict__ gb,
                                                     const float* __restrict__ fW,
                                                     const float* __restrict__ fb,
                                                     const float* __restrict__ sW,
                                                     const float* __restrict__ sb,
                                                     int d, int Lout, int dir) {
    const __nv_bfloat16* in = dir ? g_bufB : g_bufA;
    __nv_bfloat16*     outp = dir ? g_bufA : g_bufB;
    const int b  = blockIdx.y;
    const int t0 = blockIdx.x * 256;
    const int tid = threadIdx.x;
    const int warp = tid >> 5, lane = tid & 31;
    const int m_off = warp * 16;    // 16 warps x 16 rows = 256 rows
    const int g  = lane >> 2;
    const int tq = lane & 3;

    __shared__ __align__(16) __nv_bfloat16 As[256][56];    // [m][k=48], pad 8
    __shared__ __align__(16) __nv_bfloat16 Bs1t[48][56];   // [n][k=48]
    __shared__ __align__(16) __nv_bfloat16 Hs[256][32];    // K padded to 32
    __shared__ __align__(16) __nv_bfloat16 Bs2t[24][40];   // [o][c=32]

    const int Lin = Lout + d;
    // A tile: one (row, tap) task per thread: r = tid>>1, tap = tid&1.
    {
        const int r    = tid >> 1;
        const int tap  = tid & 1;
        const int row  = t0 + r + (tap ? d : 0);
        const bool ok  = row < Lin;
        const __nv_bfloat16* src = in + ((size_t)b * LMAX + row) * 24;
        const int cbase = tap * 24;
        if (ok) {
#pragma unroll
            for (int j = 0; j < 3; ++j)
                *reinterpret_cast<uint4*>(&As[r][cbase + j * 8]) =
                    *reinterpret_cast<const uint4*>(src + j * 8);
        } else {
            uint4 z = make_uint4(0, 0, 0, 0);
#pragma unroll
            for (int j = 0; j < 3; ++j)
                *reinterpret_cast<uint4*>(&As[r][cbase + j * 8]) = z;
        }
    }
    // B1t[n][k]: k = tap*24+ci ; n<24 gate, n>=24 filter
    for (int idx = tid; idx < 48 * 48; idx += 512) {
        int n = idx / 48, k = idx % 48;
        int tap = k / 24, ci = k % 24;
        float w = (n < 24) ? gW[tap * 576 + ci * 24 + n]
                           : fW[tap * 576 + ci * 24 + (n - 24)];
        Bs1t[n][k] = __float2bfloat16(w);
    }
    // Bs2t[o][c] = sW[c*24+o], zero-padded c 24..31
    for (int idx = tid; idx < 24 * 32; idx += 512) {
        int o = idx >> 5, c = idx & 31;
        Bs2t[o][c] = (c < 24) ? __float2bfloat16(sW[c * 24 + o]) : __float2bfloat16(0.f);
    }
    __syncthreads();

    // MMA1: A[256x48] x B1t -> N=48 (gate|filter), K=48 (3 k16 steps)
    float acc[6][4];
#pragma unroll
    for (int nt = 0; nt < 6; ++nt) {
        int c0 = (nt < 3) ? (nt * 8 + 2 * tq) : ((nt - 3) * 8 + 2 * tq);
        float b0 = (nt < 3) ? gb[c0] : fb[c0];
        float b1 = (nt < 3) ? gb[c0 + 1] : fb[c0 + 1];
        acc[nt][0] = b0; acc[nt][1] = b1; acc[nt][2] = b0; acc[nt][3] = b1;
    }
    const int r0 = m_off + g, r1 = r0 + 8;
#pragma unroll
    for (int kk = 0; kk < 48; kk += 16) {
        uint32_t af[4];
        af[0] = ld_bf2(&As[r0][kk + 2 * tq]);
        af[1] = ld_bf2(&As[r1][kk + 2 * tq]);
        af[2] = ld_bf2(&As[r0][kk + 8 + 2 * tq]);
        af[3] = ld_bf2(&As[r1][kk + 8 + 2 * tq]);
        uint32_t bf[6][2];
#pragma unroll
        for (int nt = 0; nt < 6; ++nt) {
            int c0 = nt * 8 + g;
            bf[nt][0] = ld_bf2(&Bs1t[c0][kk + 2 * tq]);
            bf[nt][1] = ld_bf2(&Bs1t[c0][kk + 8 + 2 * tq]);
        }
#pragma unroll
        for (int nt = 0; nt < 6; ++nt)
            mma_bf16(acc[nt], af, bf[nt]);
    }

    // Nonlinearity -> Hs (warp-private rows); zero-pad cols 24..31
#pragma unroll
    for (int nt = 0; nt < 3; ++nt) {
        int c0 = nt * 8 + 2 * tq;
        *reinterpret_cast<uint32_t*>(&Hs[r0][c0]) =
            pack_bf2(tanh_fast(acc[nt + 3][0]) * sigmoid_fast(acc[nt][0]),
                     tanh_fast(acc[nt + 3][1]) * sigmoid_fast(acc[nt][1]));
        *reinterpret_cast<uint32_t*>(&Hs[r1][c0]) =
            pack_bf2(tanh_fast(acc[nt + 3][2]) * sigmoid_fast(acc[nt][2]),
                     tanh_fast(acc[nt + 3][3]) * sigmoid_fast(acc[nt][3]));
    }
    *reinterpret_cast<uint32_t*>(&Hs[r0][24 + 2 * tq]) = 0u;
    *reinterpret_cast<uint32_t*>(&Hs[r1][24 + 2 * tq]) = 0u;
    __syncwarp();

    // MMA2: Hs[256x32] x Bs2t -> 24 outputs
    float acc2[3][4];
#pragma unroll
    for (int nt = 0; nt < 3; ++nt) {
        int c0 = nt * 8 + 2 * tq;
        float b0 = sb[c0], b1 = sb[c0 + 1];
        acc2[nt][0] = b0; acc2[nt][1] = b1; acc2[nt][2] = b0; acc2[nt][3] = b1;
    }
#pragma unroll
    for (int kk = 0; kk < 32; kk += 16) {
        uint32_t af[4];
        af[0] = ld_bf2(&Hs[r0][kk + 2 * tq]);
        af[1] = ld_bf2(&Hs[r1][kk + 2 * tq]);
        af[2] = ld_bf2(&Hs[r0][kk + 8 + 2 * tq]);
        af[3] = ld_bf2(&Hs[r1][kk + 8 + 2 * tq]);
        uint32_t bf[3][2];
#pragma unroll
        for (int nt = 0; nt < 3; ++nt) {
            int c0 = nt * 8 + g;
            bf[nt][0] = ld_bf2(&Bs2t[c0][kk + 2 * tq]);
            bf[nt][1] = ld_bf2(&Bs2t[c0][kk + 8 + 2 * tq]);
        }
#pragma unroll
        for (int nt = 0; nt < 3; ++nt)
            mma_bf16(acc2[nt], af, bf[nt]);
    }

    // Store (bf16 pairs)
#pragma unroll
    for (int nt = 0; nt < 3; ++nt) {
        int col = nt * 8 + 2 * tq;
        int ta = t0 + r0;
        if (ta < Lout)
            *reinterpret_cast<uint32_t*>(outp + ((size_t)b * LMAX + ta) * 24 + col) =
                pack_bf2(acc2[nt][0], acc2[nt][1]);
        int tb = t0 + r1;
        if (tb < Lout)
            *reinterpret_cast<uint32_t*>(outp + ((size_t)b * LMAX + tb) * 24 + col) =
                pack_bf2(acc2[nt][2], acc2[nt][3]);
    }
}

// ---------------------------------------------------------------------------
// K4a: act128 = relu(resW conv of (prev[t+256] + out[t])). bf16 in/out.
// ---------------------------------------------------------------------------
__global__ __launch_bounds__(256) void k_resrelu(const float* __restrict__ resW,
                                                 const float* __restrict__ resb) {
    const int b  = blockIdx.y;
    const int t0 = blockIdx.x * 64;
    const int tid = threadIdx.x;
    const int og = tid & 31;
    const int tg = tid >> 5;

    __shared__ float s_in[64][25];
    for (int idx = tid; idx < 64 * 24; idx += 256) {
        int r = idx / 24, c = idx % 24;
        size_t prow = (size_t)b * LMAX + 256 + t0 + r;
        size_t orow = (size_t)b * LMAX + t0 + r;
        s_in[r][c] = __bfloat162float(g_bufA[prow * 24 + c]) +
                     __bfloat162float(g_bufB[orow * 24 + c]);
    }
    __syncthreads();

    const float4 bb = reinterpret_cast<const float4*>(resb)[og];
    float acc[8][4];
#pragma unroll
    for (int rr = 0; rr < 8; ++rr) {
        acc[rr][0] = bb.x; acc[rr][1] = bb.y; acc[rr][2] = bb.z; acc[rr][3] = bb.w;
    }
#pragma unroll 4
    for (int c = 0; c < 24; ++c) {
        float4 w = reinterpret_cast<const float4*>(resW)[c * 32 + og];
#pragma unroll
        for (int rr = 0; rr < 8; ++rr) {
            float xin = s_in[tg * 8 + rr][c];
            acc[rr][0] += xin * w.x; acc[rr][1] += xin * w.y;
            acc[rr][2] += xin * w.z; acc[rr][3] += xin * w.w;
        }
    }
#pragma unroll
    for (int rr = 0; rr < 8; ++rr) {
        int row = t0 + tg * 8 + rr;
        __nv_bfloat16* dst = g_act128 + ((size_t)b * TOUT + row) * 128 + og * 4;
        *reinterpret_cast<uint32_t*>(dst) =
            pack_bf2(fmaxf(acc[rr][0], 0.f), fmaxf(acc[rr][1], 0.f));
        *reinterpret_cast<uint32_t*>(dst + 2) =
            pack_bf2(fmaxf(acc[rr][2], 0.f), fmaxf(acc[rr][3], 0.f));
    }
}

// ---------------------------------------------------------------------------
// K4b: act256 = relu(act128 @ f1W + f1b). bf16 GEMM, whole K=128 in smem.
// ---------------------------------------------------------------------------
__global__ __launch_bounds__(256) void k_gemm_relu(const float* __restrict__ f1b) {
    const int t0 = blockIdx.x * 128;
    const int o0 = blockIdx.y * 128;
    const int b  = blockIdx.z;
    const int tid  = threadIdx.x;
    const int warp = tid >> 5, lane = tid & 31;
    const int m_off = (warp >> 2) * 64;
    const int n_off = (warp & 3) * 32;
    const int g  = lane >> 2;
    const int tq = lane & 3;

    __shared__ __align__(16) __nv_bfloat16 As[128][136];
    __shared__ __align__(16) __nv_bfloat16 Bs[128][136];

#pragma unroll
    for (int q = 0; q < 8; ++q) {
        int idx = tid + q * 256;
        int r = idx >> 4, u = idx & 15;
        *reinterpret_cast<uint4*>(&As[r][u * 8]) =
            *reinterpret_cast<const uint4*>(g_act128 + ((size_t)b * TOUT + t0 + r) * 128 + u * 8);
        *reinterpret_cast<uint4*>(&Bs[r][u * 8]) =
            *reinterpret_cast<const uint4*>(g_f1t + (size_t)(o0 + r) * 128 + u * 8);
    }
    __syncthreads();

    float acc[4][4][4];
#pragma unroll
    for (int mt = 0; mt < 4; ++mt)
#pragma unroll
        for (int nt = 0; nt < 4; ++nt)
#pragma unroll
            for (int q = 0; q < 4; ++q) acc[mt][nt][q] = 0.0f;

#pragma unroll
    for (int kk = 0; kk < 128; kk += 16) {
        uint32_t af[4][4];
#pragma unroll
        for (int mt = 0; mt < 4; ++mt) {
            int r0 = m_off + mt * 16 + g;
            af[mt][0] = ld_bf2(&As[r0][kk + 2 * tq]);
            af[mt][1] = ld_bf2(&As[r0 + 8][kk + 2 * tq]);
            af[mt][2] = ld_bf2(&As[r0][kk + 8 + 2 * tq]);
            af[mt][3] = ld_bf2(&As[r0 + 8][kk + 8 + 2 * tq]);
        }
        uint32_t bf[4][2];
#pragma unroll
        for (int nt = 0; nt < 4; ++nt) {
            int c0 = n_off + nt * 8 + g;
            bf[nt][0] = ld_bf2(&Bs[c0][kk + 2 * tq]);
            bf[nt][1] = ld_bf2(&Bs[c0][kk + 8 + 2 * tq]);
        }
#pragma unroll
        for (int mt = 0; mt < 4; ++mt)
#pragma unroll
            for (int nt = 0; nt < 4; ++nt)
                mma_bf16(acc[mt][nt], af[mt], bf[nt]);
    }

#pragma unroll
    for (int nt = 0; nt < 4; ++nt) {
        const int col = o0 + n_off + nt * 8 + 2 * tq;
        const float2 bias = *reinterpret_cast<const float2*>(f1b + col);
#pragma unroll
        for (int mt = 0; mt < 4; ++mt) {
            int row = t0 + m_off + mt * 16 + g;
            *reinterpret_cast<uint32_t*>(g_act256 + ((size_t)b * TOUT + row) * 256 + col) =
                pack_bf2(fmaxf(acc[mt][nt][0] + bias.x, 0.f),
                         fmaxf(acc[mt][nt][1] + bias.y, 0.f));
            *reinterpret_cast<uint32_t*>(g_act256 + ((size_t)b * TOUT + row + 8) * 256 + col) =
                pack_bf2(fmaxf(acc[mt][nt][2] + bias.x, 0.f),
                         fmaxf(acc[mt][nt][3] + bias.y, 0.f));
        }
    }
}

// ---------------------------------------------------------------------------
// K4c: y = softmax(act256 @ f2W + f2b). bf16 GEMM, M tile 64, full N=256.
// ---------------------------------------------------------------------------
__global__ __launch_bounds__(256) void k_gemm_softmax(const float* __restrict__ f2b,
                                                      float* __restrict__ y) {
    const int t0 = blockIdx.x * 64;
    const int b  = blockIdx.y;
    const int tid  = threadIdx.x;
    const int warp = tid >> 5, lane = tid & 31;
    const int mw = warp >> 2;
    const int nw = warp & 3;
    const int m_off = mw * 32;
    const int n_off = nw * 64;
    const int g  = lane >> 2;
    const int tq = lane & 3;

    __shared__ __align__(16) __nv_bfloat16 As[64][264];
    __shared__ __align__(16) __nv_bfloat16 Bs[256][40];
    __shared__ float red1[64][4];
    __shared__ float red2[64][4];

#pragma unroll
    for (int q = 0; q < 8; ++q) {
        int idx = tid + q * 256;
        int r = idx >> 5, u = idx & 31;
        *reinterpret_cast<uint4*>(&As[r][u * 8]) =
            *reinterpret_cast<const uint4*>(g_act256 + ((size_t)b * TOUT + t0 + r) * 256 + u * 8);
    }

    float acc[2][8][4];
#pragma unroll
    for (int mt = 0; mt < 2; ++mt)
#pragma unroll
        for (int nt = 0; nt < 8; ++nt)
#pragma unroll
            for (int q = 0; q < 4; ++q) acc[mt][nt][q] = 0.0f;

    for (int k0 = 0; k0 < 256; k0 += 32) {
        __syncthreads();
#pragma unroll
        for (int q = 0; q < 4; ++q) {
            int idx = tid + q * 256;
            int r = idx >> 2, c8 = idx & 3;
            *reinterpret_cast<uint4*>(&Bs[r][c8 * 8]) =
                *reinterpret_cast<const uint4*>(g_f2t + (size_t)r * 256 + k0 + c8 * 8);
        }
        __syncthreads();
#pragma unroll
        for (int kk = 0; kk < 32; kk += 16) {
            uint32_t af[2][4];
#pragma unroll
            for (int mt = 0; mt < 2; ++mt) {
                int r0 = m_off + mt * 16 + g;
                af[mt][0] = ld_bf2(&As[r0][k0 + kk + 2 * tq]);
                af[mt][1] = ld_bf2(&As[r0 + 8][k0 + kk + 2 * tq]);
                af[mt][2] = ld_bf2(&As[r0][k0 + kk + 8 + 2 * tq]);
                af[mt][3] = ld_bf2(&As[r0 + 8][k0 + kk + 8 + 2 * tq]);
            }
            uint32_t bf[8][2];
#pragma unroll
            for (int nt = 0; nt < 8; ++nt) {
                int c0 = n_off + nt * 8 + g;
                bf[nt][0] = ld_bf2(&Bs[c0][kk + 2 * tq]);
                bf[nt][1] = ld_bf2(&Bs[c0][kk + 8 + 2 * tq]);
            }
#pragma unroll
            for (int mt = 0; mt < 2; ++mt)
#pragma unroll
                for (int nt = 0; nt < 8; ++nt)
                    mma_bf16(acc[mt][nt], af[mt], bf[nt]);
        }
    }

#pragma unroll
    for (int nt = 0; nt < 8; ++nt) {
        const int col = n_off + nt * 8 + 2 * tq;
        const float2 bias = *reinterpret_cast<const float2*>(f2b + col);
#pragma unroll
        for (int mt = 0; mt < 2; ++mt) {
            acc[mt][nt][0] += bias.x; acc[mt][nt][1] += bias.y;
            acc[mt][nt][2] += bias.x; acc[mt][nt][3] += bias.y;
        }
    }

    float rmax[2][2];
#pragma unroll
    for (int mt = 0; mt < 2; ++mt)
#pragma unroll
        for (int rr = 0; rr < 2; ++rr) {
            float m = -1e30f;
#pragma unroll
            for (int nt = 0; nt < 8; ++nt) {
                m = fmaxf(m, acc[mt][nt][rr * 2 + 0]);
                m = fmaxf(m, acc[mt][nt][rr * 2 + 1]);
            }
            m = fmaxf(m, __shfl_xor_sync(0xffffffffu, m, 1));
            m = fmaxf(m, __shfl_xor_sync(0xffffffffu, m, 2));
            rmax[mt][rr] = m;
            if (tq == 0) red1[m_off + mt * 16 + rr * 8 + g][nw] = m;
        }
    __syncthreads();
#pragma unroll
    for (int mt = 0; mt < 2; ++mt)
#pragma unroll
        for (int rr = 0; rr < 2; ++rr) {
            int r = m_off + mt * 16 + rr * 8 + g;
            rmax[mt][rr] = fmaxf(fmaxf(red1[r][0], red1[r][1]),
                                 fmaxf(red1[r][2], red1[r][3]));
        }

    float rsum[2][2];
#pragma unroll
    for (int mt = 0; mt < 2; ++mt)
#pragma unroll
        for (int rr = 0; rr < 2; ++rr) {
            float s = 0.f;
#pragma unroll
            for (int nt = 0; nt < 8; ++nt) {
                float e0 = __expf(acc[mt][nt][rr * 2 + 0] - rmax[mt][rr]);
                float e1 = __expf(acc[mt][nt][rr * 2 + 1] - rmax[mt][rr]);
                acc[mt][nt][rr * 2 + 0] = e0;
                acc[mt][nt][rr * 2 + 1] = e1;
                s += e0 + e1;
            }
            s += __shfl_xor_sync(0xffffffffu, s, 1);
            s += __shfl_xor_sync(0xffffffffu, s, 2);
            rsum[mt][rr] = s;
            if (tq == 0) red2[m_off + mt * 16 + rr * 8 + g][nw] = s;
        }
    __syncthreads();
#pragma unroll
    for (int mt = 0; mt < 2; ++mt)
#pragma unroll
        for (int rr = 0; rr < 2; ++rr) {
            int r = m_off + mt * 16 + rr * 8 + g;
            rsum[mt][rr] = __fdividef(1.0f, red2[r][0] + red2[r][1] + red2[r][2] + red2[r][3]);
        }

#pragma unroll
    for (int nt = 0; nt < 8; ++nt) {
        const int col = n_off + nt * 8 + 2 * tq;
#pragma unroll
        for (int mt = 0; mt < 2; ++mt) {
            int row = t0 + m_off + mt * 16 + g;
            float2 v0 = make_float2(acc[mt][nt][0] * rsum[mt][0],
                                    acc[mt][nt][1] * rsum[mt][0]);
            float2 v1 = make_float2(acc[mt][nt][2] * rsum[mt][1],
                                    acc[mt][nt][3] * rsum[mt][1]);
            *reinterpret_cast<float2*>(y + ((size_t)b * TOUT + row) * 256 + col) = v0;
            *reinterpret_cast<float2*>(y + ((size_t)b * TOUT + row + 8) * 256 + col) = v1;
        }
    }
}

// ---------------------------------------------------------------------------
extern "C" void kernel_launch(void* const* d_in, const int* in_sizes, int n_in,
                              void* d_out, int out_size) {
    const float* x     = (const float*)d_in[0];
    const float* cW    = (const float*)d_in[1];
    const float* cb    = (const float*)d_in[2];
    const float* gW0   = (const float*)d_in[3];
    const float* gb0   = (const float*)d_in[4];
    const float* fW0   = (const float*)d_in[5];
    const float* fb0   = (const float*)d_in[6];
    const float* sW0   = (const float*)d_in[7];
    const float* sb0   = (const float*)d_in[8];
    const float* gateW = (const float*)d_in[9];
    const float* gateB = (const float*)d_in[10];
    const float* filtW = (const float*)d_in[11];
    const float* filtB = (const float*)d_in[12];
    const float* scW   = (const float*)d_in[13];
    const float* scB   = (const float*)d_in[14];
    const float* resW  = (const float*)d_in[15];
    const float* resB  = (const float*)d_in[16];
    const float* f1W   = (const float*)d_in[17];
    const float* f1b   = (const float*)d_in[18];
    const float* f2W   = (const float*)d_in[19];
    const float* f2b   = (const float*)d_in[20];
    float* out = (float*)d_out;

    k_prep_x<<<4096, 256>>>(x);
    k_prep_w<<<256, 256>>>(cW, gW0, fW0, f1W, f2W);

    k_causal_mma<<<dim3(128, 2, BATCH), 256>>>(cb);
    k_gated0_mma<<<dim3(128, BATCH), 256>>>(gb0, fb0, sW0, sb0);

    int L = L0;
    for (int i = 0; i < 9; ++i) {
        int d = 2 << i;          // 2,4,...,512
        int Lout = L - d;
        int nb = (Lout + 255) / 256;
        // Only the LAST residual conv contributes to the output (acc is
        // overwritten each iteration in the reference), so res convs 0..7 are skipped.
        k_dilated_mma<<<dim3(nb, BATCH), 512>>>(gateW + i * 1152, gateB + i * 24,
                                                filtW + i * 1152, filtB + i * 24,
                                                scW + i * 576, scB + i * 24,
                                                d, Lout, i & 1);
        L = Lout;
    }
    // prev (input of layer i=8) lives in g_bufA (len 15872); its output in g_bufB (15360)
    k_resrelu<<<dim3(TOUT / 64, BATCH), 256>>>(resW + 8 * 24 * 128, resB + 8 * 128);
    k_gemm_relu<<<dim3(TOUT / 128, 2, BATCH), 256>>>(f1b);
    k_gemm_softmax<<<dim3(TOUT / 64, BATCH), 256>>>(f2b, out);
}

// round 11
// speedup vs baseline: 5.2430x; 1.0853x over previous
#include <cuda_runtime.h>
#include <cuda_bf16.h>
#include <cstdint>
#include <cstddef>

#define BATCH 8
#define TLEN  16384
#define CIN   256
#define T1    16383   // causal conv output length
#define L0    16382   // gated0 output length
#define LMAX  16382   // per-batch row stride for 24-ch buffers
#define TOUT  15360

// Scratch (static device globals: allocation-free per harness rules)
__device__ __nv_bfloat16 g_xb[(size_t)BATCH * TLEN * CIN];      // 67 MB (x in bf16)
__device__ __nv_bfloat16 g_bufA[(size_t)BATCH * LMAX * 24];     // 6.3 MB
__device__ __nv_bfloat16 g_bufB[(size_t)BATCH * LMAX * 24];     // 6.3 MB
__device__ __nv_bfloat16 g_act128[(size_t)BATCH * TOUT * 128];  // 31 MB
__device__ __nv_bfloat16 g_act256[(size_t)BATCH * TOUT * 256];  // 63 MB
// Composed causal+gated0 weights: [n][k], n<24 gate / n>=24 filter, k = tap*256+i
__device__ __nv_bfloat16 g_gf3t[48 * 768];
__device__ float         g_eb[48];
// Pre-converted, transposed bf16 weights: [n][k] layout for mma B-frags
__device__ __nv_bfloat16 g_f1t[256 * 128];
__device__ __nv_bfloat16 g_f2t[256 * 256];

__device__ __forceinline__ float tanh_fast(float x) {
    float y;
    asm("tanh.approx.f32 %0, %1;" : "=f"(y) : "f"(x));
    return y;
}
__device__ __forceinline__ float sigmoid_fast(float x) {
    return __fdividef(1.0f, 1.0f + __expf(-x));
}
__device__ __forceinline__ uint32_t pack_bf2(float a, float b) {
    __nv_bfloat162 t = __float22bfloat162_rn(make_float2(a, b));
    return *reinterpret_cast<uint32_t*>(&t);
}

__device__ __forceinline__ void mma_bf16(float c[4], const uint32_t a[4], const uint32_t b[2]) {
    asm volatile(
        "mma.sync.aligned.m16n8k16.row.col.f32.bf16.bf16.f32 "
        "{%0,%1,%2,%3}, {%4,%5,%6,%7}, {%8,%9}, {%0,%1,%2,%3};"
        : "+f"(c[0]), "+f"(c[1]), "+f"(c[2]), "+f"(c[3])
        : "r"(a[0]), "r"(a[1]), "r"(a[2]), "r"(a[3]), "r"(b[0]), "r"(b[1]));
}

__device__ __forceinline__ uint32_t ld_bf2(const __nv_bfloat16* p) {
    return *reinterpret_cast<const uint32_t*>(p);
}

__device__ __forceinline__ void cp16(uint32_t smem_dst, const void* gsrc) {
    asm volatile("cp.async.ca.shared.global [%0], [%1], 16;" :: "r"(smem_dst), "l"(gsrc));
}
__device__ __forceinline__ void cp_commit() {
    asm volatile("cp.async.commit_group;" ::: "memory");
}
__device__ __forceinline__ void cp_wait_all() {
    asm volatile("cp.async.wait_group 0;" ::: "memory");
}

// ---------------------------------------------------------------------------
// Prep: x -> bf16
// ---------------------------------------------------------------------------
__global__ void k_prep_x(const float* __restrict__ x) {
    const size_t n4 = (size_t)BATCH * TLEN * CIN / 4;
    for (size_t i = blockIdx.x * blockDim.x + threadIdx.x; i < n4;
         i += (size_t)gridDim.x * blockDim.x) {
        float4 v = reinterpret_cast<const float4*>(x)[i];
        uint2 u;
        u.x = pack_bf2(v.x, v.y);
        u.y = pack_bf2(v.z, v.w);
        reinterpret_cast<uint2*>(g_xb)[i] = u;
    }
}

// ---------------------------------------------------------------------------
// Prep: remaining weights -> bf16 transposed [n][k]
// ---------------------------------------------------------------------------
__global__ void k_prep_w(const float* __restrict__ f1W,
                         const float* __restrict__ f2W) {
    const int stride = gridDim.x * blockDim.x;
    const int tid = blockIdx.x * blockDim.x + threadIdx.x;
    for (int idx = tid; idx < 256 * 128; idx += stride) {
        int o = idx >> 7, k = idx & 127;
        g_f1t[idx] = __float2bfloat16(f1W[k * 256 + o]);
    }
    for (int idx = tid; idx < 256 * 256; idx += stride) {
        int o = idx >> 8, k = idx & 255;
        g_f2t[idx] = __float2bfloat16(f2W[k * 256 + o]);
    }
}

// ---------------------------------------------------------------------------
// Prep: compose causal conv (K=2, 256->256) with gated0's g/f convs (K=2,
// 256->24 each) into one K=3 conv from x (256 -> 48), fp32 accumulate.
// g_gf3t[n][tap*256+i] = sum_{k1+k2=tap} sum_c cW[k1,i,c] * W[k2,c,n']
// g_eb[n] = b[n'] + sum_c cb[c] * (W[0,c,n'] + W[1,c,n'])
// ---------------------------------------------------------------------------
__global__ void k_prep_compose(const float* __restrict__ cW,
                               const float* __restrict__ cb,
                               const float* __restrict__ gW0,
                               const float* __restrict__ gb0,
                               const float* __restrict__ fW0,
                               const float* __restrict__ fb0) {
    const int tid = blockIdx.x * blockDim.x + threadIdx.x;
    const int stride = gridDim.x * blockDim.x;
    for (int idx = tid; idx < 48 * 768; idx += stride) {
        int n = idx / 768, k = idx % 768;
        int tap = k >> 8, i = k & 255;
        const float* W = (n < 24) ? gW0 : fW0;
        int o = (n < 24) ? n : n - 24;
        float s = 0.f;
        int k1lo = (tap > 1) ? tap - 1 : 0;
        int k1hi = (tap < 1) ? tap : 1;
        for (int k1 = k1lo; k1 <= k1hi; ++k1) {
            int k2 = tap - k1;
            const float* cwp = cW + k1 * 65536 + i * 256;
            const float* wp  = W + k2 * 6144 + o;
#pragma unroll 4
            for (int c = 0; c < 256; ++c)
                s += cwp[c] * wp[c * 24];
        }
        g_gf3t[idx] = __float2bfloat16(s);
    }
    if (tid < 48) {
        const float* W  = (tid < 24) ? gW0 : fW0;
        const float* bb = (tid < 24) ? gb0 : fb0;
        int o = (tid < 24) ? tid : tid - 24;
        float s = bb[o];
        for (int c = 0; c < 256; ++c)
            s += cb[c] * (W[c * 24 + o] + W[6144 + c * 24 + o]);
        g_eb[tid] = s;
    }
}

// ---------------------------------------------------------------------------
// K2: gated0 DIRECT from x. bf16 GEMM: A[t,k]=xb[t+(k>>8), k&255] (K=768),
// B = composed [gW|fW] (N=48, whole B in smem). cp.async double-buffered A.
// Epilogue: gate nonlinearity + 24x24 1x1 as second bf16 MMA. -> bf16 g_bufA.
// ---------------------------------------------------------------------------
__global__ __launch_bounds__(256) void k_gated0_direct(const float* __restrict__ sW,
                                                       const float* __restrict__ sb) {
    const int t0 = blockIdx.x * 128;
    const int b  = blockIdx.y;
    const int tid  = threadIdx.x;
    const int warp = tid >> 5, lane = tid & 31;
    const int m_off = warp * 16;
    const int g  = lane >> 2;
    const int tq = lane & 3;

    __shared__ __align__(16) __nv_bfloat16 sGF[48][776];   // [n][k=768], pad 8
    __shared__ __align__(16) __nv_bfloat16 As[2][128][40];
    __shared__ __align__(16) __nv_bfloat16 Hs[128][32];    // K padded to 32
    __shared__ __align__(16) __nv_bfloat16 Bs2t[24][40];   // [o][c], c padded to 32
    const uint32_t as_base = (uint32_t)__cvta_generic_to_shared(&As[0][0][0]);

    // full composed B into smem (48 x 768 bf16 = 4608 uint4)
#pragma unroll
    for (int q = 0; q < 18; ++q) {
        int idx = tid + q * 256;
        int n = idx / 96, u = idx % 96;
        *reinterpret_cast<uint4*>(&sGF[n][u * 8]) =
            *reinterpret_cast<const uint4*>(g_gf3t + (size_t)n * 768 + u * 8);
    }
    // Bs2t[o][c] = sW[c*24+o]; pad c 24..31 with zeros
    for (int idx = tid; idx < 24 * 32; idx += 256) {
        int o = idx >> 5, c = idx & 31;
        Bs2t[o][c] = (c < 24) ? __float2bfloat16(sW[c * 24 + o]) : __float2bfloat16(0.f);
    }

#define GD_LOAD(chunk, s) do {                                                  \
    int tap = (chunk) >> 3; int ch = ((chunk) & 7) * 32;                        \
    _Pragma("unroll")                                                            \
    for (int q = 0; q < 2; ++q) {                                                \
        int idx = tid + q * 256;                                                 \
        int r = idx >> 2, c8 = idx & 3;                                          \
        int row = t0 + r + tap; if (row > TLEN - 1) row = TLEN - 1;              \
        cp16(as_base + (uint32_t)((((s) * 128 + r) * 40 + c8 * 8) * 2),          \
             g_xb + ((size_t)b * TLEN + row) * CIN + ch + c8 * 8);               \
    }                                                                            \
} while (0)

    float acc[6][4];
#pragma unroll
    for (int nt = 0; nt < 6; ++nt) {
        int c0 = nt * 8 + 2 * tq;
        float b0 = g_eb[c0], b1 = g_eb[c0 + 1];
        acc[nt][0] = b0; acc[nt][1] = b1; acc[nt][2] = b0; acc[nt][3] = b1;
    }

    GD_LOAD(0, 0);
    cp_commit();

    for (int c = 0; c < 24; ++c) {
        const int s = c & 1;
        const int k0 = c * 32;
        cp_wait_all();
        __syncthreads();
        if (c < 23) { GD_LOAD(c + 1, s ^ 1); cp_commit(); }
#pragma unroll
        for (int kk = 0; kk < 32; kk += 16) {
            uint32_t af[4];
            af[0] = ld_bf2(&As[s][m_off + g][kk + 2 * tq]);
            af[1] = ld_bf2(&As[s][m_off + g + 8][kk + 2 * tq]);
            af[2] = ld_bf2(&As[s][m_off + g][kk + 8 + 2 * tq]);
            af[3] = ld_bf2(&As[s][m_off + g + 8][kk + 8 + 2 * tq]);
            uint32_t bf[6][2];
#pragma unroll
            for (int nt = 0; nt < 6; ++nt) {
                int c0 = nt * 8 + g;
                bf[nt][0] = ld_bf2(&sGF[c0][k0 + kk + 2 * tq]);
                bf[nt][1] = ld_bf2(&sGF[c0][k0 + kk + 8 + 2 * tq]);
            }
#pragma unroll
            for (int nt = 0; nt < 6; ++nt)
                mma_bf16(acc[nt], af, bf[nt]);
        }
        __syncthreads();
    }
#undef GD_LOAD

    // Nonlinearity -> Hs (bf16, warp-private rows); zero-pad cols 24..31
    const int r0 = m_off + g, r1 = r0 + 8;
#pragma unroll
    for (int nt = 0; nt < 3; ++nt) {
        int c0 = nt * 8 + 2 * tq;
        *reinterpret_cast<uint32_t*>(&Hs[r0][c0]) =
            pack_bf2(tanh_fast(acc[nt + 3][0]) * sigmoid_fast(acc[nt][0]),
                     tanh_fast(acc[nt + 3][1]) * sigmoid_fast(acc[nt][1]));
        *reinterpret_cast<uint32_t*>(&Hs[r1][c0]) =
            pack_bf2(tanh_fast(acc[nt + 3][2]) * sigmoid_fast(acc[nt][2]),
                     tanh_fast(acc[nt + 3][3]) * sigmoid_fast(acc[nt][3]));
    }
    *reinterpret_cast<uint32_t*>(&Hs[r0][24 + 2 * tq]) = 0u;
    *reinterpret_cast<uint32_t*>(&Hs[r1][24 + 2 * tq]) = 0u;
    __syncwarp();

    // MMA2: Hs[128x32] x Bs2t (24 outputs), K=32
    float acc2[3][4];
#pragma unroll
    for (int nt = 0; nt < 3; ++nt) {
        int c0 = nt * 8 + 2 * tq;
        float b0 = sb[c0], b1 = sb[c0 + 1];
        acc2[nt][0] = b0; acc2[nt][1] = b1; acc2[nt][2] = b0; acc2[nt][3] = b1;
    }
#pragma unroll
    for (int kk = 0; kk < 32; kk += 16) {
        uint32_t af[4];
        af[0] = ld_bf2(&Hs[r0][kk + 2 * tq]);
        af[1] = ld_bf2(&Hs[r1][kk + 2 * tq]);
        af[2] = ld_bf2(&Hs[r0][kk + 8 + 2 * tq]);
        af[3] = ld_bf2(&Hs[r1][kk + 8 + 2 * tq]);
        uint32_t bf[3][2];
#pragma unroll
        for (int nt = 0; nt < 3; ++nt) {
            int c0 = nt * 8 + g;
            bf[nt][0] = ld_bf2(&Bs2t[c0][kk + 2 * tq]);
            bf[nt][1] = ld_bf2(&Bs2t[c0][kk + 8 + 2 * tq]);
        }
#pragma unroll
        for (int nt = 0; nt < 3; ++nt)
            mma_bf16(acc2[nt], af, bf[nt]);
    }

#pragma unroll
    for (int nt = 0; nt < 3; ++nt) {
        int col = nt * 8 + 2 * tq;
        int ta = t0 + r0;
        if (ta < L0)
            *reinterpret_cast<uint32_t*>(g_bufA + ((size_t)b * LMAX + ta) * 24 + col) =
                pack_bf2(acc2[nt][0], acc2[nt][1]);
        int tb = t0 + r1;
        if (tb < L0)
            *reinterpret_cast<uint32_t*>(g_bufA + ((size_t)b * LMAX + tb) * 24 + col) =
                pack_bf2(acc2[nt][2], acc2[nt][3]);
    }
}

// ---------------------------------------------------------------------------
// K3: dilated gated layer, bf16 MMA end-to-end. 512 threads, 256 rows/block.
// ---------------------------------------------------------------------------
__global__ __launch_bounds__(512) void k_dilated_mma(const float* __restrict__ gW,
                                                     const float* __restrict__ gb,
                                                     const float* __restrict__ fW,
                                                     const float* __restrict__ fb,
                                                     const float* __restrict__ sW,
                                                     const float* __restrict__ sb,
                                                     int d, int Lout, int dir) {
    const __nv_bfloat16* in = dir ? g_bufB : g_bufA;
    __nv_bfloat16*     outp = dir ? g_bufA : g_bufB;
    const int b  = blockIdx.y;
    const int t0 = blockIdx.x * 256;
    const int tid = threadIdx.x;
    const int warp = tid >> 5, lane = tid & 31;
    const int m_off = warp * 16;    // 16 warps x 16 rows = 256 rows
    const int g  = lane >> 2;
    const int tq = lane & 3;

    __shared__ __align__(16) __nv_bfloat16 As[256][56];    // [m][k=48], pad 8
    __shared__ __align__(16) __nv_bfloat16 Bs1t[48][56];   // [n][k=48]
    __shared__ __align__(16) __nv_bfloat16 Hs[256][32];    // K padded to 32
    __shared__ __align__(16) __nv_bfloat16 Bs2t[24][40];   // [o][c=32]

    const int Lin = Lout + d;
    // A tile: one (row, tap) task per thread: r = tid>>1, tap = tid&1.
    {
        const int r    = tid >> 1;
        const int tap  = tid & 1;
        const int row  = t0 + r + (tap ? d : 0);
        const bool ok  = row < Lin;
        const __nv_bfloat16* src = in + ((size_t)b * LMAX + row) * 24;
        const int cbase = tap * 24;
        if (ok) {
#pragma unroll
            for (int j = 0; j < 3; ++j)
                *reinterpret_cast<uint4*>(&As[r][cbase + j * 8]) =
                    *reinterpret_cast<const uint4*>(src + j * 8);
        } else {
            uint4 z = make_uint4(0, 0, 0, 0);
#pragma unroll
            for (int j = 0; j < 3; ++j)
                *reinterpret_cast<uint4*>(&As[r][cbase + j * 8]) = z;
        }
    }
    // B1t[n][k]: k = tap*24+ci ; n<24 gate, n>=24 filter
    for (int idx = tid; idx < 48 * 48; idx += 512) {
        int n = idx / 48, k = idx % 48;
        int tap = k / 24, ci = k % 24;
        float w = (n < 24) ? gW[tap * 576 + ci * 24 + n]
                           : fW[tap * 576 + ci * 24 + (n - 24)];
        Bs1t[n][k] = __float2bfloat16(w);
    }
    // Bs2t[o][c] = sW[c*24+o], zero-padded c 24..31
    for (int idx = tid; idx < 24 * 32; idx += 512) {
        int o = idx >> 5, c = idx & 31;
        Bs2t[o][c] = (c < 24) ? __float2bfloat16(sW[c * 24 + o]) : __float2bfloat16(0.f);
    }
    __syncthreads();

    // MMA1: A[256x48] x B1t -> N=48 (gate|filter), K=48 (3 k16 steps)
    float acc[6][4];
#pragma unroll
    for (int nt = 0; nt < 6; ++nt) {
        int c0 = (nt < 3) ? (nt * 8 + 2 * tq) : ((nt - 3) * 8 + 2 * tq);
        float b0 = (nt < 3) ? gb[c0] : fb[c0];
        float b1 = (nt < 3) ? gb[c0 + 1] : fb[c0 + 1];
        acc[nt][0] = b0; acc[nt][1] = b1; acc[nt][2] = b0; acc[nt][3] = b1;
    }
    const int r0 = m_off + g, r1 = r0 + 8;
#pragma unroll
    for (int kk = 0; kk < 48; kk += 16) {
        uint32_t af[4];
        af[0] = ld_bf2(&As[r0][kk + 2 * tq]);
        af[1] = ld_bf2(&As[r1][kk + 2 * tq]);
        af[2] = ld_bf2(&As[r0][kk + 8 + 2 * tq]);
        af[3] = ld_bf2(&As[r1][kk + 8 + 2 * tq]);
        uint32_t bf[6][2];
#pragma unroll
        for (int nt = 0; nt < 6; ++nt) {
            int c0 = nt * 8 + g;
            bf[nt][0] = ld_bf2(&Bs1t[c0][kk + 2 * tq]);
            bf[nt][1] = ld_bf2(&Bs1t[c0][kk + 8 + 2 * tq]);
        }
#pragma unroll
        for (int nt = 0; nt < 6; ++nt)
            mma_bf16(acc[nt], af, bf[nt]);
    }

    // Nonlinearity -> Hs (warp-private rows); zero-pad cols 24..31
#pragma unroll
    for (int nt = 0; nt < 3; ++nt) {
        int c0 = nt * 8 + 2 * tq;
        *reinterpret_cast<uint32_t*>(&Hs[r0][c0]) =
            pack_bf2(tanh_fast(acc[nt + 3][0]) * sigmoid_fast(acc[nt][0]),
                     tanh_fast(acc[nt + 3][1]) * sigmoid_fast(acc[nt][1]));
        *reinterpret_cast<uint32_t*>(&Hs[r1][c0]) =
            pack_bf2(tanh_fast(acc[nt + 3][2]) * sigmoid_fast(acc[nt][2]),
                     tanh_fast(acc[nt + 3][3]) * sigmoid_fast(acc[nt][3]));
    }
    *reinterpret_cast<uint32_t*>(&Hs[r0][24 + 2 * tq]) = 0u;
    *reinterpret_cast<uint32_t*>(&Hs[r1][24 + 2 * tq]) = 0u;
    __syncwarp();

    // MMA2: Hs[256x32] x Bs2t -> 24 outputs
    float acc2[3][4];
#pragma unroll
    for (int nt = 0; nt < 3; ++nt) {
        int c0 = nt * 8 + 2 * tq;
        float b0 = sb[c0], b1 = sb[c0 + 1];
        acc2[nt][0] = b0; acc2[nt][1] = b1; acc2[nt][2] = b0; acc2[nt][3] = b1;
    }
#pragma unroll
    for (int kk = 0; kk < 32; kk += 16) {
        uint32_t af[4];
        af[0] = ld_bf2(&Hs[r0][kk + 2 * tq]);
        af[1] = ld_bf2(&Hs[r1][kk + 2 * tq]);
        af[2] = ld_bf2(&Hs[r0][kk + 8 + 2 * tq]);
        af[3] = ld_bf2(&Hs[r1][kk + 8 + 2 * tq]);
        uint32_t bf[3][2];
#pragma unroll
        for (int nt = 0; nt < 3; ++nt) {
            int c0 = nt * 8 + g;
            bf[nt][0] = ld_bf2(&Bs2t[c0][kk + 2 * tq]);
            bf[nt][1] = ld_bf2(&Bs2t[c0][kk + 8 + 2 * tq]);
        }
#pragma unroll
        for (int nt = 0; nt < 3; ++nt)
            mma_bf16(acc2[nt], af, bf[nt]);
    }

    // Store (bf16 pairs)
#pragma unroll
    for (int nt = 0; nt < 3; ++nt) {
        int col = nt * 8 + 2 * tq;
        int ta = t0 + r0;
        if (ta < Lout)
            *reinterpret_cast<uint32_t*>(outp + ((size_t)b * LMAX + ta) * 24 + col) =
                pack_bf2(acc2[nt][0], acc2[nt][1]);
        int tb = t0 + r1;
        if (tb < Lout)
            *reinterpret_cast<uint32_t*>(outp + ((size_t)b * LMAX + tb) * 24 + col) =
                pack_bf2(acc2[nt][2], acc2[nt][3]);
    }
}

// ---------------------------------------------------------------------------
// K4a: act128 = relu(resW conv of (prev[t+256] + out[t])). bf16 in/out.
// ---------------------------------------------------------------------------
__global__ __launch_bounds__(256) void k_resrelu(const float* __restrict__ resW,
                                                 const float* __restrict__ resb) {
    const int b  = blockIdx.y;
    const int t0 = blockIdx.x * 64;
    const int tid = threadIdx.x;
    const int og = tid & 31;
    const int tg = tid >> 5;

    __shared__ float s_in[64][25];
    for (int idx = tid; idx < 64 * 24; idx += 256) {
        int r = idx / 24, c = idx % 24;
        size_t prow = (size_t)b * LMAX + 256 + t0 + r;
        size_t orow = (size_t)b * LMAX + t0 + r;
        s_in[r][c] = __bfloat162float(g_bufA[prow * 24 + c]) +
                     __bfloat162float(g_bufB[orow * 24 + c]);
    }
    __syncthreads();

    const float4 bb = reinterpret_cast<const float4*>(resb)[og];
    float acc[8][4];
#pragma unroll
    for (int rr = 0; rr < 8; ++rr) {
        acc[rr][0] = bb.x; acc[rr][1] = bb.y; acc[rr][2] = bb.z; acc[rr][3] = bb.w;
    }
#pragma unroll 4
    for (int c = 0; c < 24; ++c) {
        float4 w = reinterpret_cast<const float4*>(resW)[c * 32 + og];
#pragma unroll
        for (int rr = 0; rr < 8; ++rr) {
            float xin = s_in[tg * 8 + rr][c];
            acc[rr][0] += xin * w.x; acc[rr][1] += xin * w.y;
            acc[rr][2] += xin * w.z; acc[rr][3] += xin * w.w;
        }
    }
#pragma unroll
    for (int rr = 0; rr < 8; ++rr) {
        int row = t0 + tg * 8 + rr;
        __nv_bfloat16* dst = g_act128 + ((size_t)b * TOUT + row) * 128 + og * 4;
        *reinterpret_cast<uint32_t*>(dst) =
            pack_bf2(fmaxf(acc[rr][0], 0.f), fmaxf(acc[rr][1], 0.f));
        *reinterpret_cast<uint32_t*>(dst + 2) =
            pack_bf2(fmaxf(acc[rr][2], 0.f), fmaxf(acc[rr][3], 0.f));
    }
}

// ---------------------------------------------------------------------------
// K4b: act256 = relu(act128 @ f1W + f1b). bf16 GEMM, whole K=128 in smem.
// ---------------------------------------------------------------------------
__global__ __launch_bounds__(256) void k_gemm_relu(const float* __restrict__ f1b) {
    const int t0 = blockIdx.x * 128;
    const int o0 = blockIdx.y * 128;
    const int b  = blockIdx.z;
    const int tid  = threadIdx.x;
    const int warp = tid >> 5, lane = tid & 31;
    const int m_off = (warp >> 2) * 64;
    const int n_off = (warp & 3) * 32;
    const int g  = lane >> 2;
    const int tq = lane & 3;

    __shared__ __align__(16) __nv_bfloat16 As[128][136];
    __shared__ __align__(16) __nv_bfloat16 Bs[128][136];

#pragma unroll
    for (int q = 0; q < 8; ++q) {
        int idx = tid + q * 256;
        int r = idx >> 4, u = idx & 15;
        *reinterpret_cast<uint4*>(&As[r][u * 8]) =
            *reinterpret_cast<const uint4*>(g_act128 + ((size_t)b * TOUT + t0 + r) * 128 + u * 8);
        *reinterpret_cast<uint4*>(&Bs[r][u * 8]) =
            *reinterpret_cast<const uint4*>(g_f1t + (size_t)(o0 + r) * 128 + u * 8);
    }
    __syncthreads();

    float acc[4][4][4];
#pragma unroll
    for (int mt = 0; mt < 4; ++mt)
#pragma unroll
        for (int nt = 0; nt < 4; ++nt)
#pragma unroll
            for (int q = 0; q < 4; ++q) acc[mt][nt][q] = 0.0f;

#pragma unroll
    for (int kk = 0; kk < 128; kk += 16) {
        uint32_t af[4][4];
#pragma unroll
        for (int mt = 0; mt < 4; ++mt) {
            int r0 = m_off + mt * 16 + g;
            af[mt][0] = ld_bf2(&As[r0][kk + 2 * tq]);
            af[mt][1] = ld_bf2(&As[r0 + 8][kk + 2 * tq]);
            af[mt][2] = ld_bf2(&As[r0][kk + 8 + 2 * tq]);
            af[mt][3] = ld_bf2(&As[r0 + 8][kk + 8 + 2 * tq]);
        }
        uint32_t bf[4][2];
#pragma unroll
        for (int nt = 0; nt < 4; ++nt) {
            int c0 = n_off + nt * 8 + g;
            bf[nt][0] = ld_bf2(&Bs[c0][kk + 2 * tq]);
            bf[nt][1] = ld_bf2(&Bs[c0][kk + 8 + 2 * tq]);
        }
#pragma unroll
        for (int mt = 0; mt < 4; ++mt)
#pragma unroll
            for (int nt = 0; nt < 4; ++nt)
                mma_bf16(acc[mt][nt], af[mt], bf[nt]);
    }

#pragma unroll
    for (int nt = 0; nt < 4; ++nt) {
        const int col = o0 + n_off + nt * 8 + 2 * tq;
        const float2 bias = *reinterpret_cast<const float2*>(f1b + col);
#pragma unroll
        for (int mt = 0; mt < 4; ++mt) {
            int row = t0 + m_off + mt * 16 + g;
            *reinterpret_cast<uint32_t*>(g_act256 + ((size_t)b * TOUT + row) * 256 + col) =
                pack_bf2(fmaxf(acc[mt][nt][0] + bias.x, 0.f),
                         fmaxf(acc[mt][nt][1] + bias.y, 0.f));
            *reinterpret_cast<uint32_t*>(g_act256 + ((size_t)b * TOUT + row + 8) * 256 + col) =
                pack_bf2(fmaxf(acc[mt][nt][2] + bias.x, 0.f),
                         fmaxf(acc[mt][nt][3] + bias.y, 0.f));
        }
    }
}

// ---------------------------------------------------------------------------
// K4c: y = softmax(act256 @ f2W + f2b). bf16 GEMM, M tile 64, full N=256.
// ---------------------------------------------------------------------------
__global__ __launch_bounds__(256) void k_gemm_softmax(const float* __restrict__ f2b,
                                                      float* __restrict__ y) {
    const int t0 = blockIdx.x * 64;
    const int b  = blockIdx.y;
    const int tid  = threadIdx.x;
    const int warp = tid >> 5, lane = tid & 31;
    const int mw = warp >> 2;
    const int nw = warp & 3;
    const int m_off = mw * 32;
    const int n_off = nw * 64;
    const int g  = lane >> 2;
    const int tq = lane & 3;

    __shared__ __align__(16) __nv_bfloat16 As[64][264];
    __shared__ __align__(16) __nv_bfloat16 Bs[256][40];
    __shared__ float red1[64][4];
    __shared__ float red2[64][4];

#pragma unroll
    for (int q = 0; q < 8; ++q) {
        int idx = tid + q * 256;
        int r = idx >> 5, u = idx & 31;
        *reinterpret_cast<uint4*>(&As[r][u * 8]) =
            *reinterpret_cast<const uint4*>(g_act256 + ((size_t)b * TOUT + t0 + r) * 256 + u * 8);
    }

    float acc[2][8][4];
#pragma unroll
    for (int mt = 0; mt < 2; ++mt)
#pragma unroll
        for (int nt = 0; nt < 8; ++nt)
#pragma unroll
            for (int q = 0; q < 4; ++q) acc[mt][nt][q] = 0.0f;

    for (int k0 = 0; k0 < 256; k0 += 32) {
        __syncthreads();
#pragma unroll
        for (int q = 0; q < 4; ++q) {
            int idx = tid + q * 256;
            int r = idx >> 2, c8 = idx & 3;
            *reinterpret_cast<uint4*>(&Bs[r][c8 * 8]) =
                *reinterpret_cast<const uint4*>(g_f2t + (size_t)r * 256 + k0 + c8 * 8);
        }
        __syncthreads();
#pragma unroll
        for (int kk = 0; kk < 32; kk += 16) {
            uint32_t af[2][4];
#pragma unroll
            for (int mt = 0; mt < 2; ++mt) {
                int r0 = m_off + mt * 16 + g;
                af[mt][0] = ld_bf2(&As[r0][k0 + kk + 2 * tq]);
                af[mt][1] = ld_bf2(&As[r0 + 8][k0 + kk + 2 * tq]);
                af[mt][2] = ld_bf2(&As[r0][k0 + kk + 8 + 2 * tq]);
                af[mt][3] = ld_bf2(&As[r0 + 8][k0 + kk + 8 + 2 * tq]);
            }
            uint32_t bf[8][2];
#pragma unroll
            for (int nt = 0; nt < 8; ++nt) {
                int c0 = n_off + nt * 8 + g;
                bf[nt][0] = ld_bf2(&Bs[c0][kk + 2 * tq]);
                bf[nt][1] = ld_bf2(&Bs[c0][kk + 8 + 2 * tq]);
            }
#pragma unroll
            for (int mt = 0; mt < 2; ++mt)
#pragma unroll
                for (int nt = 0; nt < 8; ++nt)
                    mma_bf16(acc[mt][nt], af[mt], bf[nt]);
        }
    }

#pragma unroll
    for (int nt = 0; nt < 8; ++nt) {
        const int col = n_off + nt * 8 + 2 * tq;
        const float2 bias = *reinterpret_cast<const float2*>(f2b + col);
#pragma unroll
        for (int mt = 0; mt < 2; ++mt) {
            acc[mt][nt][0] += bias.x; acc[mt][nt][1] += bias.y;
            acc[mt][nt][2] += bias.x; acc[mt][nt][3] += bias.y;
        }
    }

    float rmax[2][2];
#pragma unroll
    for (int mt = 0; mt < 2; ++mt)
#pragma unroll
        for (int rr = 0; rr < 2; ++rr) {
            float m = -1e30f;
#pragma unroll
            for (int nt = 0; nt < 8; ++nt) {
                m = fmaxf(m, acc[mt][nt][rr * 2 + 0]);
                m = fmaxf(m, acc[mt][nt][rr * 2 + 1]);
            }
            m = fmaxf(m, __shfl_xor_sync(0xffffffffu, m, 1));
            m = fmaxf(m, __shfl_xor_sync(0xffffffffu, m, 2));
            rmax[mt][rr] = m;
            if (tq == 0) red1[m_off + mt * 16 + rr * 8 + g][nw] = m;
        }
    __syncthreads();
#pragma unroll
    for (int mt = 0; mt < 2; ++mt)
#pragma unroll
        for (int rr = 0; rr < 2; ++rr) {
            int r = m_off + mt * 16 + rr * 8 + g;
            rmax[mt][rr] = fmaxf(fmaxf(red1[r][0], red1[r][1]),
                                 fmaxf(red1[r][2], red1[r][3]));
        }

    float rsum[2][2];
#pragma unroll
    for (int mt = 0; mt < 2; ++mt)
#pragma unroll
        for (int rr = 0; rr < 2; ++rr) {
            float s = 0.f;
#pragma unroll
            for (int nt = 0; nt < 8; ++nt) {
                float e0 = __expf(acc[mt][nt][rr * 2 + 0] - rmax[mt][rr]);
                float e1 = __expf(acc[mt][nt][rr * 2 + 1] - rmax[mt][rr]);
                acc[mt][nt][rr * 2 + 0] = e0;
                acc[mt][nt][rr * 2 + 1] = e1;
                s += e0 + e1;
            }
            s += __shfl_xor_sync(0xffffffffu, s, 1);
            s += __shfl_xor_sync(0xffffffffu, s, 2);
            rsum[mt][rr] = s;
            if (tq == 0) red2[m_off + mt * 16 + rr * 8 + g][nw] = s;
        }
    __syncthreads();
#pragma unroll
    for (int mt = 0; mt < 2; ++mt)
#pragma unroll
        for (int rr = 0; rr < 2; ++rr) {
            int r = m_off + mt * 16 + rr * 8 + g;
            rsum[mt][rr] = __fdividef(1.0f, red2[r][0] + red2[r][1] + red2[r][2] + red2[r][3]);
        }

#pragma unroll
    for (int nt = 0; nt < 8; ++nt) {
        const int col = n_off + nt * 8 + 2 * tq;
#pragma unroll
        for (int mt = 0; mt < 2; ++mt) {
            int row = t0 + m_off + mt * 16 + g;
            float2 v0 = make_float2(acc[mt][nt][0] * rsum[mt][0],
                                    acc[mt][nt][1] * rsum[mt][0]);
            float2 v1 = make_float2(acc[mt][nt][2] * rsum[mt][1],
                                    acc[mt][nt][3] * rsum[mt][1]);
            *reinterpret_cast<float2*>(y + ((size_t)b * TOUT + row) * 256 + col) = v0;
            *reinterpret_cast<float2*>(y + ((size_t)b * TOUT + row + 8) * 256 + col) = v1;
        }
    }
}

// ---------------------------------------------------------------------------
extern "C" void kernel_launch(void* const* d_in, const int* in_sizes, int n_in,
                              void* d_out, int out_size) {
    const float* x     = (const float*)d_in[0];
    const float* cW    = (const float*)d_in[1];
    const float* cb    = (const float*)d_in[2];
    const float* gW0   = (const float*)d_in[3];
    const float* gb0   = (const float*)d_in[4];
    const float* fW0   = (const float*)d_in[5];
    const float* fb0   = (const float*)d_in[6];
    const float* sW0   = (const float*)d_in[7];
    const float* sb0   = (const float*)d_in[8];
    const float* gateW = (const float*)d_in[9];
    const float* gateB = (const float*)d_in[10];
    const float* filtW = (const float*)d_in[11];
    const float* filtB = (const float*)d_in[12];
    const float* scW   = (const float*)d_in[13];
    const float* scB   = (const float*)d_in[14];
    const float* resW  = (const float*)d_in[15];
    const float* resB  = (const float*)d_in[16];
    const float* f1W   = (const float*)d_in[17];
    const float* f1b   = (const float*)d_in[18];
    const float* f2W   = (const float*)d_in[19];
    const float* f2b   = (const float*)d_in[20];
    float* out = (float*)d_out;

    k_prep_x<<<4096, 256>>>(x);
    k_prep_w<<<128, 256>>>(f1W, f2W);
    k_prep_compose<<<144, 256>>>(cW, cb, gW0, gb0, fW0, fb0);

    // causal conv + gated0 g/f convs composed into one K=3 conv from x
    k_gated0_direct<<<dim3(128, BATCH), 256>>>(sW0, sb0);

    int L = L0;
    for (int i = 0; i < 9; ++i) {
        int d = 2 << i;          // 2,4,...,512
        int Lout = L - d;
        int nb = (Lout + 255) / 256;
        // Only the LAST residual conv contributes to the output (acc is
        // overwritten each iteration in the reference), so res convs 0..7 are skipped.
        k_dilated_mma<<<dim3(nb, BATCH), 512>>>(gateW + i * 1152, gateB + i * 24,
                                                filtW + i * 1152, filtB + i * 24,
                                                scW + i * 576, scB + i * 24,
                                                d, Lout, i & 1);
        L = Lout;
    }
    // prev (input of layer i=8) lives in g_bufA (len 15872); its output in g_bufB (15360)
    k_resrelu<<<dim3(TOUT / 64, BATCH), 256>>>(resW + 8 * 24 * 128, resB + 8 * 128);
    k_gemm_relu<<<dim3(TOUT / 128, 2, BATCH), 256>>>(f1b);
    k_gemm_softmax<<<dim3(TOUT / 64, BATCH), 256>>>(f2b, out);
}

// round 12
// speedup vs baseline: 5.4904x; 1.0472x over previous
#include <cuda_runtime.h>
#include <cuda_bf16.h>
#include <cstdint>
#include <cstddef>

#define BATCH 8
#define TLEN  16384
#define CIN   256
#define T1    16383   // causal conv output length
#define L0    16382   // gated0 output length
#define LMAX  16382   // per-batch row stride for 24-ch buffers
#define TOUT  15360

// Scratch (static device globals: allocation-free per harness rules)
__device__ __nv_bfloat16 g_xb[(size_t)BATCH * TLEN * CIN];      // 67 MB (x in bf16)
__device__ __nv_bfloat16 g_bufA[(size_t)BATCH * LMAX * 24];     // 6.3 MB
__device__ __nv_bfloat16 g_bufB[(size_t)BATCH * LMAX * 24];     // 6.3 MB
__device__ __nv_bfloat16 g_act128[(size_t)BATCH * TOUT * 128];  // 31 MB
__device__ __nv_bfloat16 g_act256[(size_t)BATCH * TOUT * 256];  // 63 MB
// Composed causal+gated0 weights: [n][k], n<24 gate / n>=24 filter, k = tap*256+i
__device__ __nv_bfloat16 g_gf3t[48 * 768];
__device__ float         g_eb[48];
// Pre-converted, transposed bf16 weights: [n][k] layout for mma B-frags
__device__ __nv_bfloat16 g_f1t[256 * 128];
__device__ __nv_bfloat16 g_f2t[256 * 256];

__device__ __forceinline__ float tanh_fast(float x) {
    float y;
    asm("tanh.approx.f32 %0, %1;" : "=f"(y) : "f"(x));
    return y;
}
__device__ __forceinline__ float sigmoid_fast(float x) {
    return __fdividef(1.0f, 1.0f + __expf(-x));
}
__device__ __forceinline__ uint32_t pack_bf2(float a, float b) {
    __nv_bfloat162 t = __float22bfloat162_rn(make_float2(a, b));
    return *reinterpret_cast<uint32_t*>(&t);
}

__device__ __forceinline__ void mma_bf16(float c[4], const uint32_t a[4], const uint32_t b[2]) {
    asm volatile(
        "mma.sync.aligned.m16n8k16.row.col.f32.bf16.bf16.f32 "
        "{%0,%1,%2,%3}, {%4,%5,%6,%7}, {%8,%9}, {%0,%1,%2,%3};"
        : "+f"(c[0]), "+f"(c[1]), "+f"(c[2]), "+f"(c[3])
        : "r"(a[0]), "r"(a[1]), "r"(a[2]), "r"(a[3]), "r"(b[0]), "r"(b[1]));
}

__device__ __forceinline__ uint32_t ld_bf2(const __nv_bfloat16* p) {
    return *reinterpret_cast<const uint32_t*>(p);
}

__device__ __forceinline__ void cp16(uint32_t smem_dst, const void* gsrc) {
    asm volatile("cp.async.ca.shared.global [%0], [%1], 16;" :: "r"(smem_dst), "l"(gsrc));
}
__device__ __forceinline__ void cp_commit() {
    asm volatile("cp.async.commit_group;" ::: "memory");
}
__device__ __forceinline__ void cp_wait_all() {
    asm volatile("cp.async.wait_group 0;" ::: "memory");
}

// ---------------------------------------------------------------------------
// Prep: x -> bf16
// ---------------------------------------------------------------------------
__global__ void k_prep_x(const float* __restrict__ x) {
    const size_t n4 = (size_t)BATCH * TLEN * CIN / 4;
    for (size_t i = blockIdx.x * blockDim.x + threadIdx.x; i < n4;
         i += (size_t)gridDim.x * blockDim.x) {
        float4 v = reinterpret_cast<const float4*>(x)[i];
        uint2 u;
        u.x = pack_bf2(v.x, v.y);
        u.y = pack_bf2(v.z, v.w);
        reinterpret_cast<uint2*>(g_xb)[i] = u;
    }
}

// ---------------------------------------------------------------------------
// Prep: remaining weights -> bf16 transposed [n][k]
// ---------------------------------------------------------------------------
__global__ void k_prep_w(const float* __restrict__ f1W,
                         const float* __restrict__ f2W) {
    const int stride = gridDim.x * blockDim.x;
    const int tid = blockIdx.x * blockDim.x + threadIdx.x;
    for (int idx = tid; idx < 256 * 128; idx += stride) {
        int o = idx >> 7, k = idx & 127;
        g_f1t[idx] = __float2bfloat16(f1W[k * 256 + o]);
    }
    for (int idx = tid; idx < 256 * 256; idx += stride) {
        int o = idx >> 8, k = idx & 255;
        g_f2t[idx] = __float2bfloat16(f2W[k * 256 + o]);
    }
}

// ---------------------------------------------------------------------------
// Prep: compose causal conv (K=2, 256->256) with gated0's g/f convs (K=2,
// 256->24 each) into one K=3 conv from x (256 -> 48), fp32 accumulate.
// ---------------------------------------------------------------------------
__global__ void k_prep_compose(const float* __restrict__ cW,
                               const float* __restrict__ cb,
                               const float* __restrict__ gW0,
                               const float* __restrict__ gb0,
                               const float* __restrict__ fW0,
                               const float* __restrict__ fb0) {
    const int tid = blockIdx.x * blockDim.x + threadIdx.x;
    const int stride = gridDim.x * blockDim.x;
    for (int idx = tid; idx < 48 * 768; idx += stride) {
        int n = idx / 768, k = idx % 768;
        int tap = k >> 8, i = k & 255;
        const float* W = (n < 24) ? gW0 : fW0;
        int o = (n < 24) ? n : n - 24;
        float s = 0.f;
        int k1lo = (tap > 1) ? tap - 1 : 0;
        int k1hi = (tap < 1) ? tap : 1;
        for (int k1 = k1lo; k1 <= k1hi; ++k1) {
            int k2 = tap - k1;
            const float* cwp = cW + k1 * 65536 + i * 256;
            const float* wp  = W + k2 * 6144 + o;
#pragma unroll 4
            for (int c = 0; c < 256; ++c)
                s += cwp[c] * wp[c * 24];
        }
        g_gf3t[idx] = __float2bfloat16(s);
    }
    if (tid < 48) {
        const float* W  = (tid < 24) ? gW0 : fW0;
        const float* bb = (tid < 24) ? gb0 : fb0;
        int o = (tid < 24) ? tid : tid - 24;
        float s = bb[o];
        for (int c = 0; c < 256; ++c)
            s += cb[c] * (W[c * 24 + o] + W[6144 + c * 24 + o]);
        g_eb[tid] = s;
    }
}

// ---------------------------------------------------------------------------
// K2: gated0 DIRECT from x, tap-reuse mainloop.
// Per channel-chunk (32 of 256): load x rows [t0, t0+129] x 32 cols ONCE,
// run 3 tap-MMAs with row-shifted A fragments against composed B columns
// tap*256+ch. 8 chunks total (vs 24), 1/3 the x traffic.
// Epilogue: gate nonlinearity + 24x24 1x1 as second bf16 MMA. -> bf16 g_bufA.
// ---------------------------------------------------------------------------
__global__ __launch_bounds__(256) void k_gated0_direct(const float* __restrict__ sW,
                                                       const float* __restrict__ sb) {
    const int t0 = blockIdx.x * 128;
    const int b  = blockIdx.y;
    const int tid  = threadIdx.x;
    const int warp = tid >> 5, lane = tid & 31;
    const int m_off = warp * 16;
    const int g  = lane >> 2;
    const int tq = lane & 3;

    __shared__ __align__(16) __nv_bfloat16 sGF[48][776];   // [n][k=768], pad 8
    __shared__ __align__(16) __nv_bfloat16 As[2][132][40]; // 130 rows used
    __shared__ __align__(16) __nv_bfloat16 Hs[128][32];    // K padded to 32
    __shared__ __align__(16) __nv_bfloat16 Bs2t[24][40];   // [o][c], c padded to 32
    const uint32_t as_base = (uint32_t)__cvta_generic_to_shared(&As[0][0][0]);

    // full composed B into smem (48 x 768 bf16 = 4608 uint4)
#pragma unroll
    for (int q = 0; q < 18; ++q) {
        int idx = tid + q * 256;
        int n = idx / 96, u = idx % 96;
        *reinterpret_cast<uint4*>(&sGF[n][u * 8]) =
            *reinterpret_cast<const uint4*>(g_gf3t + (size_t)n * 768 + u * 8);
    }
    // Bs2t[o][c] = sW[c*24+o]; pad c 24..31 with zeros
    for (int idx = tid; idx < 24 * 32; idx += 256) {
        int o = idx >> 5, c = idx & 31;
        Bs2t[o][c] = (c < 24) ? __float2bfloat16(sW[c * 24 + o]) : __float2bfloat16(0.f);
    }

    // Load 130 rows x 32 cols of x for channel chunk `ch` into buffer s.
#define GD_LOAD(chunk, s) do {                                                  \
    int ch = (chunk) * 32;                                                       \
    _Pragma("unroll")                                                            \
    for (int q = 0; q < 3; ++q) {                                                \
        int idx = tid + q * 256;                                                 \
        if (idx < 520) {                                                         \
            int r = idx >> 2, c8 = idx & 3;                                      \
            int row = t0 + r; if (row > TLEN - 1) row = TLEN - 1;                \
            cp16(as_base + (uint32_t)((((s) * 132 + r) * 40 + c8 * 8) * 2),      \
                 g_xb + ((size_t)b * TLEN + row) * CIN + ch + c8 * 8);           \
        }                                                                        \
    }                                                                            \
} while (0)

    float acc[6][4];
#pragma unroll
    for (int nt = 0; nt < 6; ++nt) {
        int c0 = nt * 8 + 2 * tq;
        float b0 = g_eb[c0], b1 = g_eb[c0 + 1];
        acc[nt][0] = b0; acc[nt][1] = b1; acc[nt][2] = b0; acc[nt][3] = b1;
    }

    GD_LOAD(0, 0);
    cp_commit();

    for (int c = 0; c < 8; ++c) {
        const int s = c & 1;
        const int ch = c * 32;
        cp_wait_all();
        __syncthreads();
        if (c < 7) { GD_LOAD(c + 1, s ^ 1); cp_commit(); }
#pragma unroll
        for (int tap = 0; tap < 3; ++tap) {
            const int kbase = tap * 256 + ch;
            const int ra = m_off + g + tap;
            const int rb = ra + 8;
#pragma unroll
            for (int kk = 0; kk < 32; kk += 16) {
                uint32_t af[4];
                af[0] = ld_bf2(&As[s][ra][kk + 2 * tq]);
                af[1] = ld_bf2(&As[s][rb][kk + 2 * tq]);
                af[2] = ld_bf2(&As[s][ra][kk + 8 + 2 * tq]);
                af[3] = ld_bf2(&As[s][rb][kk + 8 + 2 * tq]);
                uint32_t bf[6][2];
#pragma unroll
                for (int nt = 0; nt < 6; ++nt) {
                    int c0 = nt * 8 + g;
                    bf[nt][0] = ld_bf2(&sGF[c0][kbase + kk + 2 * tq]);
                    bf[nt][1] = ld_bf2(&sGF[c0][kbase + kk + 8 + 2 * tq]);
                }
#pragma unroll
                for (int nt = 0; nt < 6; ++nt)
                    mma_bf16(acc[nt], af, bf[nt]);
            }
        }
        __syncthreads();
    }
#undef GD_LOAD

    // Nonlinearity -> Hs (bf16, warp-private rows); zero-pad cols 24..31
    const int r0 = m_off + g, r1 = r0 + 8;
#pragma unroll
    for (int nt = 0; nt < 3; ++nt) {
        int c0 = nt * 8 + 2 * tq;
        *reinterpret_cast<uint32_t*>(&Hs[r0][c0]) =
            pack_bf2(tanh_fast(acc[nt + 3][0]) * sigmoid_fast(acc[nt][0]),
                     tanh_fast(acc[nt + 3][1]) * sigmoid_fast(acc[nt][1]));
        *reinterpret_cast<uint32_t*>(&Hs[r1][c0]) =
            pack_bf2(tanh_fast(acc[nt + 3][2]) * sigmoid_fast(acc[nt][2]),
                     tanh_fast(acc[nt + 3][3]) * sigmoid_fast(acc[nt][3]));
    }
    *reinterpret_cast<uint32_t*>(&Hs[r0][24 + 2 * tq]) = 0u;
    *reinterpret_cast<uint32_t*>(&Hs[r1][24 + 2 * tq]) = 0u;
    __syncwarp();

    // MMA2: Hs[128x32] x Bs2t (24 outputs), K=32
    float acc2[3][4];
#pragma unroll
    for (int nt = 0; nt < 3; ++nt) {
        int c0 = nt * 8 + 2 * tq;
        float b0 = sb[c0], b1 = sb[c0 + 1];
        acc2[nt][0] = b0; acc2[nt][1] = b1; acc2[nt][2] = b0; acc2[nt][3] = b1;
    }
#pragma unroll
    for (int kk = 0; kk < 32; kk += 16) {
        uint32_t af[4];
        af[0] = ld_bf2(&Hs[r0][kk + 2 * tq]);
        af[1] = ld_bf2(&Hs[r1][kk + 2 * tq]);
        af[2] = ld_bf2(&Hs[r0][kk + 8 + 2 * tq]);
        af[3] = ld_bf2(&Hs[r1][kk + 8 + 2 * tq]);
        uint32_t bf[3][2];
#pragma unroll
        for (int nt = 0; nt < 3; ++nt) {
            int c0 = nt * 8 + g;
            bf[nt][0] = ld_bf2(&Bs2t[c0][kk + 2 * tq]);
            bf[nt][1] = ld_bf2(&Bs2t[c0][kk + 8 + 2 * tq]);
        }
#pragma unroll
        for (int nt = 0; nt < 3; ++nt)
            mma_bf16(acc2[nt], af, bf[nt]);
    }

#pragma unroll
    for (int nt = 0; nt < 3; ++nt) {
        int col = nt * 8 + 2 * tq;
        int ta = t0 + r0;
        if (ta < L0)
            *reinterpret_cast<uint32_t*>(g_bufA + ((size_t)b * LMAX + ta) * 24 + col) =
                pack_bf2(acc2[nt][0], acc2[nt][1]);
        int tb = t0 + r1;
        if (tb < L0)
            *reinterpret_cast<uint32_t*>(g_bufA + ((size_t)b * LMAX + tb) * 24 + col) =
                pack_bf2(acc2[nt][2], acc2[nt][3]);
    }
}

// ---------------------------------------------------------------------------
// K3: dilated gated layer, bf16 MMA end-to-end. 512 threads, 256 rows/block.
// ---------------------------------------------------------------------------
__global__ __launch_bounds__(512) void k_dilated_mma(const float* __restrict__ gW,
                                                     const float* __restrict__ gb,
                                                     const float* __restrict__ fW,
                                                     const float* __restrict__ fb,
                                                     const float* __restrict__ sW,
                                                     const float* __restrict__ sb,
                                                     int d, int Lout, int dir) {
    const __nv_bfloat16* in = dir ? g_bufB : g_bufA;
    __nv_bfloat16*     outp = dir ? g_bufA : g_bufB;
    const int b  = blockIdx.y;
    const int t0 = blockIdx.x * 256;
    const int tid = threadIdx.x;
    const int warp = tid >> 5, lane = tid & 31;
    const int m_off = warp * 16;    // 16 warps x 16 rows = 256 rows
    const int g  = lane >> 2;
    const int tq = lane & 3;

    __shared__ __align__(16) __nv_bfloat16 As[256][56];    // [m][k=48], pad 8
    __shared__ __align__(16) __nv_bfloat16 Bs1t[48][56];   // [n][k=48]
    __shared__ __align__(16) __nv_bfloat16 Hs[256][32];    // K padded to 32
    __shared__ __align__(16) __nv_bfloat16 Bs2t[24][40];   // [o][c=32]

    const int Lin = Lout + d;
    // A tile: one (row, tap) task per thread: r = tid>>1, tap = tid&1.
    {
        const int r    = tid >> 1;
        const int tap  = tid & 1;
        const int row  = t0 + r + (tap ? d : 0);
        const bool ok  = row < Lin;
        const __nv_bfloat16* src = in + ((size_t)b * LMAX + row) * 24;
        const int cbase = tap * 24;
        if (ok) {
#pragma unroll
            for (int j = 0; j < 3; ++j)
                *reinterpret_cast<uint4*>(&As[r][cbase + j * 8]) =
                    *reinterpret_cast<const uint4*>(src + j * 8);
        } else {
            uint4 z = make_uint4(0, 0, 0, 0);
#pragma unroll
            for (int j = 0; j < 3; ++j)
                *reinterpret_cast<uint4*>(&As[r][cbase + j * 8]) = z;
        }
    }
    // B1t[n][k]: k = tap*24+ci ; n<24 gate, n>=24 filter
    for (int idx = tid; idx < 48 * 48; idx += 512) {
        int n = idx / 48, k = idx % 48;
        int tap = k / 24, ci = k % 24;
        float w = (n < 24) ? gW[tap * 576 + ci * 24 + n]
                           : fW[tap * 576 + ci * 24 + (n - 24)];
        Bs1t[n][k] = __float2bfloat16(w);
    }
    // Bs2t[o][c] = sW[c*24+o], zero-padded c 24..31
    for (int idx = tid; idx < 24 * 32; idx += 512) {
        int o = idx >> 5, c = idx & 31;
        Bs2t[o][c] = (c < 24) ? __float2bfloat16(sW[c * 24 + o]) : __float2bfloat16(0.f);
    }
    __syncthreads();

    // MMA1: A[256x48] x B1t -> N=48 (gate|filter), K=48 (3 k16 steps)
    float acc[6][4];
#pragma unroll
    for (int nt = 0; nt < 6; ++nt) {
        int c0 = (nt < 3) ? (nt * 8 + 2 * tq) : ((nt - 3) * 8 + 2 * tq);
        float b0 = (nt < 3) ? gb[c0] : fb[c0];
        float b1 = (nt < 3) ? gb[c0 + 1] : fb[c0 + 1];
        acc[nt][0] = b0; acc[nt][1] = b1; acc[nt][2] = b0; acc[nt][3] = b1;
    }
    const int r0 = m_off + g, r1 = r0 + 8;
#pragma unroll
    for (int kk = 0; kk < 48; kk += 16) {
        uint32_t af[4];
        af[0] = ld_bf2(&As[r0][kk + 2 * tq]);
        af[1] = ld_bf2(&As[r1][kk + 2 * tq]);
        af[2] = ld_bf2(&As[r0][kk + 8 + 2 * tq]);
        af[3] = ld_bf2(&As[r1][kk + 8 + 2 * tq]);
        uint32_t bf[6][2];
#pragma unroll
        for (int nt = 0; nt < 6; ++nt) {
            int c0 = nt * 8 + g;
            bf[nt][0] = ld_bf2(&Bs1t[c0][kk + 2 * tq]);
            bf[nt][1] = ld_bf2(&Bs1t[c0][kk + 8 + 2 * tq]);
        }
#pragma unroll
        for (int nt = 0; nt < 6; ++nt)
            mma_bf16(acc[nt], af, bf[nt]);
    }

    // Nonlinearity -> Hs (warp-private rows); zero-pad cols 24..31
#pragma unroll
    for (int nt = 0; nt < 3; ++nt) {
        int c0 = nt * 8 + 2 * tq;
        *reinterpret_cast<uint32_t*>(&Hs[r0][c0]) =
            pack_bf2(tanh_fast(acc[nt + 3][0]) * sigmoid_fast(acc[nt][0]),
                     tanh_fast(acc[nt + 3][1]) * sigmoid_fast(acc[nt][1]));
        *reinterpret_cast<uint32_t*>(&Hs[r1][c0]) =
            pack_bf2(tanh_fast(acc[nt + 3][2]) * sigmoid_fast(acc[nt][2]),
                     tanh_fast(acc[nt + 3][3]) * sigmoid_fast(acc[nt][3]));
    }
    *reinterpret_cast<uint32_t*>(&Hs[r0][24 + 2 * tq]) = 0u;
    *reinterpret_cast<uint32_t*>(&Hs[r1][24 + 2 * tq]) = 0u;
    __syncwarp();

    // MMA2: Hs[256x32] x Bs2t -> 24 outputs
    float acc2[3][4];
#pragma unroll
    for (int nt = 0; nt < 3; ++nt) {
        int c0 = nt * 8 + 2 * tq;
        float b0 = sb[c0], b1 = sb[c0 + 1];
        acc2[nt][0] = b0; acc2[nt][1] = b1; acc2[nt][2] = b0; acc2[nt][3] = b1;
    }
#pragma unroll
    for (int kk = 0; kk < 32; kk += 16) {
        uint32_t af[4];
        af[0] = ld_bf2(&Hs[r0][kk + 2 * tq]);
        af[1] = ld_bf2(&Hs[r1][kk + 2 * tq]);
        af[2] = ld_bf2(&Hs[r0][kk + 8 + 2 * tq]);
        af[3] = ld_bf2(&Hs[r1][kk + 8 + 2 * tq]);
        uint32_t bf[3][2];
#pragma unroll
        for (int nt = 0; nt < 3; ++nt) {
            int c0 = nt * 8 + g;
            bf[nt][0] = ld_bf2(&Bs2t[c0][kk + 2 * tq]);
            bf[nt][1] = ld_bf2(&Bs2t[c0][kk + 8 + 2 * tq]);
        }
#pragma unroll
        for (int nt = 0; nt < 3; ++nt)
            mma_bf16(acc2[nt], af, bf[nt]);
    }

    // Store (bf16 pairs)
#pragma unroll
    for (int nt = 0; nt < 3; ++nt) {
        int col = nt * 8 + 2 * tq;
        int ta = t0 + r0;
        if (ta < Lout)
            *reinterpret_cast<uint32_t*>(outp + ((size_t)b * LMAX + ta) * 24 + col) =
                pack_bf2(acc2[nt][0], acc2[nt][1]);
        int tb = t0 + r1;
        if (tb < Lout)
            *reinterpret_cast<uint32_t*>(outp + ((size_t)b * LMAX + tb) * 24 + col) =
                pack_bf2(acc2[nt][2], acc2[nt][3]);
    }
}

// ---------------------------------------------------------------------------
// K4a: act128 = relu(resW conv of (prev[t+256] + out[t])). bf16 in/out.
// ---------------------------------------------------------------------------
__global__ __launch_bounds__(256) void k_resrelu(const float* __restrict__ resW,
                                                 const float* __restrict__ resb) {
    const int b  = blockIdx.y;
    const int t0 = blockIdx.x * 64;
    const int tid = threadIdx.x;
    const int og = tid & 31;
    const int tg = tid >> 5;

    __shared__ float s_in[64][25];
    for (int idx = tid; idx < 64 * 24; idx += 256) {
        int r = idx / 24, c = idx % 24;
        size_t prow = (size_t)b * LMAX + 256 + t0 + r;
        size_t orow = (size_t)b * LMAX + t0 + r;
        s_in[r][c] = __bfloat162float(g_bufA[prow * 24 + c]) +
                     __bfloat162float(g_bufB[orow * 24 + c]);
    }
    __syncthreads();

    const float4 bb = reinterpret_cast<const float4*>(resb)[og];
    float acc[8][4];
#pragma unroll
    for (int rr = 0; rr < 8; ++rr) {
        acc[rr][0] = bb.x; acc[rr][1] = bb.y; acc[rr][2] = bb.z; acc[rr][3] = bb.w;
    }
#pragma unroll 4
    for (int c = 0; c < 24; ++c) {
        float4 w = reinterpret_cast<const float4*>(resW)[c * 32 + og];
#pragma unroll
        for (int rr = 0; rr < 8; ++rr) {
            float xin = s_in[tg * 8 + rr][c];
            acc[rr][0] += xin * w.x; acc[rr][1] += xin * w.y;
            acc[rr][2] += xin * w.z; acc[rr][3] += xin * w.w;
        }
    }
#pragma unroll
    for (int rr = 0; rr < 8; ++rr) {
        int row = t0 + tg * 8 + rr;
        __nv_bfloat16* dst = g_act128 + ((size_t)b * TOUT + row) * 128 + og * 4;
        *reinterpret_cast<uint32_t*>(dst) =
            pack_bf2(fmaxf(acc[rr][0], 0.f), fmaxf(acc[rr][1], 0.f));
        *reinterpret_cast<uint32_t*>(dst + 2) =
            pack_bf2(fmaxf(acc[rr][2], 0.f), fmaxf(acc[rr][3], 0.f));
    }
}

// ---------------------------------------------------------------------------
// K4b: act256 = relu(act128 @ f1W + f1b). bf16 GEMM, whole K=128 in smem.
// ---------------------------------------------------------------------------
__global__ __launch_bounds__(256) void k_gemm_relu(const float* __restrict__ f1b) {
    const int t0 = blockIdx.x * 128;
    const int o0 = blockIdx.y * 128;
    const int b  = blockIdx.z;
    const int tid  = threadIdx.x;
    const int warp = tid >> 5, lane = tid & 31;
    const int m_off = (warp >> 2) * 64;
    const int n_off = (warp & 3) * 32;
    const int g  = lane >> 2;
    const int tq = lane & 3;

    __shared__ __align__(16) __nv_bfloat16 As[128][136];
    __shared__ __align__(16) __nv_bfloat16 Bs[128][136];

#pragma unroll
    for (int q = 0; q < 8; ++q) {
        int idx = tid + q * 256;
        int r = idx >> 4, u = idx & 15;
        *reinterpret_cast<uint4*>(&As[r][u * 8]) =
            *reinterpret_cast<const uint4*>(g_act128 + ((size_t)b * TOUT + t0 + r) * 128 + u * 8);
        *reinterpret_cast<uint4*>(&Bs[r][u * 8]) =
            *reinterpret_cast<const uint4*>(g_f1t + (size_t)(o0 + r) * 128 + u * 8);
    }
    __syncthreads();

    float acc[4][4][4];
#pragma unroll
    for (int mt = 0; mt < 4; ++mt)
#pragma unroll
        for (int nt = 0; nt < 4; ++nt)
#pragma unroll
            for (int q = 0; q < 4; ++q) acc[mt][nt][q] = 0.0f;

#pragma unroll
    for (int kk = 0; kk < 128; kk += 16) {
        uint32_t af[4][4];
#pragma unroll
        for (int mt = 0; mt < 4; ++mt) {
            int r0 = m_off + mt * 16 + g;
            af[mt][0] = ld_bf2(&As[r0][kk + 2 * tq]);
            af[mt][1] = ld_bf2(&As[r0 + 8][kk + 2 * tq]);
            af[mt][2] = ld_bf2(&As[r0][kk + 8 + 2 * tq]);
            af[mt][3] = ld_bf2(&As[r0 + 8][kk + 8 + 2 * tq]);
        }
        uint32_t bf[4][2];
#pragma unroll
        for (int nt = 0; nt < 4; ++nt) {
            int c0 = n_off + nt * 8 + g;
            bf[nt][0] = ld_bf2(&Bs[c0][kk + 2 * tq]);
            bf[nt][1] = ld_bf2(&Bs[c0][kk + 8 + 2 * tq]);
        }
#pragma unroll
        for (int mt = 0; mt < 4; ++mt)
#pragma unroll
            for (int nt = 0; nt < 4; ++nt)
                mma_bf16(acc[mt][nt], af[mt], bf[nt]);
    }

#pragma unroll
    for (int nt = 0; nt < 4; ++nt) {
        const int col = o0 + n_off + nt * 8 + 2 * tq;
        const float2 bias = *reinterpret_cast<const float2*>(f1b + col);
#pragma unroll
        for (int mt = 0; mt < 4; ++mt) {
            int row = t0 + m_off + mt * 16 + g;
            *reinterpret_cast<uint32_t*>(g_act256 + ((size_t)b * TOUT + row) * 256 + col) =
                pack_bf2(fmaxf(acc[mt][nt][0] + bias.x, 0.f),
                         fmaxf(acc[mt][nt][1] + bias.y, 0.f));
            *reinterpret_cast<uint32_t*>(g_act256 + ((size_t)b * TOUT + row + 8) * 256 + col) =
                pack_bf2(fmaxf(acc[mt][nt][2] + bias.x, 0.f),
                         fmaxf(acc[mt][nt][3] + bias.y, 0.f));
        }
    }
}

// ---------------------------------------------------------------------------
// K4c: y = softmax(act256 @ f2W + f2b). bf16 GEMM, M tile 64, full N=256.
// ---------------------------------------------------------------------------
__global__ __launch_bounds__(256) void k_gemm_softmax(const float* __restrict__ f2b,
                                                      float* __restrict__ y) {
    const int t0 = blockIdx.x * 64;
    const int b  = blockIdx.y;
    const int tid  = threadIdx.x;
    const int warp = tid >> 5, lane = tid & 31;
    const int mw = warp >> 2;
    const int nw = warp & 3;
    const int m_off = mw * 32;
    const int n_off = nw * 64;
    const int g  = lane >> 2;
    const int tq = lane & 3;

    __shared__ __align__(16) __nv_bfloat16 As[64][264];
    __shared__ __align__(16) __nv_bfloat16 Bs[256][40];
    __shared__ float red1[64][4];
    __shared__ float red2[64][4];

#pragma unroll
    for (int q = 0; q < 8; ++q) {
        int idx = tid + q * 256;
        int r = idx >> 5, u = idx & 31;
        *reinterpret_cast<uint4*>(&As[r][u * 8]) =
            *reinterpret_cast<const uint4*>(g_act256 + ((size_t)b * TOUT + t0 + r) * 256 + u * 8);
    }

    float acc[2][8][4];
#pragma unroll
    for (int mt = 0; mt < 2; ++mt)
#pragma unroll
        for (int nt = 0; nt < 8; ++nt)
#pragma unroll
            for (int q = 0; q < 4; ++q) acc[mt][nt][q] = 0.0f;

    for (int k0 = 0; k0 < 256; k0 += 32) {
        __syncthreads();
#pragma unroll
        for (int q = 0; q < 4; ++q) {
            int idx = tid + q * 256;
            int r = idx >> 2, c8 = idx & 3;
            *reinterpret_cast<uint4*>(&Bs[r][c8 * 8]) =
                *reinterpret_cast<const uint4*>(g_f2t + (size_t)r * 256 + k0 + c8 * 8);
        }
        __syncthreads();
#pragma unroll
        for (int kk = 0; kk < 32; kk += 16) {
            uint32_t af[2][4];
#pragma unroll
            for (int mt = 0; mt < 2; ++mt) {
                int r0 = m_off + mt * 16 + g;
                af[mt][0] = ld_bf2(&As[r0][k0 + kk + 2 * tq]);
                af[mt][1] = ld_bf2(&As[r0 + 8][k0 + kk + 2 * tq]);
                af[mt][2] = ld_bf2(&As[r0][k0 + kk + 8 + 2 * tq]);
                af[mt][3] = ld_bf2(&As[r0 + 8][k0 + kk + 8 + 2 * tq]);
            }
            uint32_t bf[8][2];
#pragma unroll
            for (int nt = 0; nt < 8; ++nt) {
                int c0 = n_off + nt * 8 + g;
                bf[nt][0] = ld_bf2(&Bs[c0][kk + 2 * tq]);
                bf[nt][1] = ld_bf2(&Bs[c0][kk + 8 + 2 * tq]);
            }
#pragma unroll
            for (int mt = 0; mt < 2; ++mt)
#pragma unroll
                for (int nt = 0; nt < 8; ++nt)
                    mma_bf16(acc[mt][nt], af[mt], bf[nt]);
        }
    }

#pragma unroll
    for (int nt = 0; nt < 8; ++nt) {
        const int col = n_off + nt * 8 + 2 * tq;
        const float2 bias = *reinterpret_cast<const float2*>(f2b + col);
#pragma unroll
        for (int mt = 0; mt < 2; ++mt) {
            acc[mt][nt][0] += bias.x; acc[mt][nt][1] += bias.y;
            acc[mt][nt][2] += bias.x; acc[mt][nt][3] += bias.y;
        }
    }

    float rmax[2][2];
#pragma unroll
    for (int mt = 0; mt < 2; ++mt)
#pragma unroll
        for (int rr = 0; rr < 2; ++rr) {
            float m = -1e30f;
#pragma unroll
            for (int nt = 0; nt < 8; ++nt) {
                m = fmaxf(m, acc[mt][nt][rr * 2 + 0]);
                m = fmaxf(m, acc[mt][nt][rr * 2 + 1]);
            }
            m = fmaxf(m, __shfl_xor_sync(0xffffffffu, m, 1));
            m = fmaxf(m, __shfl_xor_sync(0xffffffffu, m, 2));
            rmax[mt][rr] = m;
            if (tq == 0) red1[m_off + mt * 16 + rr * 8 + g][nw] = m;
        }
    __syncthreads();
#pragma unroll
    for (int mt = 0; mt < 2; ++mt)
#pragma unroll
        for (int rr = 0; rr < 2; ++rr) {
            int r = m_off + mt * 16 + rr * 8 + g;
            rmax[mt][rr] = fmaxf(fmaxf(red1[r][0], red1[r][1]),
                                 fmaxf(red1[r][2], red1[r][3]));
        }

    float rsum[2][2];
#pragma unroll
    for (int mt = 0; mt < 2; ++mt)
#pragma unroll
        for (int rr = 0; rr < 2; ++rr) {
            float s = 0.f;
#pragma unroll
            for (int nt = 0; nt < 8; ++nt) {
                float e0 = __expf(acc[mt][nt][rr * 2 + 0] - rmax[mt][rr]);
                float e1 = __expf(acc[mt][nt][rr * 2 + 1] - rmax[mt][rr]);
                acc[mt][nt][rr * 2 + 0] = e0;
                acc[mt][nt][rr * 2 + 1] = e1;
                s += e0 + e1;
            }
            s += __shfl_xor_sync(0xffffffffu, s, 1);
            s += __shfl_xor_sync(0xffffffffu, s, 2);
            rsum[mt][rr] = s;
            if (tq == 0) red2[m_off + mt * 16 + rr * 8 + g][nw] = s;
        }
    __syncthreads();
#pragma unroll
    for (int mt = 0; mt < 2; ++mt)
#pragma unroll
        for (int rr = 0; rr < 2; ++rr) {
            int r = m_off + mt * 16 + rr * 8 + g;
            rsum[mt][rr] = __fdividef(1.0f, red2[r][0] + red2[r][1] + red2[r][2] + red2[r][3]);
        }

#pragma unroll
    for (int nt = 0; nt < 8; ++nt) {
        const int col = n_off + nt * 8 + 2 * tq;
#pragma unroll
        for (int mt = 0; mt < 2; ++mt) {
            int row = t0 + m_off + mt * 16 + g;
            float2 v0 = make_float2(acc[mt][nt][0] * rsum[mt][0],
                                    acc[mt][nt][1] * rsum[mt][0]);
            float2 v1 = make_float2(acc[mt][nt][2] * rsum[mt][1],
                                    acc[mt][nt][3] * rsum[mt][1]);
            *reinterpret_cast<float2*>(y + ((size_t)b * TOUT + row) * 256 + col) = v0;
            *reinterpret_cast<float2*>(y + ((size_t)b * TOUT + row + 8) * 256 + col) = v1;
        }
    }
}

// ---------------------------------------------------------------------------
extern "C" void kernel_launch(void* const* d_in, const int* in_sizes, int n_in,
                              void* d_out, int out_size) {
    const float* x     = (const float*)d_in[0];
    const float* cW    = (const float*)d_in[1];
    const float* cb    = (const float*)d_in[2];
    const float* gW0   = (const float*)d_in[3];
    const float* gb0   = (const float*)d_in[4];
    const float* fW0   = (const float*)d_in[5];
    const float* fb0   = (const float*)d_in[6];
    const float* sW0   = (const float*)d_in[7];
    const float* sb0   = (const float*)d_in[8];
    const float* gateW = (const float*)d_in[9];
    const float* gateB = (const float*)d_in[10];
    const float* filtW = (const float*)d_in[11];
    const float* filtB = (const float*)d_in[12];
    const float* scW   = (const float*)d_in[13];
    const float* scB   = (const float*)d_in[14];
    const float* resW  = (const float*)d_in[15];
    const float* resB  = (const float*)d_in[16];
    const float* f1W   = (const float*)d_in[17];
    const float* f1b   = (const float*)d_in[18];
    const float* f2W   = (const float*)d_in[19];
    const float* f2b   = (const float*)d_in[20];
    float* out = (float*)d_out;

    k_prep_x<<<4096, 256>>>(x);
    k_prep_w<<<128, 256>>>(f1W, f2W);
    k_prep_compose<<<144, 256>>>(cW, cb, gW0, gb0, fW0, fb0);

    // causal conv + gated0 g/f convs composed into one K=3 conv from x
    k_gated0_direct<<<dim3(128, BATCH), 256>>>(sW0, sb0);

    int L = L0;
    for (int i = 0; i < 9; ++i) {
        int d = 2 << i;          // 2,4,...,512
        int Lout = L - d;
        int nb = (Lout + 255) / 256;
        // Only the LAST residual conv contributes to the output (acc is
        // overwritten each iteration in the reference), so res convs 0..7 are skipped.
        k_dilated_mma<<<dim3(nb, BATCH), 512>>>(gateW + i * 1152, gateB + i * 24,
                                                filtW + i * 1152, filtB + i * 24,
                                                scW + i * 576, scB + i * 24,
                                                d, Lout, i & 1);
        L = Lout;
    }
    // prev (input of layer i=8) lives in g_bufA (len 15872); its output in g_bufB (15360)
    k_resrelu<<<dim3(TOUT / 64, BATCH), 256>>>(resW + 8 * 24 * 128, resB + 8 * 128);
    k_gemm_relu<<<dim3(TOUT / 128, 2, BATCH), 256>>>(f1b);
    k_gemm_softmax<<<dim3(TOUT / 64, BATCH), 256>>>(f2b, out);
}

// round 13
// speedup vs baseline: 5.7513x; 1.0475x over previous
#include <cuda_runtime.h>
#include <cuda_bf16.h>
#include <cstdint>
#include <cstddef>

#define BATCH 8
#define TLEN  16384
#define CIN   256
#define T1    16383   // causal conv output length
#define L0    16382   // gated0 output length
#define LMAX  16382   // per-batch row stride for 24-ch buffers
#define TOUT  15360

// Scratch (static device globals: allocation-free per harness rules)
__device__ __nv_bfloat16 g_xb[(size_t)BATCH * TLEN * CIN];      // 67 MB (x in bf16)
__device__ __nv_bfloat16 g_bufA[(size_t)BATCH * LMAX * 24];     // 6.3 MB
__device__ __nv_bfloat16 g_bufB[(size_t)BATCH * LMAX * 24];     // 6.3 MB
__device__ __nv_bfloat16 g_act128[(size_t)BATCH * TOUT * 128];  // 31 MB
__device__ __nv_bfloat16 g_act256[(size_t)BATCH * TOUT * 256];  // 63 MB
// Composed causal+gated0 weights: [n][k], n<24 gate / n>=24 filter, k = tap*256+i
__device__ __nv_bfloat16 g_gf3t[48 * 768];
__device__ float         g_eb[48];
// Pre-converted, transposed bf16 weights: [n][k] layout for mma B-frags
__device__ __nv_bfloat16 g_f1t[256 * 128];
__device__ __nv_bfloat16 g_f2t[256 * 256];

__device__ __forceinline__ float tanh_fast(float x) {
    float y;
    asm("tanh.approx.f32 %0, %1;" : "=f"(y) : "f"(x));
    return y;
}
__device__ __forceinline__ float sigmoid_fast(float x) {
    return __fdividef(1.0f, 1.0f + __expf(-x));
}
__device__ __forceinline__ uint32_t pack_bf2(float a, float b) {
    __nv_bfloat162 t = __float22bfloat162_rn(make_float2(a, b));
    return *reinterpret_cast<uint32_t*>(&t);
}

__device__ __forceinline__ void mma_bf16(float c[4], const uint32_t a[4], const uint32_t b[2]) {
    asm volatile(
        "mma.sync.aligned.m16n8k16.row.col.f32.bf16.bf16.f32 "
        "{%0,%1,%2,%3}, {%4,%5,%6,%7}, {%8,%9}, {%0,%1,%2,%3};"
        : "+f"(c[0]), "+f"(c[1]), "+f"(c[2]), "+f"(c[3])
        : "r"(a[0]), "r"(a[1]), "r"(a[2]), "r"(a[3]), "r"(b[0]), "r"(b[1]));
}

__device__ __forceinline__ uint32_t ld_bf2(const __nv_bfloat16* p) {
    return *reinterpret_cast<const uint32_t*>(p);
}
__device__ __forceinline__ uint32_t smem_u32(const void* p) {
    return (uint32_t)__cvta_generic_to_shared(p);
}
// ldmatrix x4: r = {m0,m1,m2,m3}; A-tile order [r,kk],[r+8,kk],[r,kk+8],[r+8,kk+8]
__device__ __forceinline__ void ldsm4(uint32_t r[4], uint32_t addr) {
    asm volatile("ldmatrix.sync.aligned.m8n8.x4.shared.b16 {%0,%1,%2,%3}, [%4];"
                 : "=r"(r[0]), "=r"(r[1]), "=r"(r[2]), "=r"(r[3]) : "r"(addr));
}

__device__ __forceinline__ void cp16(uint32_t smem_dst, const void* gsrc) {
    asm volatile("cp.async.ca.shared.global [%0], [%1], 16;" :: "r"(smem_dst), "l"(gsrc));
}
__device__ __forceinline__ void cp_commit() {
    asm volatile("cp.async.commit_group;" ::: "memory");
}
__device__ __forceinline__ void cp_wait_all() {
    asm volatile("cp.async.wait_group 0;" ::: "memory");
}

// ---------------------------------------------------------------------------
// Prep: x -> bf16
// ---------------------------------------------------------------------------
__global__ void k_prep_x(const float* __restrict__ x) {
    const size_t n4 = (size_t)BATCH * TLEN * CIN / 4;
    for (size_t i = blockIdx.x * blockDim.x + threadIdx.x; i < n4;
         i += (size_t)gridDim.x * blockDim.x) {
        float4 v = reinterpret_cast<const float4*>(x)[i];
        uint2 u;
        u.x = pack_bf2(v.x, v.y);
        u.y = pack_bf2(v.z, v.w);
        reinterpret_cast<uint2*>(g_xb)[i] = u;
    }
}

// ---------------------------------------------------------------------------
// Prep: remaining weights -> bf16 transposed [n][k]
// ---------------------------------------------------------------------------
__global__ void k_prep_w(const float* __restrict__ f1W,
                         const float* __restrict__ f2W) {
    const int stride = gridDim.x * blockDim.x;
    const int tid = blockIdx.x * blockDim.x + threadIdx.x;
    for (int idx = tid; idx < 256 * 128; idx += stride) {
        int o = idx >> 7, k = idx & 127;
        g_f1t[idx] = __float2bfloat16(f1W[k * 256 + o]);
    }
    for (int idx = tid; idx < 256 * 256; idx += stride) {
        int o = idx >> 8, k = idx & 255;
        g_f2t[idx] = __float2bfloat16(f2W[k * 256 + o]);
    }
}

// ---------------------------------------------------------------------------
// Prep: compose causal conv (K=2, 256->256) with gated0's g/f convs (K=2,
// 256->24 each) into one K=3 conv from x (256 -> 48), fp32 accumulate.
// ---------------------------------------------------------------------------
__global__ void k_prep_compose(const float* __restrict__ cW,
                               const float* __restrict__ cb,
                               const float* __restrict__ gW0,
                               const float* __restrict__ gb0,
                               const float* __restrict__ fW0,
                               const float* __restrict__ fb0) {
    const int tid = blockIdx.x * blockDim.x + threadIdx.x;
    const int stride = gridDim.x * blockDim.x;
    for (int idx = tid; idx < 48 * 768; idx += stride) {
        int n = idx / 768, k = idx % 768;
        int tap = k >> 8, i = k & 255;
        const float* W = (n < 24) ? gW0 : fW0;
        int o = (n < 24) ? n : n - 24;
        float s = 0.f;
        int k1lo = (tap > 1) ? tap - 1 : 0;
        int k1hi = (tap < 1) ? tap : 1;
        for (int k1 = k1lo; k1 <= k1hi; ++k1) {
            int k2 = tap - k1;
            const float* cwp = cW + k1 * 65536 + i * 256;
            const float* wp  = W + k2 * 6144 + o;
#pragma unroll 4
            for (int c = 0; c < 256; ++c)
                s += cwp[c] * wp[c * 24];
        }
        g_gf3t[idx] = __float2bfloat16(s);
    }
    if (tid < 48) {
        const float* W  = (tid < 24) ? gW0 : fW0;
        const float* bb = (tid < 24) ? gb0 : fb0;
        int o = (tid < 24) ? tid : tid - 24;
        float s = bb[o];
        for (int c = 0; c < 256; ++c)
            s += cb[c] * (W[c * 24 + o] + W[6144 + c * 24 + o]);
        g_eb[tid] = s;
    }
}

// ---------------------------------------------------------------------------
// K2: gated0 DIRECT from x, tap-reuse mainloop + ldmatrix fragment loads.
// ---------------------------------------------------------------------------
__global__ __launch_bounds__(256) void k_gated0_direct(const float* __restrict__ sW,
                                                       const float* __restrict__ sb) {
    const int t0 = blockIdx.x * 128;
    const int b  = blockIdx.y;
    const int tid  = threadIdx.x;
    const int warp = tid >> 5, lane = tid & 31;
    const int m_off = warp * 16;
    const int g  = lane >> 2;
    const int tq = lane & 3;
    // ldmatrix lane-derived offsets
    const int arow = (lane & 7) + ((lane & 8) ? 8 : 0);   // A: row off
    const int acol = (lane & 16) ? 8 : 0;                 // A: col off
    const int brow = (lane & 7) + ((lane & 16) ? 8 : 0);  // B: n off (2-nt pair)
    const int bcol = (lane & 8) ? 8 : 0;                  // B: k off

    __shared__ __align__(16) __nv_bfloat16 sGF[48][776];   // [n][k=768], pad 8
    __shared__ __align__(16) __nv_bfloat16 As[2][132][40]; // 130 rows used
    __shared__ __align__(16) __nv_bfloat16 Hs[128][40];    // K padded to 32, row pad 40
    __shared__ __align__(16) __nv_bfloat16 Bs2t[24][40];   // [o][c], c padded to 32
    const uint32_t as_base = (uint32_t)__cvta_generic_to_shared(&As[0][0][0]);

    // full composed B into smem (48 x 768 bf16 = 4608 uint4)
#pragma unroll
    for (int q = 0; q < 18; ++q) {
        int idx = tid + q * 256;
        int n = idx / 96, u = idx % 96;
        *reinterpret_cast<uint4*>(&sGF[n][u * 8]) =
            *reinterpret_cast<const uint4*>(g_gf3t + (size_t)n * 768 + u * 8);
    }
    // Bs2t[o][c] = sW[c*24+o]; pad c 24..31 with zeros
    for (int idx = tid; idx < 24 * 32; idx += 256) {
        int o = idx >> 5, c = idx & 31;
        Bs2t[o][c] = (c < 24) ? __float2bfloat16(sW[c * 24 + o]) : __float2bfloat16(0.f);
    }

#define GD_LOAD(chunk, s) do {                                                  \
    int ch = (chunk) * 32;                                                       \
    _Pragma("unroll")                                                            \
    for (int q = 0; q < 3; ++q) {                                                \
        int idx = tid + q * 256;                                                 \
        if (idx < 520) {                                                         \
            int r = idx >> 2, c8 = idx & 3;                                      \
            int row = t0 + r; if (row > TLEN - 1) row = TLEN - 1;                \
            cp16(as_base + (uint32_t)((((s) * 132 + r) * 40 + c8 * 8) * 2),      \
                 g_xb + ((size_t)b * TLEN + row) * CIN + ch + c8 * 8);           \
        }                                                                        \
    }                                                                            \
} while (0)

    float acc[6][4];
#pragma unroll
    for (int nt = 0; nt < 6; ++nt) {
        int c0 = nt * 8 + 2 * tq;
        float b0 = g_eb[c0], b1 = g_eb[c0 + 1];
        acc[nt][0] = b0; acc[nt][1] = b1; acc[nt][2] = b0; acc[nt][3] = b1;
    }

    GD_LOAD(0, 0);
    cp_commit();

    for (int c = 0; c < 8; ++c) {
        const int s = c & 1;
        const int ch = c * 32;
        cp_wait_all();
        __syncthreads();
        if (c < 7) { GD_LOAD(c + 1, s ^ 1); cp_commit(); }
#pragma unroll
        for (int tap = 0; tap < 3; ++tap) {
            const int kbase = tap * 256 + ch;
#pragma unroll
            for (int kk = 0; kk < 32; kk += 16) {
                uint32_t af[4];
                ldsm4(af, smem_u32(&As[s][m_off + tap + arow][kk + acol]));
                uint32_t bf[6][2];
#pragma unroll
                for (int p = 0; p < 3; ++p) {
                    uint32_t bq[4];
                    ldsm4(bq, smem_u32(&sGF[p * 16 + brow][kbase + kk + bcol]));
                    bf[p * 2 + 0][0] = bq[0]; bf[p * 2 + 0][1] = bq[1];
                    bf[p * 2 + 1][0] = bq[2]; bf[p * 2 + 1][1] = bq[3];
                }
#pragma unroll
                for (int nt = 0; nt < 6; ++nt)
                    mma_bf16(acc[nt], af, bf[nt]);
            }
        }
        __syncthreads();
    }
#undef GD_LOAD

    // Nonlinearity -> Hs (bf16, warp-private rows); zero-pad cols 24..31
    const int r0 = m_off + g, r1 = r0 + 8;
#pragma unroll
    for (int nt = 0; nt < 3; ++nt) {
        int c0 = nt * 8 + 2 * tq;
        *reinterpret_cast<uint32_t*>(&Hs[r0][c0]) =
            pack_bf2(tanh_fast(acc[nt + 3][0]) * sigmoid_fast(acc[nt][0]),
                     tanh_fast(acc[nt + 3][1]) * sigmoid_fast(acc[nt][1]));
        *reinterpret_cast<uint32_t*>(&Hs[r1][c0]) =
            pack_bf2(tanh_fast(acc[nt + 3][2]) * sigmoid_fast(acc[nt][2]),
                     tanh_fast(acc[nt + 3][3]) * sigmoid_fast(acc[nt][3]));
    }
    *reinterpret_cast<uint32_t*>(&Hs[r0][24 + 2 * tq]) = 0u;
    *reinterpret_cast<uint32_t*>(&Hs[r1][24 + 2 * tq]) = 0u;
    __syncwarp();

    // MMA2: Hs[128x32] x Bs2t (24 outputs), K=32 (scalar frag loads; once per block)
    float acc2[3][4];
#pragma unroll
    for (int nt = 0; nt < 3; ++nt) {
        int c0 = nt * 8 + 2 * tq;
        float b0 = sb[c0], b1 = sb[c0 + 1];
        acc2[nt][0] = b0; acc2[nt][1] = b1; acc2[nt][2] = b0; acc2[nt][3] = b1;
    }
#pragma unroll
    for (int kk = 0; kk < 32; kk += 16) {
        uint32_t af[4];
        af[0] = ld_bf2(&Hs[r0][kk + 2 * tq]);
        af[1] = ld_bf2(&Hs[r1][kk + 2 * tq]);
        af[2] = ld_bf2(&Hs[r0][kk + 8 + 2 * tq]);
        af[3] = ld_bf2(&Hs[r1][kk + 8 + 2 * tq]);
        uint32_t bf[3][2];
#pragma unroll
        for (int nt = 0; nt < 3; ++nt) {
            int c0 = nt * 8 + g;
            bf[nt][0] = ld_bf2(&Bs2t[c0][kk + 2 * tq]);
            bf[nt][1] = ld_bf2(&Bs2t[c0][kk + 8 + 2 * tq]);
        }
#pragma unroll
        for (int nt = 0; nt < 3; ++nt)
            mma_bf16(acc2[nt], af, bf[nt]);
    }

#pragma unroll
    for (int nt = 0; nt < 3; ++nt) {
        int col = nt * 8 + 2 * tq;
        int ta = t0 + r0;
        if (ta < L0)
            *reinterpret_cast<uint32_t*>(g_bufA + ((size_t)b * LMAX + ta) * 24 + col) =
                pack_bf2(acc2[nt][0], acc2[nt][1]);
        int tb = t0 + r1;
        if (tb < L0)
            *reinterpret_cast<uint32_t*>(g_bufA + ((size_t)b * LMAX + tb) * 24 + col) =
                pack_bf2(acc2[nt][2], acc2[nt][3]);
    }
}

// ---------------------------------------------------------------------------
// K3: dilated gated layer, bf16 MMA + ldmatrix. 512 threads, 256 rows/block.
// ---------------------------------------------------------------------------
__global__ __launch_bounds__(512) void k_dilated_mma(const float* __restrict__ gW,
                                                     const float* __restrict__ gb,
                                                     const float* __restrict__ fW,
                                                     const float* __restrict__ fb,
                                                     const float* __restrict__ sW,
                                                     const float* __restrict__ sb,
                                                     int d, int Lout, int dir) {
    const __nv_bfloat16* in = dir ? g_bufB : g_bufA;
    __nv_bfloat16*     outp = dir ? g_bufA : g_bufB;
    const int b  = blockIdx.y;
    const int t0 = blockIdx.x * 256;
    const int tid = threadIdx.x;
    const int warp = tid >> 5, lane = tid & 31;
    const int m_off = warp * 16;    // 16 warps x 16 rows = 256 rows
    const int g  = lane >> 2;
    const int tq = lane & 3;
    const int arow = (lane & 7) + ((lane & 8) ? 8 : 0);
    const int acol = (lane & 16) ? 8 : 0;
    const int brow = (lane & 7) + ((lane & 16) ? 8 : 0);
    const int bcol = (lane & 8) ? 8 : 0;

    __shared__ __align__(16) __nv_bfloat16 As[256][56];    // [m][k=48], pad 8
    __shared__ __align__(16) __nv_bfloat16 Bs1t[48][56];   // [n][k=48]
    __shared__ __align__(16) __nv_bfloat16 Hs[256][40];    // K padded to 32, row pad 40
    __shared__ __align__(16) __nv_bfloat16 Bs2t[24][40];   // [o][c=32]

    const int Lin = Lout + d;
    // A tile: one (row, tap) task per thread: r = tid>>1, tap = tid&1.
    {
        const int r    = tid >> 1;
        const int tap  = tid & 1;
        const int row  = t0 + r + (tap ? d : 0);
        const bool ok  = row < Lin;
        const __nv_bfloat16* src = in + ((size_t)b * LMAX + row) * 24;
        const int cbase = tap * 24;
        if (ok) {
#pragma unroll
            for (int j = 0; j < 3; ++j)
                *reinterpret_cast<uint4*>(&As[r][cbase + j * 8]) =
                    *reinterpret_cast<const uint4*>(src + j * 8);
        } else {
            uint4 z = make_uint4(0, 0, 0, 0);
#pragma unroll
            for (int j = 0; j < 3; ++j)
                *reinterpret_cast<uint4*>(&As[r][cbase + j * 8]) = z;
        }
    }
    // B1t[n][k]: k = tap*24+ci ; n<24 gate, n>=24 filter
    for (int idx = tid; idx < 48 * 48; idx += 512) {
        int n = idx / 48, k = idx % 48;
        int tap = k / 24, ci = k % 24;
        float w = (n < 24) ? gW[tap * 576 + ci * 24 + n]
                           : fW[tap * 576 + ci * 24 + (n - 24)];
        Bs1t[n][k] = __float2bfloat16(w);
    }
    // Bs2t[o][c] = sW[c*24+o], zero-padded c 24..31
    for (int idx = tid; idx < 24 * 32; idx += 512) {
        int o = idx >> 5, c = idx & 31;
        Bs2t[o][c] = (c < 24) ? __float2bfloat16(sW[c * 24 + o]) : __float2bfloat16(0.f);
    }
    __syncthreads();

    // MMA1: A[256x48] x B1t -> N=48, K=48 (3 k16 steps), ldmatrix frags
    float acc[6][4];
#pragma unroll
    for (int nt = 0; nt < 6; ++nt) {
        int c0 = (nt < 3) ? (nt * 8 + 2 * tq) : ((nt - 3) * 8 + 2 * tq);
        float b0 = (nt < 3) ? gb[c0] : fb[c0];
        float b1 = (nt < 3) ? gb[c0 + 1] : fb[c0 + 1];
        acc[nt][0] = b0; acc[nt][1] = b1; acc[nt][2] = b0; acc[nt][3] = b1;
    }
    const int r0 = m_off + g, r1 = r0 + 8;
#pragma unroll
    for (int kk = 0; kk < 48; kk += 16) {
        uint32_t af[4];
        ldsm4(af, smem_u32(&As[m_off + arow][kk + acol]));
        uint32_t bf[6][2];
#pragma unroll
        for (int p = 0; p < 3; ++p) {
            uint32_t bq[4];
            ldsm4(bq, smem_u32(&Bs1t[p * 16 + brow][kk + bcol]));
            bf[p * 2 + 0][0] = bq[0]; bf[p * 2 + 0][1] = bq[1];
            bf[p * 2 + 1][0] = bq[2]; bf[p * 2 + 1][1] = bq[3];
        }
#pragma unroll
        for (int nt = 0; nt < 6; ++nt)
            mma_bf16(acc[nt], af, bf[nt]);
    }

    // Nonlinearity -> Hs (warp-private rows); zero-pad cols 24..31
#pragma unroll
    for (int nt = 0; nt < 3; ++nt) {
        int c0 = nt * 8 + 2 * tq;
        *reinterpret_cast<uint32_t*>(&Hs[r0][c0]) =
            pack_bf2(tanh_fast(acc[nt + 3][0]) * sigmoid_fast(acc[nt][0]),
                     tanh_fast(acc[nt + 3][1]) * sigmoid_fast(acc[nt][1]));
        *reinterpret_cast<uint32_t*>(&Hs[r1][c0]) =
            pack_bf2(tanh_fast(acc[nt + 3][2]) * sigmoid_fast(acc[nt][2]),
                     tanh_fast(acc[nt + 3][3]) * sigmoid_fast(acc[nt][3]));
    }
    *reinterpret_cast<uint32_t*>(&Hs[r0][24 + 2 * tq]) = 0u;
    *reinterpret_cast<uint32_t*>(&Hs[r1][24 + 2 * tq]) = 0u;
    __syncwarp();

    // MMA2: Hs[256x32] x Bs2t -> 24 outputs (scalar frags; once per block)
    float acc2[3][4];
#pragma unroll
    for (int nt = 0; nt < 3; ++nt) {
        int c0 = nt * 8 + 2 * tq;
        float b0 = sb[c0], b1 = sb[c0 + 1];
        acc2[nt][0] = b0; acc2[nt][1] = b1; acc2[nt][2] = b0; acc2[nt][3] = b1;
    }
#pragma unroll
    for (int kk = 0; kk < 32; kk += 16) {
        uint32_t af[4];
        af[0] = ld_bf2(&Hs[r0][kk + 2 * tq]);
        af[1] = ld_bf2(&Hs[r1][kk + 2 * tq]);
        af[2] = ld_bf2(&Hs[r0][kk + 8 + 2 * tq]);
        af[3] = ld_bf2(&Hs[r1][kk + 8 + 2 * tq]);
        uint32_t bf[3][2];
#pragma unroll
        for (int nt = 0; nt < 3; ++nt) {
            int c0 = nt * 8 + g;
            bf[nt][0] = ld_bf2(&Bs2t[c0][kk + 2 * tq]);
            bf[nt][1] = ld_bf2(&Bs2t[c0][kk + 8 + 2 * tq]);
        }
#pragma unroll
        for (int nt = 0; nt < 3; ++nt)
            mma_bf16(acc2[nt], af, bf[nt]);
    }

    // Store (bf16 pairs)
#pragma unroll
    for (int nt = 0; nt < 3; ++nt) {
        int col = nt * 8 + 2 * tq;
        int ta = t0 + r0;
        if (ta < Lout)
            *reinterpret_cast<uint32_t*>(outp + ((size_t)b * LMAX + ta) * 24 + col) =
                pack_bf2(acc2[nt][0], acc2[nt][1]);
        int tb = t0 + r1;
        if (tb < Lout)
            *reinterpret_cast<uint32_t*>(outp + ((size_t)b * LMAX + tb) * 24 + col) =
                pack_bf2(acc2[nt][2], acc2[nt][3]);
    }
}

// ---------------------------------------------------------------------------
// K4a: act128 = relu(resW conv of (prev[t+256] + out[t])). bf16 in/out.
// ---------------------------------------------------------------------------
__global__ __launch_bounds__(256) void k_resrelu(const float* __restrict__ resW,
                                                 const float* __restrict__ resb) {
    const int b  = blockIdx.y;
    const int t0 = blockIdx.x * 64;
    const int tid = threadIdx.x;
    const int og = tid & 31;
    const int tg = tid >> 5;

    __shared__ float s_in[64][25];
    for (int idx = tid; idx < 64 * 24; idx += 256) {
        int r = idx / 24, c = idx % 24;
        size_t prow = (size_t)b * LMAX + 256 + t0 + r;
        size_t orow = (size_t)b * LMAX + t0 + r;
        s_in[r][c] = __bfloat162float(g_bufA[prow * 24 + c]) +
                     __bfloat162float(g_bufB[orow * 24 + c]);
    }
    __syncthreads();

    const float4 bb = reinterpret_cast<const float4*>(resb)[og];
    float acc[8][4];
#pragma unroll
    for (int rr = 0; rr < 8; ++rr) {
        acc[rr][0] = bb.x; acc[rr][1] = bb.y; acc[rr][2] = bb.z; acc[rr][3] = bb.w;
    }
#pragma unroll 4
    for (int c = 0; c < 24; ++c) {
        float4 w = reinterpret_cast<const float4*>(resW)[c * 32 + og];
#pragma unroll
        for (int rr = 0; rr < 8; ++rr) {
            float xin = s_in[tg * 8 + rr][c];
            acc[rr][0] += xin * w.x; acc[rr][1] += xin * w.y;
            acc[rr][2] += xin * w.z; acc[rr][3] += xin * w.w;
        }
    }
#pragma unroll
    for (int rr = 0; rr < 8; ++rr) {
        int row = t0 + tg * 8 + rr;
        __nv_bfloat16* dst = g_act128 + ((size_t)b * TOUT + row) * 128 + og * 4;
        *reinterpret_cast<uint32_t*>(dst) =
            pack_bf2(fmaxf(acc[rr][0], 0.f), fmaxf(acc[rr][1], 0.f));
        *reinterpret_cast<uint32_t*>(dst + 2) =
            pack_bf2(fmaxf(acc[rr][2], 0.f), fmaxf(acc[rr][3], 0.f));
    }
}

// ---------------------------------------------------------------------------
// K4b: act256 = relu(act128 @ f1W + f1b). bf16 GEMM + ldmatrix, K=128 in smem.
// ---------------------------------------------------------------------------
__global__ __launch_bounds__(256) void k_gemm_relu(const float* __restrict__ f1b) {
    const int t0 = blockIdx.x * 128;
    const int o0 = blockIdx.y * 128;
    const int b  = blockIdx.z;
    const int tid  = threadIdx.x;
    const int warp = tid >> 5, lane = tid & 31;
    const int m_off = (warp >> 2) * 64;
    const int n_off = (warp & 3) * 32;
    const int g  = lane >> 2;
    const int tq = lane & 3;
    const int arow = (lane & 7) + ((lane & 8) ? 8 : 0);
    const int acol = (lane & 16) ? 8 : 0;
    const int brow = (lane & 7) + ((lane & 16) ? 8 : 0);
    const int bcol = (lane & 8) ? 8 : 0;

    __shared__ __align__(16) __nv_bfloat16 As[128][136];
    __shared__ __align__(16) __nv_bfloat16 Bs[128][136];

#pragma unroll
    for (int q = 0; q < 8; ++q) {
        int idx = tid + q * 256;
        int r = idx >> 4, u = idx & 15;
        *reinterpret_cast<uint4*>(&As[r][u * 8]) =
            *reinterpret_cast<const uint4*>(g_act128 + ((size_t)b * TOUT + t0 + r) * 128 + u * 8);
        *reinterpret_cast<uint4*>(&Bs[r][u * 8]) =
            *reinterpret_cast<const uint4*>(g_f1t + (size_t)(o0 + r) * 128 + u * 8);
    }
    __syncthreads();

    float acc[4][4][4];
#pragma unroll
    for (int mt = 0; mt < 4; ++mt)
#pragma unroll
        for (int nt = 0; nt < 4; ++nt)
#pragma unroll
            for (int q = 0; q < 4; ++q) acc[mt][nt][q] = 0.0f;

#pragma unroll
    for (int kk = 0; kk < 128; kk += 16) {
        uint32_t af[4][4];
#pragma unroll
        for (int mt = 0; mt < 4; ++mt)
            ldsm4(af[mt], smem_u32(&As[m_off + mt * 16 + arow][kk + acol]));
        uint32_t bf[4][2];
#pragma unroll
        for (int p = 0; p < 2; ++p) {
            uint32_t bq[4];
            ldsm4(bq, smem_u32(&Bs[n_off + p * 16 + brow][kk + bcol]));
            bf[p * 2 + 0][0] = bq[0]; bf[p * 2 + 0][1] = bq[1];
            bf[p * 2 + 1][0] = bq[2]; bf[p * 2 + 1][1] = bq[3];
        }
#pragma unroll
        for (int mt = 0; mt < 4; ++mt)
#pragma unroll
            for (int nt = 0; nt < 4; ++nt)
                mma_bf16(acc[mt][nt], af[mt], bf[nt]);
    }

#pragma unroll
    for (int nt = 0; nt < 4; ++nt) {
        const int col = o0 + n_off + nt * 8 + 2 * tq;
        const float2 bias = *reinterpret_cast<const float2*>(f1b + col);
#pragma unroll
        for (int mt = 0; mt < 4; ++mt) {
            int row = t0 + m_off + mt * 16 + g;
            *reinterpret_cast<uint32_t*>(g_act256 + ((size_t)b * TOUT + row) * 256 + col) =
                pack_bf2(fmaxf(acc[mt][nt][0] + bias.x, 0.f),
                         fmaxf(acc[mt][nt][1] + bias.y, 0.f));
            *reinterpret_cast<uint32_t*>(g_act256 + ((size_t)b * TOUT + row + 8) * 256 + col) =
                pack_bf2(fmaxf(acc[mt][nt][2] + bias.x, 0.f),
                         fmaxf(acc[mt][nt][3] + bias.y, 0.f));
        }
    }
}

// ---------------------------------------------------------------------------
// K4c: y = softmax(act256 @ f2W + f2b). bf16 GEMM + ldmatrix, M tile 64, N=256.
// ---------------------------------------------------------------------------
__global__ __launch_bounds__(256) void k_gemm_softmax(const float* __restrict__ f2b,
                                                      float* __restrict__ y) {
    const int t0 = blockIdx.x * 64;
    const int b  = blockIdx.y;
    const int tid  = threadIdx.x;
    const int warp = tid >> 5, lane = tid & 31;
    const int mw = warp >> 2;
    const int nw = warp & 3;
    const int m_off = mw * 32;
    const int n_off = nw * 64;
    const int g  = lane >> 2;
    const int tq = lane & 3;
    const int arow = (lane & 7) + ((lane & 8) ? 8 : 0);
    const int acol = (lane & 16) ? 8 : 0;
    const int brow = (lane & 7) + ((lane & 16) ? 8 : 0);
    const int bcol = (lane & 8) ? 8 : 0;

    __shared__ __align__(16) __nv_bfloat16 As[64][264];
    __shared__ __align__(16) __nv_bfloat16 Bs[256][40];
    __shared__ float red1[64][4];
    __shared__ float red2[64][4];

#pragma unroll
    for (int q = 0; q < 8; ++q) {
        int idx = tid + q * 256;
        int r = idx >> 5, u = idx & 31;
        *reinterpret_cast<uint4*>(&As[r][u * 8]) =
            *reinterpret_cast<const uint4*>(g_act256 + ((size_t)b * TOUT + t0 + r) * 256 + u * 8);
    }

    float acc[2][8][4];
#pragma unroll
    for (int mt = 0; mt < 2; ++mt)
#pragma unroll
        for (int nt = 0; nt < 8; ++nt)
#pragma unroll
            for (int q = 0; q < 4; ++q) acc[mt][nt][q] = 0.0f;

    for (int k0 = 0; k0 < 256; k0 += 32) {
        __syncthreads();
#pragma unroll
        for (int q = 0; q < 4; ++q) {
            int idx = tid + q * 256;
            int r = idx >> 2, c8 = idx & 3;
            *reinterpret_cast<uint4*>(&Bs[r][c8 * 8]) =
                *reinterpret_cast<const uint4*>(g_f2t + (size_t)r * 256 + k0 + c8 * 8);
        }
        __syncthreads();
#pragma unroll
        for (int kk = 0; kk < 32; kk += 16) {
            uint32_t af[2][4];
#pragma unroll
            for (int mt = 0; mt < 2; ++mt)
                ldsm4(af[mt], smem_u32(&As[m_off + mt * 16 + arow][k0 + kk + acol]));
            uint32_t bf[8][2];
#pragma unroll
            for (int p = 0; p < 4; ++p) {
                uint32_t bq[4];
                ldsm4(bq, smem_u32(&Bs[n_off + p * 16 + brow][kk + bcol]));
                bf[p * 2 + 0][0] = bq[0]; bf[p * 2 + 0][1] = bq[1];
                bf[p * 2 + 1][0] = bq[2]; bf[p * 2 + 1][1] = bq[3];
            }
#pragma unroll
            for (int mt = 0; mt < 2; ++mt)
#pragma unroll
                for (int nt = 0; nt < 8; ++nt)
                    mma_bf16(acc[mt][nt], af[mt], bf[nt]);
        }
    }

#pragma unroll
    for (int nt = 0; nt < 8; ++nt) {
        const int col = n_off + nt * 8 + 2 * tq;
        const float2 bias = *reinterpret_cast<const float2*>(f2b + col);
#pragma unroll
        for (int mt = 0; mt < 2; ++mt) {
            acc[mt][nt][0] += bias.x; acc[mt][nt][1] += bias.y;
            acc[mt][nt][2] += bias.x; acc[mt][nt][3] += bias.y;
        }
    }

    float rmax[2][2];
#pragma unroll
    for (int mt = 0; mt < 2; ++mt)
#pragma unroll
        for (int rr = 0; rr < 2; ++rr) {
            float m = -1e30f;
#pragma unroll
            for (int nt = 0; nt < 8; ++nt) {
                m = fmaxf(m, acc[mt][nt][rr * 2 + 0]);
                m = fmaxf(m, acc[mt][nt][rr * 2 + 1]);
            }
            m = fmaxf(m, __shfl_xor_sync(0xffffffffu, m, 1));
            m = fmaxf(m, __shfl_xor_sync(0xffffffffu, m, 2));
            rmax[mt][rr] = m;
            if (tq == 0) red1[m_off + mt * 16 + rr * 8 + g][nw] = m;
        }
    __syncthreads();
#pragma unroll
    for (int mt = 0; mt < 2; ++mt)
#pragma unroll
        for (int rr = 0; rr < 2; ++rr) {
            int r = m_off + mt * 16 + rr * 8 + g;
            rmax[mt][rr] = fmaxf(fmaxf(red1[r][0], red1[r][1]),
                                 fmaxf(red1[r][2], red1[r][3]));
        }

    float rsum[2][2];
#pragma unroll
    for (int mt = 0; mt < 2; ++mt)
#pragma unroll
        for (int rr = 0; rr < 2; ++rr) {
            float s = 0.f;
#pragma unroll
            for (int nt = 0; nt < 8; ++nt) {
                float e0 = __expf(acc[mt][nt][rr * 2 + 0] - rmax[mt][rr]);
                float e1 = __expf(acc[mt][nt][rr * 2 + 1] - rmax[mt][rr]);
                acc[mt][nt][rr * 2 + 0] = e0;
                acc[mt][nt][rr * 2 + 1] = e1;
                s += e0 + e1;
            }
            s += __shfl_xor_sync(0xffffffffu, s, 1);
            s += __shfl_xor_sync(0xffffffffu, s, 2);
            rsum[mt][rr] = s;
            if (tq == 0) red2[m_off + mt * 16 + rr * 8 + g][nw] = s;
        }
    __syncthreads();
#pragma unroll
    for (int mt = 0; mt < 2; ++mt)
#pragma unroll
        for (int rr = 0; rr < 2; ++rr) {
            int r = m_off + mt * 16 + rr * 8 + g;
            rsum[mt][rr] = __fdividef(1.0f, red2[r][0] + red2[r][1] + red2[r][2] + red2[r][3]);
        }

#pragma unroll
    for (int nt = 0; nt < 8; ++nt) {
        const int col = n_off + nt * 8 + 2 * tq;
#pragma unroll
        for (int mt = 0; mt < 2; ++mt) {
            int row = t0 + m_off + mt * 16 + g;
            float2 v0 = make_float2(acc[mt][nt][0] * rsum[mt][0],
                                    acc[mt][nt][1] * rsum[mt][0]);
            float2 v1 = make_float2(acc[mt][nt][2] * rsum[mt][1],
                                    acc[mt][nt][3] * rsum[mt][1]);
            *reinterpret_cast<float2*>(y + ((size_t)b * TOUT + row) * 256 + col) = v0;
            *reinterpret_cast<float2*>(y + ((size_t)b * TOUT + row + 8) * 256 + col) = v1;
        }
    }
}

// ---------------------------------------------------------------------------
extern "C" void kernel_launch(void* const* d_in, const int* in_sizes, int n_in,
                              void* d_out, int out_size) {
    const float* x     = (const float*)d_in[0];
    const float* cW    = (const float*)d_in[1];
    const float* cb    = (const float*)d_in[2];
    const float* gW0   = (const float*)d_in[3];
    const float* gb0   = (const float*)d_in[4];
    const float* fW0   = (const float*)d_in[5];
    const float* fb0   = (const float*)d_in[6];
    const float* sW0   = (const float*)d_in[7];
    const float* sb0   = (const float*)d_in[8];
    const float* gateW = (const float*)d_in[9];
    const float* gateB = (const float*)d_in[10];
    const float* filtW = (const float*)d_in[11];
    const float* filtB = (const float*)d_in[12];
    const float* scW   = (const float*)d_in[13];
    const float* scB   = (const float*)d_in[14];
    const float* resW  = (const float*)d_in[15];
    const float* resB  = (const float*)d_in[16];
    const float* f1W   = (const float*)d_in[17];
    const float* f1b   = (const float*)d_in[18];
    const float* f2W   = (const float*)d_in[19];
    const float* f2b   = (const float*)d_in[20];
    float* out = (float*)d_out;

    k_prep_x<<<4096, 256>>>(x);
    k_prep_w<<<128, 256>>>(f1W, f2W);
    k_prep_compose<<<144, 256>>>(cW, cb, gW0, gb0, fW0, fb0);

    // causal conv + gated0 g/f convs composed into one K=3 conv from x
    k_gated0_direct<<<dim3(128, BATCH), 256>>>(sW0, sb0);

    int L = L0;
    for (int i = 0; i < 9; ++i) {
        int d = 2 << i;          // 2,4,...,512
        int Lout = L - d;
        int nb = (Lout + 255) / 256;
        // Only the LAST residual conv contributes to the output (acc is
        // overwritten each iteration in the reference), so res convs 0..7 are skipped.
        k_dilated_mma<<<dim3(nb, BATCH), 512>>>(gateW + i * 1152, gateB + i * 24,
                                                filtW + i * 1152, filtB + i * 24,
                                                scW + i * 576, scB + i * 24,
                                                d, Lout, i & 1);
        L = Lout;
    }
    // prev (input of layer i=8) lives in g_bufA (len 15872); its output in g_bufB (15360)
    k_resrelu<<<dim3(TOUT / 64, BATCH), 256>>>(resW + 8 * 24 * 128, resB + 8 * 128);
    k_gemm_relu<<<dim3(TOUT / 128, 2, BATCH), 256>>>(f1b);
    k_gemm_softmax<<<dim3(TOUT / 64, BATCH), 256>>>(f2b, out);
}